// round 6
// baseline (speedup 1.0000x reference)
#include <cuda_runtime.h>
#include <math.h>
#include <cstdint>

// ---------------- problem constants ----------------
#define D_   1024
#define H_   16
#define DH_  64
#define NL_  4
#define DFF_ 4096
#define V_   32000
#define S_   1024
#define NB_  2
#define BSZ_ (NB_*S_)

static inline int cdiv(int a, int b) { return (a + b - 1) / b; }

// ---------------- scratch ----------------
__device__ float g_x   [BSZ_*D_];
__device__ float g_h   [BSZ_*D_];
__device__ float g_qkv [BSZ_*3*D_];
__device__ float g_o   [BSZ_*D_];
__device__ float g_ff  [BSZ_*DFF_];
__device__ float g_att [(size_t)NB_*H_*S_*S_];
__device__ float g_vT  [(size_t)NB_*H_*DH_*S_];
__device__ float g_wqkv[(size_t)NL_*3*D_*D_];
__device__ float g_woT [(size_t)NL_*D_*D_];
__device__ float g_w1T [(size_t)NL_*DFF_*D_];
__device__ float g_w2T [(size_t)NL_*D_*DFF_];
__device__ float g_bqkv[NL_*3*D_];
__device__ float g_embr[(size_t)V_*D_];

// ---------------- tf32 / mma helpers ----------------
__device__ __forceinline__ float tf32r(float x) {
    uint32_t u;
    asm("cvt.rna.tf32.f32 %0, %1;" : "=r"(u) : "f"(x));
    return __uint_as_float(u);
}
__device__ __forceinline__ void mma1688(float* d, const uint32_t* a, const uint32_t* b) {
    asm volatile(
        "mma.sync.aligned.m16n8k8.row.col.f32.tf32.tf32.f32 "
        "{%0,%1,%2,%3}, {%4,%5,%6,%7}, {%8,%9}, {%0,%1,%2,%3};"
        : "+f"(d[0]), "+f"(d[1]), "+f"(d[2]), "+f"(d[3])
        : "r"(a[0]), "r"(a[1]), "r"(a[2]), "r"(a[3]), "r"(b[0]), "r"(b[1]));
}
__device__ __forceinline__ uint32_t smem_u32(const void* p) {
    uint32_t a;
    asm("{ .reg .u64 t; cvta.to.shared.u64 t, %1; cvt.u32.u64 %0, t; }" : "=r"(a) : "l"(p));
    return a;
}
__device__ __forceinline__ void cpa16(uint32_t dst, const float* src, bool pred) {
    int sz = pred ? 16 : 0;
    asm volatile("cp.async.cg.shared.global [%0], [%1], 16, %2;"
                 :: "r"(dst), "l"(src), "r"(sz) : "memory");
}
#define CPA_COMMIT() asm volatile("cp.async.commit_group;" ::: "memory")
#define CPA_WAIT1()  asm volatile("cp.async.wait_group 1;" ::: "memory")

constexpr int BK = 32, LDS_ = 36, NSTAGE = 3;

// ============ 256-thread GEMM: BM=128, BN=256, 8 warps of 64x64 ============
constexpr int BM2 = 128, BN2 = 256;
constexpr int STG2 = (BM2 + BN2) * LDS_;            // floats per stage
constexpr int SMEM2 = NSTAGE * STG2 * 4;            // 165,888 B

template<bool RELU, bool RESID, bool BIAS, bool CAUSAL, bool ROUND>
__global__ void __launch_bounds__(256, 1) gemm_mma256(
    const float* __restrict__ Ag, const float* __restrict__ Bg,
    const float* __restrict__ biasg, const float* __restrict__ Cing,
    float* __restrict__ Cg,
    int M, int N, int K, int lda, int ldb, int ldc,
    int nz2, long sA1, long sA2, long sB1, long sB2, long sC1, long sC2,
    float alpha)
{
    int row0 = blockIdx.y * BM2;
    int col0 = blockIdx.x * BN2;
    if (CAUSAL && col0 > row0 + BM2 - 1) return;

    int z = blockIdx.z, z1 = z / nz2, z2 = z - z1 * nz2;
    const float* A   = Ag + z1 * sA1 + z2 * sA2;
    const float* B   = Bg + z1 * sB1 + z2 * sB2;
    float*       C   = Cg + z1 * sC1 + z2 * sC2;
    const float* Cin = RESID ? (Cing + z1 * sC1 + z2 * sC2) : nullptr;

    extern __shared__ float sm[];
    uint32_t sm0 = smem_u32(sm);

    int tid = threadIdx.x;
    int wid = tid >> 5, lane = tid & 31;
    int wm = wid >> 2, wn = wid & 3;          // 2x4 warps, 64x64 each
    int gid = lane >> 2, tig = lane & 3;

    int cr = tid >> 3;                        // 0..31
    int cc = (tid & 7) * 4;

    float acc[4][8][4];
    #pragma unroll
    for (int a = 0; a < 4; a++)
        #pragma unroll
        for (int b = 0; b < 8; b++)
            #pragma unroll
            for (int c = 0; c < 4; c++) acc[a][b][c] = 0.f;

    int KT = K / BK;

    auto issue = [&](int kt, int slot) {
        int k0 = kt * BK;
        uint32_t abase = sm0 + (uint32_t)slot * STG2 * 4;
        uint32_t bbase = abase + BM2 * LDS_ * 4;
        #pragma unroll
        for (int i = 0; i < 4; i++) {                 // A: 128 rows
            int r = cr + i * 32;
            int gm = row0 + r;
            const float* pa = A + (size_t)(gm < M ? gm : 0) * lda + k0 + cc;
            cpa16(abase + (r * LDS_ + cc) * 4, pa, gm < M);
        }
        #pragma unroll
        for (int i = 0; i < 8; i++) {                 // B: 256 rows
            int r = cr + i * 32;
            int gn = col0 + r;
            const float* pb = B + (size_t)(gn < N ? gn : 0) * ldb + k0 + cc;
            cpa16(bbase + (r * LDS_ + cc) * 4, pb, gn < N);
        }
    };

    int nPre = KT < (NSTAGE - 1) ? KT : (NSTAGE - 1);
    for (int p = 0; p < nPre; p++) { issue(p, p); CPA_COMMIT(); }

    for (int kt = 0; kt < KT; kt++) {
        CPA_WAIT1();
        __syncthreads();
        int nxt = kt + NSTAGE - 1;
        if (nxt < KT) issue(nxt, nxt % NSTAGE);
        CPA_COMMIT();

        const float* As = sm + (kt % NSTAGE) * STG2;
        const float* Bs = As + BM2 * LDS_;
        const float* Ab = As + (wm * 64 + gid) * LDS_;
        const float* Bb = Bs + (wn * 64 + gid) * LDS_;

        #pragma unroll
        for (int ks = 0; ks < 4; ks++) {
            int kc = ks * 8 + tig;
            uint32_t af[4][4], bf[8][2];
            #pragma unroll
            for (int mt = 0; mt < 4; mt++) {
                const float* p = Ab + mt * 16 * LDS_;
                af[mt][0] = __float_as_uint(p[kc]);
                af[mt][1] = __float_as_uint(p[8 * LDS_ + kc]);
                af[mt][2] = __float_as_uint(p[kc + 4]);
                af[mt][3] = __float_as_uint(p[8 * LDS_ + kc + 4]);
            }
            #pragma unroll
            for (int nt = 0; nt < 8; nt++) {
                const float* p = Bb + nt * 8 * LDS_;
                bf[nt][0] = __float_as_uint(p[kc]);
                bf[nt][1] = __float_as_uint(p[kc + 4]);
            }
            #pragma unroll
            for (int mt = 0; mt < 4; mt++)
                #pragma unroll
                for (int nt = 0; nt < 8; nt++)
                    mma1688(acc[mt][nt], af[mt], bf[nt]);
        }
    }

    #pragma unroll
    for (int mt = 0; mt < 4; mt++) {
        #pragma unroll
        for (int half = 0; half < 2; half++) {
            int gm = row0 + wm * 64 + mt * 16 + gid + half * 8;
            if (gm >= M) continue;
            #pragma unroll
            for (int nt = 0; nt < 8; nt++) {
                int gn = col0 + wn * 64 + nt * 8 + 2 * tig;
                if (gn >= N) continue;
                float v0 = acc[mt][nt][half * 2 + 0] * alpha;
                float v1 = acc[mt][nt][half * 2 + 1] * alpha;
                if (BIAS)  { v0 += biasg[gn]; v1 += biasg[gn + 1]; }
                if (RESID) {
                    const float* ci = Cin + (size_t)gm * ldc + gn;
                    v0 += ci[0]; v1 += ci[1];
                }
                if (RELU) { v0 = fmaxf(v0, 0.f); v1 = fmaxf(v1, 0.f); }
                if (ROUND) { v0 = tf32r(v0); v1 = tf32r(v1); }
                *(float2*)(C + (size_t)gm * ldc + gn) = make_float2(v0, v1);
            }
        }
    }
}

// ============ 128-thread GEMM: BM=128, BN=128 (used for P@V, with K-trim) ============
constexpr int BM1 = 128, BN1 = 128;
constexpr int STG1 = 2 * BM1 * LDS_;
constexpr int SMEM1 = NSTAGE * STG1 * 4;

template<bool ROUND, bool CAUSALK>
__global__ void __launch_bounds__(128) gemm_mma128(
    const float* __restrict__ Ag, const float* __restrict__ Bg,
    float* __restrict__ Cg,
    int M, int N, int K, int lda, int ldb, int ldc,
    int nz2, long sA1, long sA2, long sB1, long sB2, long sC1, long sC2,
    float alpha)
{
    int row0 = blockIdx.y * BM1;
    int col0 = blockIdx.x * BN1;

    int z = blockIdx.z, z1 = z / nz2, z2 = z - z1 * nz2;
    const float* A = Ag + z1 * sA1 + z2 * sA2;
    const float* B = Bg + z1 * sB1 + z2 * sB2;
    float*       C = Cg + z1 * sC1 + z2 * sC2;

    extern __shared__ float sm[];
    uint32_t sm0 = smem_u32(sm);

    int tid = threadIdx.x;
    int wid = tid >> 5, lane = tid & 31;
    int wm = wid >> 1, wn = wid & 1;
    int gid = lane >> 2, tig = lane & 3;

    int cr = tid >> 3;
    int cc = (tid & 7) * 4;

    float acc[4][8][4];
    #pragma unroll
    for (int a = 0; a < 4; a++)
        #pragma unroll
        for (int b = 0; b < 8; b++)
            #pragma unroll
            for (int c = 0; c < 4; c++) acc[a][b][c] = 0.f;

    int KT = K / BK;
    if (CAUSALK) { int lim = (row0 + BM1) / BK; if (lim < KT) KT = lim; }

    auto issue = [&](int kt, int slot) {
        int k0 = kt * BK;
        uint32_t abase = sm0 + (uint32_t)slot * STG1 * 4;
        uint32_t bbase = abase + BM1 * LDS_ * 4;
        #pragma unroll
        for (int i = 0; i < 8; i++) {
            int r = cr + i * 16;
            int gm = row0 + r;
            const float* pa = A + (size_t)(gm < M ? gm : 0) * lda + k0 + cc;
            cpa16(abase + (r * LDS_ + cc) * 4, pa, gm < M);
            int gn = col0 + r;
            const float* pb = B + (size_t)(gn < N ? gn : 0) * ldb + k0 + cc;
            cpa16(bbase + (r * LDS_ + cc) * 4, pb, gn < N);
        }
    };

    int nPre = KT < (NSTAGE - 1) ? KT : (NSTAGE - 1);
    for (int p = 0; p < nPre; p++) { issue(p, p); CPA_COMMIT(); }

    for (int kt = 0; kt < KT; kt++) {
        CPA_WAIT1();
        __syncthreads();
        int nxt = kt + NSTAGE - 1;
        if (nxt < KT) issue(nxt, nxt % NSTAGE);
        CPA_COMMIT();

        const float* As = sm + (kt % NSTAGE) * STG1;
        const float* Bs = As + BM1 * LDS_;
        const float* Ab = As + (wm * 64 + gid) * LDS_;
        const float* Bb = Bs + (wn * 64 + gid) * LDS_;

        #pragma unroll
        for (int ks = 0; ks < 4; ks++) {
            int kc = ks * 8 + tig;
            uint32_t af[4][4], bf[8][2];
            #pragma unroll
            for (int mt = 0; mt < 4; mt++) {
                const float* p = Ab + mt * 16 * LDS_;
                af[mt][0] = __float_as_uint(p[kc]);
                af[mt][1] = __float_as_uint(p[8 * LDS_ + kc]);
                af[mt][2] = __float_as_uint(p[kc + 4]);
                af[mt][3] = __float_as_uint(p[8 * LDS_ + kc + 4]);
            }
            #pragma unroll
            for (int nt = 0; nt < 8; nt++) {
                const float* p = Bb + nt * 8 * LDS_;
                bf[nt][0] = __float_as_uint(p[kc]);
                bf[nt][1] = __float_as_uint(p[kc + 4]);
            }
            #pragma unroll
            for (int mt = 0; mt < 4; mt++)
                #pragma unroll
                for (int nt = 0; nt < 8; nt++)
                    mma1688(acc[mt][nt], af[mt], bf[nt]);
        }
    }

    #pragma unroll
    for (int mt = 0; mt < 4; mt++) {
        #pragma unroll
        for (int half = 0; half < 2; half++) {
            int gm = row0 + wm * 64 + mt * 16 + gid + half * 8;
            if (gm >= M) continue;
            #pragma unroll
            for (int nt = 0; nt < 8; nt++) {
                int gn = col0 + wn * 64 + nt * 8 + 2 * tig;
                if (gn >= N) continue;
                float v0 = acc[mt][nt][half * 2 + 0] * alpha;
                float v1 = acc[mt][nt][half * 2 + 1] * alpha;
                if (ROUND) { v0 = tf32r(v0); v1 = tf32r(v1); }
                *(float2*)(C + (size_t)gm * ldc + gn) = make_float2(v0, v1);
            }
        }
    }
}

// ============ auxiliary kernels ============
__global__ void embed_k(const int* __restrict__ idx, const float* __restrict__ emb) {
    int t = blockIdx.x * blockDim.x + threadIdx.x;
    if (t >= BSZ_ * D_) return;
    int d = t & (D_ - 1);
    int bs = t >> 10;
    int s = bs & (S_ - 1);
    int tok = idx[bs];
    int i2 = d & ~1;
    float freq = __expf((float)i2 * (-9.210340371976184f / (float)D_));
    float ang = (float)s * freq;
    float pe = (d & 1) ? cosf(ang) : sinf(ang);
    g_x[t] = emb[(size_t)tok * D_ + d] * 32.0f + pe;
}

__global__ void roundcpy_k(const float* __restrict__ in, float* __restrict__ out, size_t n) {
    size_t i = (size_t)blockIdx.x * blockDim.x + threadIdx.x;
    if (i < n) out[i] = tf32r(in[i]);
}

__global__ void ln_k(const float* __restrict__ in, float* __restrict__ out,
                     const float* __restrict__ sc, const float* __restrict__ bi) {
    int row = blockIdx.x;
    const float* x = in + (size_t)row * D_;
    int tid = threadIdx.x;
    float s = 0.f, ss = 0.f;
    for (int i = tid; i < D_; i += 256) { float v = x[i]; s += v; ss = fmaf(v, v, ss); }
    __shared__ float rs[8], rq[8];
    #pragma unroll
    for (int o = 16; o > 0; o >>= 1) {
        s  += __shfl_xor_sync(0xffffffffu, s,  o);
        ss += __shfl_xor_sync(0xffffffffu, ss, o);
    }
    if ((tid & 31) == 0) { rs[tid >> 5] = s; rq[tid >> 5] = ss; }
    __syncthreads();
    if (tid < 32) {
        float a = (tid < 8) ? rs[tid] : 0.f;
        float b = (tid < 8) ? rq[tid] : 0.f;
        #pragma unroll
        for (int o = 4; o > 0; o >>= 1) {
            a += __shfl_xor_sync(0xffffffffu, a, o);
            b += __shfl_xor_sync(0xffffffffu, b, o);
        }
        if (tid == 0) { rs[0] = a; rq[0] = b; }
    }
    __syncthreads();
    float mean = rs[0] * (1.0f / D_);
    float var  = rq[0] * (1.0f / D_) - mean * mean;
    float inv  = rsqrtf(var + 1e-5f);
    for (int i = tid; i < D_; i += 256)
        out[(size_t)row * D_ + i] = tf32r((x[i] - mean) * inv * sc[i] + bi[i]);
}

__global__ void softmax_k(float* __restrict__ att) {
    size_t row = blockIdx.x;
    int i = (int)(row & (S_ - 1));
    float* p = att + row * (size_t)S_;
    int n = i + 1;
    int tid = threadIdx.x;
    __shared__ float red[8];
    float m = -3.4e38f;
    for (int j = tid; j < n; j += 256) m = fmaxf(m, p[j]);
    #pragma unroll
    for (int o = 16; o > 0; o >>= 1) m = fmaxf(m, __shfl_xor_sync(0xffffffffu, m, o));
    if ((tid & 31) == 0) red[tid >> 5] = m;
    __syncthreads();
    if (tid < 32) {
        float t = (tid < 8) ? red[tid] : -3.4e38f;
        #pragma unroll
        for (int o = 4; o > 0; o >>= 1) t = fmaxf(t, __shfl_xor_sync(0xffffffffu, t, o));
        if (tid == 0) red[0] = t;
    }
    __syncthreads();
    m = red[0];
    float sum = 0.f;
    for (int j = tid; j < n; j += 256) { float e = __expf(p[j] - m); p[j] = e; sum += e; }
    __syncthreads();
    #pragma unroll
    for (int o = 16; o > 0; o >>= 1) sum += __shfl_xor_sync(0xffffffffu, sum, o);
    if ((tid & 31) == 0) red[tid >> 5] = sum;
    __syncthreads();
    if (tid < 32) {
        float t = (tid < 8) ? red[tid] : 0.f;
        #pragma unroll
        for (int o = 4; o > 0; o >>= 1) t += __shfl_xor_sync(0xffffffffu, t, o);
        if (tid == 0) red[0] = t;
    }
    __syncthreads();
    float inv = 1.0f / red[0];
    for (int j = tid; j < n; j += 256) p[j] = tf32r(p[j] * inv);
    for (int j = n + tid; j < S_; j += 256) p[j] = 0.f;
}

__global__ void transpose_k(const float* __restrict__ in, float* __restrict__ out,
                            int R, int C, int ldi, int ldo,
                            int nz2, long sI1, long sI2, long sO1, long sO2)
{
    int z = blockIdx.z, z1 = z / nz2, z2 = z - z1 * nz2;
    in  += z1 * sI1 + z2 * sI2;
    out += z1 * sO1 + z2 * sO2;
    __shared__ float t[32][33];
    int c0 = blockIdx.x * 32, r0 = blockIdx.y * 32;
    int x = threadIdx.x, y = threadIdx.y;
    #pragma unroll
    for (int i = 0; i < 32; i += 8) {
        int r = r0 + y + i;
        if (r < R && c0 + x < C) t[y + i][x] = in[(size_t)r * ldi + c0 + x];
    }
    __syncthreads();
    #pragma unroll
    for (int i = 0; i < 32; i += 8) {
        int c = c0 + y + i;
        if (c < C && r0 + x < R) out[(size_t)c * ldo + r0 + x] = tf32r(t[x][y + i]);
    }
}

__global__ void packb_k(const float* __restrict__ bq, const float* __restrict__ bk,
                        const float* __restrict__ bv) {
    int i = blockIdx.x * 256 + threadIdx.x;
    if (i >= NL_ * 3 * D_) return;
    int l = i / (3 * D_), r = i - l * 3 * D_;
    float v = (r < D_) ? bq[l * D_ + r] : (r < 2 * D_) ? bk[l * D_ + r - D_] : bv[l * D_ + r - 2 * D_];
    g_bqkv[i] = v;
}

// ============ launch helpers ============
template<bool RELU, bool RESID, bool BIAS, bool CAUSAL, bool ROUND>
static void tc_gemm(const float* A, const float* B, const float* bias, const float* Cin, float* C,
                    int M, int N, int K, int lda, int ldb, int ldc, float alpha = 1.f,
                    int Z = 1, int nz2 = 1,
                    long sA1 = 0, long sA2 = 0, long sB1 = 0, long sB2 = 0,
                    long sC1 = 0, long sC2 = 0)
{
    cudaFuncSetAttribute(gemm_mma256<RELU, RESID, BIAS, CAUSAL, ROUND>,
                         cudaFuncAttributeMaxDynamicSharedMemorySize, SMEM2);
    dim3 grid(cdiv(N, BN2), cdiv(M, BM2), Z);
    gemm_mma256<RELU, RESID, BIAS, CAUSAL, ROUND><<<grid, 256, SMEM2>>>(
        A, B, bias, Cin, C, M, N, K, lda, ldb, ldc,
        nz2, sA1, sA2, sB1, sB2, sC1, sC2, alpha);
}

template<bool ROUND, bool CAUSALK>
static void tc_gemm_sm(const float* A, const float* B, float* C,
                       int M, int N, int K, int lda, int ldb, int ldc, float alpha,
                       int Z, int nz2,
                       long sA1, long sA2, long sB1, long sB2, long sC1, long sC2)
{
    cudaFuncSetAttribute(gemm_mma128<ROUND, CAUSALK>,
                         cudaFuncAttributeMaxDynamicSharedMemorySize, SMEM1);
    dim3 grid(cdiv(N, BN1), cdiv(M, BM1), Z);
    gemm_mma128<ROUND, CAUSALK><<<grid, 128, SMEM1>>>(
        A, B, C, M, N, K, lda, ldb, ldc,
        nz2, sA1, sA2, sB1, sB2, sC1, sC2, alpha);
}

static void tr(const float* in, float* out, int R, int C, int ldi, int ldo,
               int Z, int nz2, long sI1, long sI2, long sO1, long sO2)
{
    dim3 grid(cdiv(C, 32), cdiv(R, 32), Z);
    transpose_k<<<grid, dim3(32, 8)>>>(in, out, R, C, ldi, ldo, nz2, sI1, sI2, sO1, sO2);
}

// ============ orchestration ============
extern "C" void kernel_launch(void* const* d_in, const int* in_sizes, int n_in,
                              void* d_out, int out_size) {
    const int*   idx   = (const int*)  d_in[0];
    const float* emb   = (const float*)d_in[1];
    const float* cls_b = (const float*)d_in[2];
    const float* ln1_s = (const float*)d_in[3];
    const float* ln1_b = (const float*)d_in[4];
    const float* wq    = (const float*)d_in[5];
    const float* bq    = (const float*)d_in[6];
    const float* wk    = (const float*)d_in[7];
    const float* bk    = (const float*)d_in[8];
    const float* wv    = (const float*)d_in[9];
    const float* bv    = (const float*)d_in[10];
    const float* wo    = (const float*)d_in[11];
    const float* bo    = (const float*)d_in[12];
    const float* ln2_s = (const float*)d_in[13];
    const float* ln2_b = (const float*)d_in[14];
    const float* w1    = (const float*)d_in[15];
    const float* b1    = (const float*)d_in[16];
    const float* w2    = (const float*)d_in[17];
    const float* b2    = (const float*)d_in[18];
    const float* lnf_s = (const float*)d_in[19];
    const float* lnf_b = (const float*)d_in[20];
    float* out = (float*)d_out;

    float *gx, *gh, *gqkv, *go, *gff, *gatt, *gvT, *gwqkv, *gwoT, *gw1T, *gw2T, *gbq, *gembr;
    cudaGetSymbolAddress((void**)&gx,   g_x);
    cudaGetSymbolAddress((void**)&gh,   g_h);
    cudaGetSymbolAddress((void**)&gqkv, g_qkv);
    cudaGetSymbolAddress((void**)&go,   g_o);
    cudaGetSymbolAddress((void**)&gff,  g_ff);
    cudaGetSymbolAddress((void**)&gatt, g_att);
    cudaGetSymbolAddress((void**)&gvT,  g_vT);
    cudaGetSymbolAddress((void**)&gwqkv,g_wqkv);
    cudaGetSymbolAddress((void**)&gwoT, g_woT);
    cudaGetSymbolAddress((void**)&gw1T, g_w1T);
    cudaGetSymbolAddress((void**)&gw2T, g_w2T);
    cudaGetSymbolAddress((void**)&gbq,  g_bqkv);
    cudaGetSymbolAddress((void**)&gembr,g_embr);

    // weight repack to K-major [N,K] (tf32-rounded)
    tr(wq, gwqkv,                   D_, DH_, DH_, D_, NL_*H_, H_,
       (long)H_*D_*DH_, (long)D_*DH_, (long)3*D_*D_, (long)DH_*D_);
    tr(wk, gwqkv + (size_t)D_*D_,   D_, DH_, DH_, D_, NL_*H_, H_,
       (long)H_*D_*DH_, (long)D_*DH_, (long)3*D_*D_, (long)DH_*D_);
    tr(wv, gwqkv + (size_t)2*D_*D_, D_, DH_, DH_, D_, NL_*H_, H_,
       (long)H_*D_*DH_, (long)D_*DH_, (long)3*D_*D_, (long)DH_*D_);
    tr(wo, gwoT, D_, D_, D_, D_, NL_, 1, (long)D_*D_, 0, (long)D_*D_, 0);
    tr(w1, gw1T, D_, DFF_, DFF_, D_, NL_, 1, (long)D_*DFF_, 0, (long)DFF_*D_, 0);
    tr(w2, gw2T, DFF_, D_, D_, DFF_, NL_, 1, (long)DFF_*D_, 0, (long)D_*DFF_, 0);
    packb_k<<<cdiv(NL_*3*D_, 256), 256>>>(bq, bk, bv);
    roundcpy_k<<<cdiv(V_*D_, 256), 256>>>(emb, gembr, (size_t)V_*D_);

    embed_k<<<cdiv(BSZ_*D_, 256), 256>>>(idx, emb);

    for (int l = 0; l < NL_; l++) {
        ln_k<<<BSZ_, 256>>>(gx, gh, ln1_s + l*D_, ln1_b + l*D_);

        // qkv: [2048,1024] @ [3072,1024]^T
        tc_gemm<false,false,true,false,true>(gh, gwqkv + (size_t)l*3*D_*D_, gbq + l*3*D_, nullptr, gqkv,
                                             BSZ_, 3*D_, D_, D_, D_, 3*D_);

        // scores = 1/8 * q @ k^T per (b,h), causal tile skip
        tc_gemm<false,false,false,true,false>(gqkv, gqkv + D_, nullptr, nullptr, gatt,
                                              S_, S_, DH_, 3*D_, 3*D_, S_, 0.125f,
                                              NB_*H_, H_,
                                              (long)S_*3*D_, DH_, (long)S_*3*D_, DH_,
                                              (long)H_*S_*S_, (long)S_*S_);

        softmax_k<<<NB_*H_*S_, 256>>>(gatt);

        // V^T per (b,h)
        tr(gqkv + 2*D_, gvT, S_, DH_, 3*D_, S_, NB_*H_, H_,
           (long)S_*3*D_, DH_, (long)H_*DH_*S_, (long)DH_*S_);

        // o = P @ (V^T)^T with causal K-trim
        tc_gemm_sm<true,true>(gatt, gvT, go,
                              S_, DH_, S_, S_, S_, D_, 1.f,
                              NB_*H_, H_,
                              (long)H_*S_*S_, (long)S_*S_,
                              (long)H_*DH_*S_, (long)DH_*S_,
                              (long)S_*D_, DH_);

        // x += o @ wo^T + bo
        tc_gemm<false,true,true,false,false>(go, gwoT + (size_t)l*D_*D_, bo + l*D_, gx, gx,
                                             BSZ_, D_, D_, D_, D_, D_);

        ln_k<<<BSZ_, 256>>>(gx, gh, ln2_s + l*D_, ln2_b + l*D_);

        tc_gemm<true,false,true,false,true>(gh, gw1T + (size_t)l*DFF_*D_, b1 + l*DFF_, nullptr, gff,
                                            BSZ_, DFF_, D_, D_, D_, DFF_);
        tc_gemm<false,true,true,false,false>(gff, gw2T + (size_t)l*D_*DFF_, b2 + l*D_, gx, gx,
                                             BSZ_, D_, DFF_, DFF_, DFF_, D_);
    }

    ln_k<<<BSZ_, 256>>>(gx, gh, lnf_s, lnf_b);

    tc_gemm<false,false,true,false,false>(gh, gembr, cls_b, nullptr, out,
                                          BSZ_, V_, D_, D_, D_, V_);
}

// round 7
// speedup vs baseline: 1.1030x; 1.1030x over previous
#include <cuda_runtime.h>
#include <math.h>
#include <cstdint>

// ---------------- problem constants ----------------
#define D_   1024
#define H_   16
#define DH_  64
#define NL_  4
#define DFF_ 4096
#define V_   32000
#define S_   1024
#define NB_  2
#define BSZ_ (NB_*S_)

static inline int cdiv(int a, int b) { return (a + b - 1) / b; }

// ---------------- scratch ----------------
__device__ float g_x   [BSZ_*D_];
__device__ float g_h   [BSZ_*D_];
__device__ float g_qkv [BSZ_*3*D_];
__device__ float g_o   [BSZ_*D_];
__device__ float g_ff  [BSZ_*DFF_];
__device__ float g_att [(size_t)NB_*H_*S_*S_];
__device__ float g_vT  [(size_t)NB_*H_*DH_*S_];
__device__ float g_wqkv[(size_t)NL_*3*D_*D_];
__device__ float g_woT [(size_t)NL_*D_*D_];
__device__ float g_w1T [(size_t)NL_*DFF_*D_];
__device__ float g_w2T [(size_t)NL_*D_*DFF_];
__device__ float g_bqkv[NL_*3*D_];
__device__ float g_embr[(size_t)V_*D_];

// ---------------- helpers ----------------
__device__ __forceinline__ float tf32r(float x) {
    uint32_t u;
    asm("cvt.rna.tf32.f32 %0, %1;" : "=r"(u) : "f"(x));
    return __uint_as_float(u);
}
// K-permutation within aligned groups of 8: (k,k+4) pairs become adjacent
__device__ __forceinline__ int p8(int k) { return (k < 4) ? 2 * k : 2 * k - 7; }
__device__ __forceinline__ int pcol(int i) { return (i & ~7) | p8(i & 7); }

__device__ __forceinline__ void mma1688(float* d, const uint32_t* a, const uint32_t* b) {
    asm volatile(
        "mma.sync.aligned.m16n8k8.row.col.f32.tf32.tf32.f32 "
        "{%0,%1,%2,%3}, {%4,%5,%6,%7}, {%8,%9}, {%0,%1,%2,%3};"
        : "+f"(d[0]), "+f"(d[1]), "+f"(d[2]), "+f"(d[3])
        : "r"(a[0]), "r"(a[1]), "r"(a[2]), "r"(a[3]), "r"(b[0]), "r"(b[1]));
}
__device__ __forceinline__ uint32_t smem_u32(const void* p) {
    uint32_t a;
    asm("{ .reg .u64 t; cvta.to.shared.u64 t, %1; cvt.u32.u64 %0, t; }" : "=r"(a) : "l"(p));
    return a;
}
__device__ __forceinline__ void cpa16(uint32_t dst, const float* src, bool pred) {
    int sz = pred ? 16 : 0;
    asm volatile("cp.async.cg.shared.global [%0], [%1], 16, %2;"
                 :: "r"(dst), "l"(src), "r"(sz) : "memory");
}
#define CPA_COMMIT() asm volatile("cp.async.commit_group;" ::: "memory")
#define CPA_WAIT1()  asm volatile("cp.async.wait_group 1;" ::: "memory")

constexpr int BK = 32, LDS_ = 36, NSTAGE = 3;
constexpr int BM1 = 128, BN1 = 128;
constexpr int STG1 = 2 * BM1 * LDS_;
constexpr int SMEM1 = NSTAGE * STG1 * 4;     // 110,592 B -> 2 CTAs/SM

// ============ v2-load GEMM (operands K-permuted by p8) ============
// C = alpha * A @ B^T (+bias)(+Cin)(relu)(round)(perm-N-stores)
template<bool RELU, bool RESID, bool BIAS, bool CAUSAL, bool ROUND, bool PERM>
__global__ void __launch_bounds__(128) gemm_v2(
    const float* __restrict__ Ag, const float* __restrict__ Bg,
    const float* __restrict__ biasg, const float* __restrict__ Cing,
    float* __restrict__ Cg,
    int M, int N, int K, int lda, int ldb, int ldc,
    int nz2, long sA1, long sA2, long sB1, long sB2, long sC1, long sC2,
    float alpha)
{
    int row0 = blockIdx.y * BM1;
    int col0 = blockIdx.x * BN1;
    if (CAUSAL && col0 > row0 + BM1 - 1) return;

    int z = blockIdx.z, z1 = z / nz2, z2 = z - z1 * nz2;
    const float* A   = Ag + z1 * sA1 + z2 * sA2;
    const float* B   = Bg + z1 * sB1 + z2 * sB2;
    float*       C   = Cg + z1 * sC1 + z2 * sC2;
    const float* Cin = RESID ? (Cing + z1 * sC1 + z2 * sC2) : nullptr;

    extern __shared__ float sm[];
    uint32_t sm0 = smem_u32(sm);

    int tid = threadIdx.x;
    int wid = tid >> 5, lane = tid & 31;
    int wm = wid >> 1, wn = wid & 1;
    int gid = lane >> 2, tig = lane & 3;

    int cr = tid >> 3;
    int cc = (tid & 7) * 4;

    float acc[4][8][4];
    #pragma unroll
    for (int a = 0; a < 4; a++)
        #pragma unroll
        for (int b = 0; b < 8; b++)
            #pragma unroll
            for (int c = 0; c < 4; c++) acc[a][b][c] = 0.f;

    int KT = K / BK;

    auto issue = [&](int kt, int slot) {
        int k0 = kt * BK;
        uint32_t abase = sm0 + (uint32_t)slot * STG1 * 4;
        uint32_t bbase = abase + BM1 * LDS_ * 4;
        #pragma unroll
        for (int i = 0; i < 8; i++) {
            int r = cr + i * 16;
            int gm = row0 + r;
            const float* pa = A + (size_t)(gm < M ? gm : 0) * lda + k0 + cc;
            cpa16(abase + (r * LDS_ + cc) * 4, pa, gm < M);
            int gn = col0 + r;
            const float* pb = B + (size_t)(gn < N ? gn : 0) * ldb + k0 + cc;
            cpa16(bbase + (r * LDS_ + cc) * 4, pb, gn < N);
        }
    };

    int nPre = KT < (NSTAGE - 1) ? KT : (NSTAGE - 1);
    for (int p = 0; p < nPre; p++) { issue(p, p); CPA_COMMIT(); }

    for (int kt = 0; kt < KT; kt++) {
        CPA_WAIT1();
        __syncthreads();
        int nxt = kt + NSTAGE - 1;
        if (nxt < KT) issue(nxt, nxt % NSTAGE);
        CPA_COMMIT();

        const float* As = sm + (kt % NSTAGE) * STG1;
        const float* Bs = As + BM1 * LDS_;
        const float* Ab = As + (wm * 64 + gid) * LDS_;
        const float* Bb = Bs + (wn * 64 + gid) * LDS_;

        #pragma unroll
        for (int ks = 0; ks < 4; ks++) {
            int c2 = ks * 8 + 2 * tig;       // permuted pair (k, k+4)
            uint32_t af[4][4], bf[8][2];
            #pragma unroll
            for (int mt = 0; mt < 4; mt++) {
                const float* p = Ab + mt * 16 * LDS_;
                float2 a01 = *(const float2*)(p + c2);
                float2 a23 = *(const float2*)(p + 8 * LDS_ + c2);
                af[mt][0] = __float_as_uint(a01.x);
                af[mt][1] = __float_as_uint(a23.x);
                af[mt][2] = __float_as_uint(a01.y);
                af[mt][3] = __float_as_uint(a23.y);
            }
            #pragma unroll
            for (int nt = 0; nt < 8; nt++) {
                float2 b01 = *(const float2*)(Bb + nt * 8 * LDS_ + c2);
                bf[nt][0] = __float_as_uint(b01.x);
                bf[nt][1] = __float_as_uint(b01.y);
            }
            #pragma unroll
            for (int mt = 0; mt < 4; mt++)
                #pragma unroll
                for (int nt = 0; nt < 8; nt++)
                    mma1688(acc[mt][nt], af[mt], bf[nt]);
        }
    }

    #pragma unroll
    for (int mt = 0; mt < 4; mt++) {
        #pragma unroll
        for (int half = 0; half < 2; half++) {
            int gm = row0 + wm * 64 + mt * 16 + gid + half * 8;
            if (gm >= M) continue;
            #pragma unroll
            for (int nt = 0; nt < 8; nt++) {
                int gn = col0 + wn * 64 + nt * 8 + 2 * tig;
                if (gn >= N) continue;
                float v0 = acc[mt][nt][half * 2 + 0] * alpha;
                float v1 = acc[mt][nt][half * 2 + 1] * alpha;
                if (BIAS)  { v0 += biasg[gn]; v1 += biasg[gn + 1]; }
                if (RESID) {
                    const float* ci = Cin + (size_t)gm * ldc + gn;
                    v0 += ci[0]; v1 += ci[1];
                }
                if (RELU) { v0 = fmaxf(v0, 0.f); v1 = fmaxf(v1, 0.f); }
                if (ROUND) { v0 = tf32r(v0); v1 = tf32r(v1); }
                if (PERM) {
                    float* cp = C + (size_t)gm * ldc;
                    cp[pcol(gn)]     = v0;
                    cp[pcol(gn + 1)] = v1;
                } else {
                    *(float2*)(C + (size_t)gm * ldc + gn) = make_float2(v0, v1);
                }
            }
        }
    }
}

// ============ scalar-load GEMM (natural K-order) for P@V with causal trim ============
template<bool ROUND, bool CAUSALK>
__global__ void __launch_bounds__(128) gemm_sc(
    const float* __restrict__ Ag, const float* __restrict__ Bg,
    float* __restrict__ Cg,
    int M, int N, int K, int lda, int ldb, int ldc,
    int nz2, long sA1, long sA2, long sB1, long sB2, long sC1, long sC2,
    float alpha)
{
    int row0 = blockIdx.y * BM1;
    int col0 = blockIdx.x * BN1;

    int z = blockIdx.z, z1 = z / nz2, z2 = z - z1 * nz2;
    const float* A = Ag + z1 * sA1 + z2 * sA2;
    const float* B = Bg + z1 * sB1 + z2 * sB2;
    float*       C = Cg + z1 * sC1 + z2 * sC2;

    extern __shared__ float sm[];
    uint32_t sm0 = smem_u32(sm);

    int tid = threadIdx.x;
    int wid = tid >> 5, lane = tid & 31;
    int wm = wid >> 1, wn = wid & 1;
    int gid = lane >> 2, tig = lane & 3;

    int cr = tid >> 3;
    int cc = (tid & 7) * 4;

    float acc[4][8][4];
    #pragma unroll
    for (int a = 0; a < 4; a++)
        #pragma unroll
        for (int b = 0; b < 8; b++)
            #pragma unroll
            for (int c = 0; c < 4; c++) acc[a][b][c] = 0.f;

    int KT = K / BK;
    if (CAUSALK) { int lim = (row0 + BM1) / BK; if (lim < KT) KT = lim; }

    auto issue = [&](int kt, int slot) {
        int k0 = kt * BK;
        uint32_t abase = sm0 + (uint32_t)slot * STG1 * 4;
        uint32_t bbase = abase + BM1 * LDS_ * 4;
        #pragma unroll
        for (int i = 0; i < 8; i++) {
            int r = cr + i * 16;
            int gm = row0 + r;
            const float* pa = A + (size_t)(gm < M ? gm : 0) * lda + k0 + cc;
            cpa16(abase + (r * LDS_ + cc) * 4, pa, gm < M);
            int gn = col0 + r;
            const float* pb = B + (size_t)(gn < N ? gn : 0) * ldb + k0 + cc;
            cpa16(bbase + (r * LDS_ + cc) * 4, pb, gn < N);
        }
    };

    int nPre = KT < (NSTAGE - 1) ? KT : (NSTAGE - 1);
    for (int p = 0; p < nPre; p++) { issue(p, p); CPA_COMMIT(); }

    for (int kt = 0; kt < KT; kt++) {
        CPA_WAIT1();
        __syncthreads();
        int nxt = kt + NSTAGE - 1;
        if (nxt < KT) issue(nxt, nxt % NSTAGE);
        CPA_COMMIT();

        const float* As = sm + (kt % NSTAGE) * STG1;
        const float* Bs = As + BM1 * LDS_;
        const float* Ab = As + (wm * 64 + gid) * LDS_;
        const float* Bb = Bs + (wn * 64 + gid) * LDS_;

        #pragma unroll
        for (int ks = 0; ks < 4; ks++) {
            int kc = ks * 8 + tig;
            uint32_t af[4][4], bf[8][2];
            #pragma unroll
            for (int mt = 0; mt < 4; mt++) {
                const float* p = Ab + mt * 16 * LDS_;
                af[mt][0] = __float_as_uint(p[kc]);
                af[mt][1] = __float_as_uint(p[8 * LDS_ + kc]);
                af[mt][2] = __float_as_uint(p[kc + 4]);
                af[mt][3] = __float_as_uint(p[8 * LDS_ + kc + 4]);
            }
            #pragma unroll
            for (int nt = 0; nt < 8; nt++) {
                const float* p = Bb + nt * 8 * LDS_;
                bf[nt][0] = __float_as_uint(p[kc]);
                bf[nt][1] = __float_as_uint(p[kc + 4]);
            }
            #pragma unroll
            for (int mt = 0; mt < 4; mt++)
                #pragma unroll
                for (int nt = 0; nt < 8; nt++)
                    mma1688(acc[mt][nt], af[mt], bf[nt]);
        }
    }

    #pragma unroll
    for (int mt = 0; mt < 4; mt++) {
        #pragma unroll
        for (int half = 0; half < 2; half++) {
            int gm = row0 + wm * 64 + mt * 16 + gid + half * 8;
            if (gm >= M) continue;
            #pragma unroll
            for (int nt = 0; nt < 8; nt++) {
                int gn = col0 + wn * 64 + nt * 8 + 2 * tig;
                if (gn >= N) continue;
                float v0 = acc[mt][nt][half * 2 + 0] * alpha;
                float v1 = acc[mt][nt][half * 2 + 1] * alpha;
                if (ROUND) { v0 = tf32r(v0); v1 = tf32r(v1); }
                *(float2*)(C + (size_t)gm * ldc + gn) = make_float2(v0, v1);
            }
        }
    }
}

// ============ auxiliary kernels ============
// embed + PE; first threads also pack qkv biases
__global__ void embed_k(const int* __restrict__ idx, const float* __restrict__ emb,
                        const float* __restrict__ bq, const float* __restrict__ bk,
                        const float* __restrict__ bv) {
    int t = blockIdx.x * blockDim.x + threadIdx.x;
    if (t < NL_ * 3 * D_) {
        int l = t / (3 * D_), r = t - l * 3 * D_;
        float v = (r < D_) ? bq[l * D_ + r] : (r < 2 * D_) ? bk[l * D_ + r - D_] : bv[l * D_ + r - 2 * D_];
        g_bqkv[t] = v;
    }
    if (t >= BSZ_ * D_) return;
    int d = t & (D_ - 1);
    int bs = t >> 10;
    int s = bs & (S_ - 1);
    int tok = idx[bs];
    int i2 = d & ~1;
    float freq = __expf((float)i2 * (-9.210340371976184f / (float)D_));
    float ang = (float)s * freq;
    float pe = (d & 1) ? cosf(ang) : sinf(ang);
    g_x[t] = emb[(size_t)tok * D_ + d] * 32.0f + pe;
}

// rounded + K-permuted copy (for classifier weight)
__global__ void roundcpy_k(const float* __restrict__ in, float* __restrict__ out, size_t n) {
    size_t i = (size_t)blockIdx.x * blockDim.x + threadIdx.x;
    if (i >= n) return;
    size_t row = i >> 10;
    int d = (int)(i & (D_ - 1));
    out[(row << 10) + pcol(d)] = tf32r(in[i]);
}

// layernorm -> tf32, K-permuted output
__global__ void ln_k(const float* __restrict__ in, float* __restrict__ out,
                     const float* __restrict__ sc, const float* __restrict__ bi) {
    int row = blockIdx.x;
    const float* x = in + (size_t)row * D_;
    int tid = threadIdx.x;
    float s = 0.f, ss = 0.f;
    for (int i = tid; i < D_; i += 256) { float v = x[i]; s += v; ss = fmaf(v, v, ss); }
    __shared__ float rs[8], rq[8];
    #pragma unroll
    for (int o = 16; o > 0; o >>= 1) {
        s  += __shfl_xor_sync(0xffffffffu, s,  o);
        ss += __shfl_xor_sync(0xffffffffu, ss, o);
    }
    if ((tid & 31) == 0) { rs[tid >> 5] = s; rq[tid >> 5] = ss; }
    __syncthreads();
    if (tid < 32) {
        float a = (tid < 8) ? rs[tid] : 0.f;
        float b = (tid < 8) ? rq[tid] : 0.f;
        #pragma unroll
        for (int o = 4; o > 0; o >>= 1) {
            a += __shfl_xor_sync(0xffffffffu, a, o);
            b += __shfl_xor_sync(0xffffffffu, b, o);
        }
        if (tid == 0) { rs[0] = a; rq[0] = b; }
    }
    __syncthreads();
    float mean = rs[0] * (1.0f / D_);
    float var  = rq[0] * (1.0f / D_) - mean * mean;
    float inv  = rsqrtf(var + 1e-5f);
    for (int i = tid; i < D_; i += 256)
        out[(size_t)row * D_ + pcol(i)] = tf32r((x[i] - mean) * inv * sc[i] + bi[i]);
}

__global__ void softmax_k(float* __restrict__ att) {
    size_t row = blockIdx.x;
    int i = (int)(row & (S_ - 1));
    float* p = att + row * (size_t)S_;
    int n = i + 1;
    int tid = threadIdx.x;
    __shared__ float red[8];
    float m = -3.4e38f;
    for (int j = tid; j < n; j += 256) m = fmaxf(m, p[j]);
    #pragma unroll
    for (int o = 16; o > 0; o >>= 1) m = fmaxf(m, __shfl_xor_sync(0xffffffffu, m, o));
    if ((tid & 31) == 0) red[tid >> 5] = m;
    __syncthreads();
    if (tid < 32) {
        float t = (tid < 8) ? red[tid] : -3.4e38f;
        #pragma unroll
        for (int o = 4; o > 0; o >>= 1) t = fmaxf(t, __shfl_xor_sync(0xffffffffu, t, o));
        if (tid == 0) red[0] = t;
    }
    __syncthreads();
    m = red[0];
    float sum = 0.f;
    for (int j = tid; j < n; j += 256) { float e = __expf(p[j] - m); p[j] = e; sum += e; }
    __syncthreads();
    #pragma unroll
    for (int o = 16; o > 0; o >>= 1) sum += __shfl_xor_sync(0xffffffffu, sum, o);
    if ((tid & 31) == 0) red[tid >> 5] = sum;
    __syncthreads();
    if (tid < 32) {
        float t = (tid < 8) ? red[tid] : 0.f;
        #pragma unroll
        for (int o = 4; o > 0; o >>= 1) t += __shfl_xor_sync(0xffffffffu, t, o);
        if (tid == 0) red[0] = t;
    }
    __syncthreads();
    float inv = 1.0f / red[0];
    for (int j = tid; j < n; j += 256) p[j] = tf32r(p[j] * inv);
    for (int j = n + tid; j < S_; j += 256) p[j] = 0.f;
}

// transpose with optional K-permutation of output column index
template<bool PERMC>
__global__ void transpose_k(const float* __restrict__ in, float* __restrict__ out,
                            int R, int C, int ldi, int ldo,
                            int nz2, long sI1, long sI2, long sO1, long sO2)
{
    int z = blockIdx.z, z1 = z / nz2, z2 = z - z1 * nz2;
    in  += z1 * sI1 + z2 * sI2;
    out += z1 * sO1 + z2 * sO2;
    __shared__ float t[32][33];
    int c0 = blockIdx.x * 32, r0 = blockIdx.y * 32;
    int x = threadIdx.x, y = threadIdx.y;
    #pragma unroll
    for (int i = 0; i < 32; i += 8) {
        int r = r0 + y + i;
        if (r < R && c0 + x < C) t[y + i][x] = in[(size_t)r * ldi + c0 + x];
    }
    __syncthreads();
    #pragma unroll
    for (int i = 0; i < 32; i += 8) {
        int c = c0 + y + i;
        int rr = r0 + x;
        if (c < C && rr < R) {
            int wcol = PERMC ? pcol(rr) : rr;
            out[(size_t)c * ldo + wcol] = tf32r(t[x][y + i]);
        }
    }
}

// ============ launch helpers ============
template<bool RELU, bool RESID, bool BIAS, bool CAUSAL, bool ROUND, bool PERM>
static void tc_gemm(const float* A, const float* B, const float* bias, const float* Cin, float* C,
                    int M, int N, int K, int lda, int ldb, int ldc, float alpha = 1.f,
                    int Z = 1, int nz2 = 1,
                    long sA1 = 0, long sA2 = 0, long sB1 = 0, long sB2 = 0,
                    long sC1 = 0, long sC2 = 0)
{
    cudaFuncSetAttribute(gemm_v2<RELU, RESID, BIAS, CAUSAL, ROUND, PERM>,
                         cudaFuncAttributeMaxDynamicSharedMemorySize, SMEM1);
    dim3 grid(cdiv(N, BN1), cdiv(M, BM1), Z);
    gemm_v2<RELU, RESID, BIAS, CAUSAL, ROUND, PERM><<<grid, 128, SMEM1>>>(
        A, B, bias, Cin, C, M, N, K, lda, ldb, ldc,
        nz2, sA1, sA2, sB1, sB2, sC1, sC2, alpha);
}

template<bool ROUND, bool CAUSALK>
static void tc_gemm_sc(const float* A, const float* B, float* C,
                       int M, int N, int K, int lda, int ldb, int ldc, float alpha,
                       int Z, int nz2,
                       long sA1, long sA2, long sB1, long sB2, long sC1, long sC2)
{
    cudaFuncSetAttribute(gemm_sc<ROUND, CAUSALK>,
                         cudaFuncAttributeMaxDynamicSharedMemorySize, SMEM1);
    dim3 grid(cdiv(N, BN1), cdiv(M, BM1), Z);
    gemm_sc<ROUND, CAUSALK><<<grid, 128, SMEM1>>>(
        A, B, C, M, N, K, lda, ldb, ldc,
        nz2, sA1, sA2, sB1, sB2, sC1, sC2, alpha);
}

template<bool PERMC>
static void tr(const float* in, float* out, int R, int C, int ldi, int ldo,
               int Z, int nz2, long sI1, long sI2, long sO1, long sO2)
{
    dim3 grid(cdiv(C, 32), cdiv(R, 32), Z);
    transpose_k<PERMC><<<grid, dim3(32, 8)>>>(in, out, R, C, ldi, ldo, nz2, sI1, sI2, sO1, sO2);
}

// ============ orchestration ============
extern "C" void kernel_launch(void* const* d_in, const int* in_sizes, int n_in,
                              void* d_out, int out_size) {
    const int*   idx   = (const int*)  d_in[0];
    const float* emb   = (const float*)d_in[1];
    const float* cls_b = (const float*)d_in[2];
    const float* ln1_s = (const float*)d_in[3];
    const float* ln1_b = (const float*)d_in[4];
    const float* wq    = (const float*)d_in[5];
    const float* bq    = (const float*)d_in[6];
    const float* wk    = (const float*)d_in[7];
    const float* bk    = (const float*)d_in[8];
    const float* wv    = (const float*)d_in[9];
    const float* bv    = (const float*)d_in[10];
    const float* wo    = (const float*)d_in[11];
    const float* bo    = (const float*)d_in[12];
    const float* ln2_s = (const float*)d_in[13];
    const float* ln2_b = (const float*)d_in[14];
    const float* w1    = (const float*)d_in[15];
    const float* b1    = (const float*)d_in[16];
    const float* w2    = (const float*)d_in[17];
    const float* b2    = (const float*)d_in[18];
    const float* lnf_s = (const float*)d_in[19];
    const float* lnf_b = (const float*)d_in[20];
    float* out = (float*)d_out;

    float *gx, *gh, *gqkv, *go, *gff, *gatt, *gvT, *gwqkv, *gwoT, *gw1T, *gw2T, *gbq, *gembr;
    cudaGetSymbolAddress((void**)&gx,   g_x);
    cudaGetSymbolAddress((void**)&gh,   g_h);
    cudaGetSymbolAddress((void**)&gqkv, g_qkv);
    cudaGetSymbolAddress((void**)&go,   g_o);
    cudaGetSymbolAddress((void**)&gff,  g_ff);
    cudaGetSymbolAddress((void**)&gatt, g_att);
    cudaGetSymbolAddress((void**)&gvT,  g_vT);
    cudaGetSymbolAddress((void**)&gwqkv,g_wqkv);
    cudaGetSymbolAddress((void**)&gwoT, g_woT);
    cudaGetSymbolAddress((void**)&gw1T, g_w1T);
    cudaGetSymbolAddress((void**)&gw2T, g_w2T);
    cudaGetSymbolAddress((void**)&gbq,  g_bqkv);
    cudaGetSymbolAddress((void**)&gembr,g_embr);

    // launch 1: embed (+bias pack)
    embed_k<<<cdiv(BSZ_*D_, 256), 256>>>(idx, emb, bq, bk, bv);
    // launches 2-4: QKV weight repack, K-permuted
    tr<true>(wq, gwqkv,                   D_, DH_, DH_, D_, NL_*H_, H_,
             (long)H_*D_*DH_, (long)D_*DH_, (long)3*D_*D_, (long)DH_*D_);
    tr<true>(wk, gwqkv + (size_t)D_*D_,   D_, DH_, DH_, D_, NL_*H_, H_,
             (long)H_*D_*DH_, (long)D_*DH_, (long)3*D_*D_, (long)DH_*D_);
    tr<true>(wv, gwqkv + (size_t)2*D_*D_, D_, DH_, DH_, D_, NL_*H_, H_,
             (long)H_*D_*DH_, (long)D_*DH_, (long)3*D_*D_, (long)DH_*D_);

    const long sQ  = (long)S_ * 3 * D_;
    const long sAT = (long)H_ * S_ * S_;

    for (int l = 0; l < NL_; l++) {
        // launch 5 (l=0): ln1
        ln_k<<<BSZ_, 256>>>(gx, gh, ln1_s + l*D_, ln1_b + l*D_);

        // launch 6 (l=0): QKV GEMM  <- profiled by ncu -s 5 -c 1
        tc_gemm<false,false,true,false,true,true>(gh, gwqkv + (size_t)l*3*D_*D_, gbq + l*3*D_,
                                                  nullptr, gqkv,
                                                  BSZ_, 3*D_, D_, D_, D_, 3*D_);

        // scores = 1/8 * q @ k^T  (K = e, permuted on both sides)
        tc_gemm<false,false,false,true,false,false>(gqkv, gqkv + D_, nullptr, nullptr, gatt,
                                                    S_, S_, DH_, 3*D_, 3*D_, S_, 0.125f,
                                                    NB_*H_, H_,
                                                    sQ, DH_, sQ, DH_,
                                                    sAT, (long)S_*S_);

        softmax_k<<<NB_*H_*S_, 256>>>(gatt);

        // V^T per (b,h): rows = e (perm order carried from v), cols = j natural
        tr<false>(gqkv + 2*D_, gvT, S_, DH_, 3*D_, S_, NB_*H_, H_,
                  sQ, DH_, (long)H_*DH_*S_, (long)DH_*S_);

        // o = P @ (V^T)^T with causal K-trim (natural j order, scalar kernel)
        tc_gemm_sc<true,true>(gatt, gvT, go,
                              S_, DH_, S_, S_, S_, D_, 1.f,
                              NB_*H_, H_,
                              sAT, (long)S_*S_,
                              (long)H_*DH_*S_, (long)DH_*S_,
                              (long)S_*D_, DH_);

        if (l == 0)   // woT repack (K = attention-concat D, permuted)
            tr<true>(wo, gwoT, D_, D_, D_, D_, NL_, 1, (long)D_*D_, 0, (long)D_*D_, 0);

        // x += o @ wo^T + bo
        tc_gemm<false,true,true,false,false,false>(go, gwoT + (size_t)l*D_*D_, bo + l*D_, gx, gx,
                                                   BSZ_, D_, D_, D_, D_, D_);

        ln_k<<<BSZ_, 256>>>(gx, gh, ln2_s + l*D_, ln2_b + l*D_);

        if (l == 0)
            tr<true>(w1, gw1T, D_, DFF_, DFF_, D_, NL_, 1, (long)D_*DFF_, 0, (long)DFF_*D_, 0);

        // ff = relu(h @ w1 + b1)  (output K-permuted for FFN2)
        tc_gemm<true,false,true,false,true,true>(gh, gw1T + (size_t)l*DFF_*D_, b1 + l*DFF_,
                                                 nullptr, gff,
                                                 BSZ_, DFF_, D_, D_, D_, DFF_);

        if (l == 0)
            tr<true>(w2, gw2T, DFF_, D_, D_, DFF_, NL_, 1, (long)DFF_*D_, 0, (long)D_*DFF_, 0);

        // x += ff @ w2 + b2
        tc_gemm<false,true,true,false,false,false>(gff, gw2T + (size_t)l*D_*DFF_, b2 + l*D_, gx, gx,
                                                   BSZ_, D_, DFF_, DFF_, DFF_, D_);
    }

    ln_k<<<BSZ_, 256>>>(gx, gh, lnf_s, lnf_b);

    // classifier weight: rounded + K-permuted copy
    roundcpy_k<<<cdiv(V_*D_, 256), 256>>>(emb, gembr, (size_t)V_*D_);

    // logits = h @ emb^T + cls_b
    tc_gemm<false,false,true,false,false,false>(gh, gembr, cls_b, nullptr, out,
                                                BSZ_, V_, D_, D_, D_, V_);
}

// round 8
// speedup vs baseline: 1.1901x; 1.0789x over previous
#include <cuda_runtime.h>
#include <math.h>
#include <cstdint>

// ---------------- problem constants ----------------
#define D_   1024
#define H_   16
#define DH_  64
#define NL_  4
#define DFF_ 4096
#define V_   32000
#define S_   1024
#define NB_  2
#define BSZ_ (NB_*S_)

static inline int cdiv(int a, int b) { return (a + b - 1) / b; }

// ---------------- scratch ----------------
__device__ float g_x   [BSZ_*D_];
__device__ float g_h   [BSZ_*D_];
__device__ float g_qkv [BSZ_*3*D_];
__device__ float g_o   [BSZ_*D_];
__device__ float g_ff  [BSZ_*DFF_];
__device__ float g_att [(size_t)NB_*H_*S_*S_];
__device__ float g_vT  [(size_t)NB_*H_*DH_*S_];
__device__ float g_wqkv[(size_t)NL_*3*D_*D_];
__device__ float g_woT [(size_t)NL_*D_*D_];
__device__ float g_w1T [(size_t)NL_*DFF_*D_];
__device__ float g_w2T [(size_t)NL_*D_*DFF_];
__device__ float g_bqkv[NL_*3*D_];
__device__ float g_embr[(size_t)V_*D_];

// ---------------- helpers ----------------
__device__ __forceinline__ float tf32r(float x) {
    uint32_t u;
    asm("cvt.rna.tf32.f32 %0, %1;" : "=r"(u) : "f"(x));
    return __uint_as_float(u);
}
__device__ __forceinline__ void mma1688(float* d, const uint32_t* a, const uint32_t* b) {
    asm volatile(
        "mma.sync.aligned.m16n8k8.row.col.f32.tf32.tf32.f32 "
        "{%0,%1,%2,%3}, {%4,%5,%6,%7}, {%8,%9}, {%0,%1,%2,%3};"
        : "+f"(d[0]), "+f"(d[1]), "+f"(d[2]), "+f"(d[3])
        : "r"(a[0]), "r"(a[1]), "r"(a[2]), "r"(a[3]), "r"(b[0]), "r"(b[1]));
}
__device__ __forceinline__ uint32_t smem_u32(const void* p) {
    uint32_t a;
    asm("{ .reg .u64 t; cvta.to.shared.u64 t, %1; cvt.u32.u64 %0, t; }" : "=r"(a) : "l"(p));
    return a;
}
__device__ __forceinline__ void cpa16(uint32_t dst, const float* src, bool pred) {
    int sz = pred ? 16 : 0;
    asm volatile("cp.async.cg.shared.global [%0], [%1], 16, %2;"
                 :: "r"(dst), "l"(src), "r"(sz) : "memory");
}
#define CPA_COMMIT() asm volatile("cp.async.commit_group;" ::: "memory")
#define CPA_WAIT1()  asm volatile("cp.async.wait_group 1;" ::: "memory")

constexpr int BK = 32, LDS_ = 36, NSTAGE = 3;
constexpr int BM1 = 128, BN1 = 128;
constexpr int STG1 = 2 * BM1 * LDS_;
constexpr int SMEM1 = NSTAGE * STG1 * 4;     // 110,592 B -> 2 CTAs/SM

// ============ tf32 mma.sync GEMM (R5-proven, scalar conflict-free LDS) ============
// C = alpha * A @ B^T (+bias)(+Cin)(relu)(round)
// SWAPXY: blockIdx.x indexes M-tiles, blockIdx.y indexes N-tiles (L2-friendly for N>>M)
// CAUSALK: trim K loop to K <= row0+BM (for P@V where A cols j>row are zero)
template<bool RELU, bool RESID, bool BIAS, bool CAUSAL, bool ROUND, bool SWAPXY, bool CAUSALK>
__global__ void __launch_bounds__(128) gemm_mma(
    const float* __restrict__ Ag, const float* __restrict__ Bg,
    const float* __restrict__ biasg, const float* __restrict__ Cing,
    float* __restrict__ Cg,
    int M, int N, int K, int lda, int ldb, int ldc,
    int nz2, long sA1, long sA2, long sB1, long sB2, long sC1, long sC2,
    float alpha)
{
    int row0 = (SWAPXY ? blockIdx.x : blockIdx.y) * BM1;
    int col0 = (SWAPXY ? blockIdx.y : blockIdx.x) * BN1;
    if (CAUSAL && col0 > row0 + BM1 - 1) return;

    int z = blockIdx.z, z1 = z / nz2, z2 = z - z1 * nz2;
    const float* A   = Ag + z1 * sA1 + z2 * sA2;
    const float* B   = Bg + z1 * sB1 + z2 * sB2;
    float*       C   = Cg + z1 * sC1 + z2 * sC2;
    const float* Cin = RESID ? (Cing + z1 * sC1 + z2 * sC2) : nullptr;

    extern __shared__ float sm[];
    uint32_t sm0 = smem_u32(sm);

    int tid = threadIdx.x;
    int wid = tid >> 5, lane = tid & 31;
    int wm = wid >> 1, wn = wid & 1;          // 2x2 warps, 64x64 each
    int gid = lane >> 2, tig = lane & 3;

    int cr = tid >> 3;
    int cc = (tid & 7) * 4;

    float acc[4][8][4];
    #pragma unroll
    for (int a = 0; a < 4; a++)
        #pragma unroll
        for (int b = 0; b < 8; b++)
            #pragma unroll
            for (int c = 0; c < 4; c++) acc[a][b][c] = 0.f;

    int KT = K / BK;
    if (CAUSALK) { int lim = (row0 + BM1) / BK; if (lim < KT) KT = lim; }

    auto issue = [&](int kt, int slot) {
        int k0 = kt * BK;
        uint32_t abase = sm0 + (uint32_t)slot * STG1 * 4;
        uint32_t bbase = abase + BM1 * LDS_ * 4;
        #pragma unroll
        for (int i = 0; i < 8; i++) {
            int r = cr + i * 16;
            int gm = row0 + r;
            const float* pa = A + (size_t)(gm < M ? gm : 0) * lda + k0 + cc;
            cpa16(abase + (r * LDS_ + cc) * 4, pa, gm < M);
            int gn = col0 + r;
            const float* pb = B + (size_t)(gn < N ? gn : 0) * ldb + k0 + cc;
            cpa16(bbase + (r * LDS_ + cc) * 4, pb, gn < N);
        }
    };

    int nPre = KT < (NSTAGE - 1) ? KT : (NSTAGE - 1);
    for (int p = 0; p < nPre; p++) { issue(p, p); CPA_COMMIT(); }

    for (int kt = 0; kt < KT; kt++) {
        CPA_WAIT1();
        __syncthreads();
        int nxt = kt + NSTAGE - 1;
        if (nxt < KT) issue(nxt, nxt % NSTAGE);
        CPA_COMMIT();

        const float* As = sm + (kt % NSTAGE) * STG1;
        const float* Bs = As + BM1 * LDS_;
        const float* Ab = As + (wm * 64 + gid) * LDS_;
        const float* Bb = Bs + (wn * 64 + gid) * LDS_;

        #pragma unroll
        for (int ks = 0; ks < 4; ks++) {
            int kc = ks * 8 + tig;
            uint32_t af[4][4], bf[8][2];
            #pragma unroll
            for (int mt = 0; mt < 4; mt++) {
                const float* p = Ab + mt * 16 * LDS_;
                af[mt][0] = __float_as_uint(p[kc]);
                af[mt][1] = __float_as_uint(p[8 * LDS_ + kc]);
                af[mt][2] = __float_as_uint(p[kc + 4]);
                af[mt][3] = __float_as_uint(p[8 * LDS_ + kc + 4]);
            }
            #pragma unroll
            for (int nt = 0; nt < 8; nt++) {
                const float* p = Bb + nt * 8 * LDS_;
                bf[nt][0] = __float_as_uint(p[kc]);
                bf[nt][1] = __float_as_uint(p[kc + 4]);
            }
            #pragma unroll
            for (int mt = 0; mt < 4; mt++)
                #pragma unroll
                for (int nt = 0; nt < 8; nt++)
                    mma1688(acc[mt][nt], af[mt], bf[nt]);
        }
    }

    #pragma unroll
    for (int mt = 0; mt < 4; mt++) {
        #pragma unroll
        for (int half = 0; half < 2; half++) {
            int gm = row0 + wm * 64 + mt * 16 + gid + half * 8;
            if (gm >= M) continue;
            #pragma unroll
            for (int nt = 0; nt < 8; nt++) {
                int gn = col0 + wn * 64 + nt * 8 + 2 * tig;
                if (gn >= N) continue;
                float v0 = acc[mt][nt][half * 2 + 0] * alpha;
                float v1 = acc[mt][nt][half * 2 + 1] * alpha;
                if (BIAS)  { v0 += biasg[gn]; v1 += biasg[gn + 1]; }
                if (RESID) {
                    const float* ci = Cin + (size_t)gm * ldc + gn;
                    v0 += ci[0]; v1 += ci[1];
                }
                if (RELU) { v0 = fmaxf(v0, 0.f); v1 = fmaxf(v1, 0.f); }
                if (ROUND) { v0 = tf32r(v0); v1 = tf32r(v1); }
                *(float2*)(C + (size_t)gm * ldc + gn) = make_float2(v0, v1);
            }
        }
    }
}

// ============ auxiliary kernels ============
__global__ void embed_k(const int* __restrict__ idx, const float* __restrict__ emb,
                        const float* __restrict__ bq, const float* __restrict__ bk,
                        const float* __restrict__ bv) {
    int t = blockIdx.x * blockDim.x + threadIdx.x;
    if (t < NL_ * 3 * D_) {
        int l = t / (3 * D_), r = t - l * 3 * D_;
        float v = (r < D_) ? bq[l * D_ + r] : (r < 2 * D_) ? bk[l * D_ + r - D_] : bv[l * D_ + r - 2 * D_];
        g_bqkv[t] = v;
    }
    if (t >= BSZ_ * D_) return;
    int d = t & (D_ - 1);
    int bs = t >> 10;
    int s = bs & (S_ - 1);
    int tok = idx[bs];
    int i2 = d & ~1;
    float freq = __expf((float)i2 * (-9.210340371976184f / (float)D_));
    float ang = (float)s * freq;
    float pe = (d & 1) ? cosf(ang) : sinf(ang);
    g_x[t] = emb[(size_t)tok * D_ + d] * 32.0f + pe;
}

__global__ void roundcpy_k(const float* __restrict__ in, float* __restrict__ out, size_t n) {
    size_t i = (size_t)blockIdx.x * blockDim.x + threadIdx.x;
    if (i < n) out[i] = tf32r(in[i]);
}

__global__ void ln_k(const float* __restrict__ in, float* __restrict__ out,
                     const float* __restrict__ sc, const float* __restrict__ bi) {
    int row = blockIdx.x;
    const float* x = in + (size_t)row * D_;
    int tid = threadIdx.x;
    float s = 0.f, ss = 0.f;
    for (int i = tid; i < D_; i += 256) { float v = x[i]; s += v; ss = fmaf(v, v, ss); }
    __shared__ float rs[8], rq[8];
    #pragma unroll
    for (int o = 16; o > 0; o >>= 1) {
        s  += __shfl_xor_sync(0xffffffffu, s,  o);
        ss += __shfl_xor_sync(0xffffffffu, ss, o);
    }
    if ((tid & 31) == 0) { rs[tid >> 5] = s; rq[tid >> 5] = ss; }
    __syncthreads();
    if (tid < 32) {
        float a = (tid < 8) ? rs[tid] : 0.f;
        float b = (tid < 8) ? rq[tid] : 0.f;
        #pragma unroll
        for (int o = 4; o > 0; o >>= 1) {
            a += __shfl_xor_sync(0xffffffffu, a, o);
            b += __shfl_xor_sync(0xffffffffu, b, o);
        }
        if (tid == 0) { rs[0] = a; rq[0] = b; }
    }
    __syncthreads();
    float mean = rs[0] * (1.0f / D_);
    float var  = rq[0] * (1.0f / D_) - mean * mean;
    float inv  = rsqrtf(var + 1e-5f);
    for (int i = tid; i < D_; i += 256)
        out[(size_t)row * D_ + i] = tf32r((x[i] - mean) * inv * sc[i] + bi[i]);
}

__global__ void softmax_k(float* __restrict__ att) {
    size_t row = blockIdx.x;
    int i = (int)(row & (S_ - 1));
    float* p = att + row * (size_t)S_;
    int n = i + 1;
    int tid = threadIdx.x;
    __shared__ float red[8];
    float m = -3.4e38f;
    for (int j = tid; j < n; j += 256) m = fmaxf(m, p[j]);
    #pragma unroll
    for (int o = 16; o > 0; o >>= 1) m = fmaxf(m, __shfl_xor_sync(0xffffffffu, m, o));
    if ((tid & 31) == 0) red[tid >> 5] = m;
    __syncthreads();
    if (tid < 32) {
        float t = (tid < 8) ? red[tid] : -3.4e38f;
        #pragma unroll
        for (int o = 4; o > 0; o >>= 1) t = fmaxf(t, __shfl_xor_sync(0xffffffffu, t, o));
        if (tid == 0) red[0] = t;
    }
    __syncthreads();
    m = red[0];
    float sum = 0.f;
    for (int j = tid; j < n; j += 256) { float e = __expf(p[j] - m); p[j] = e; sum += e; }
    __syncthreads();
    #pragma unroll
    for (int o = 16; o > 0; o >>= 1) sum += __shfl_xor_sync(0xffffffffu, sum, o);
    if ((tid & 31) == 0) red[tid >> 5] = sum;
    __syncthreads();
    if (tid < 32) {
        float t = (tid < 8) ? red[tid] : 0.f;
        #pragma unroll
        for (int o = 4; o > 0; o >>= 1) t += __shfl_xor_sync(0xffffffffu, t, o);
        if (tid == 0) red[0] = t;
    }
    __syncthreads();
    float inv = 1.0f / red[0];
    for (int j = tid; j < n; j += 256) p[j] = tf32r(p[j] * inv);
    for (int j = n + tid; j < S_; j += 256) p[j] = 0.f;
}

__global__ void transpose_k(const float* __restrict__ in, float* __restrict__ out,
                            int R, int C, int ldi, int ldo,
                            int nz2, long sI1, long sI2, long sO1, long sO2)
{
    int z = blockIdx.z, z1 = z / nz2, z2 = z - z1 * nz2;
    in  += z1 * sI1 + z2 * sI2;
    out += z1 * sO1 + z2 * sO2;
    __shared__ float t[32][33];
    int c0 = blockIdx.x * 32, r0 = blockIdx.y * 32;
    int x = threadIdx.x, y = threadIdx.y;
    #pragma unroll
    for (int i = 0; i < 32; i += 8) {
        int r = r0 + y + i;
        if (r < R && c0 + x < C) t[y + i][x] = in[(size_t)r * ldi + c0 + x];
    }
    __syncthreads();
    #pragma unroll
    for (int i = 0; i < 32; i += 8) {
        int c = c0 + y + i;
        if (c < C && r0 + x < R) out[(size_t)c * ldo + r0 + x] = tf32r(t[x][y + i]);
    }
}

// ============ launch helpers ============
template<bool RELU, bool RESID, bool BIAS, bool CAUSAL, bool ROUND, bool SWAPXY, bool CAUSALK>
static void tc_gemm(const float* A, const float* B, const float* bias, const float* Cin, float* C,
                    int M, int N, int K, int lda, int ldb, int ldc, float alpha = 1.f,
                    int Z = 1, int nz2 = 1,
                    long sA1 = 0, long sA2 = 0, long sB1 = 0, long sB2 = 0,
                    long sC1 = 0, long sC2 = 0)
{
    cudaFuncSetAttribute(gemm_mma<RELU, RESID, BIAS, CAUSAL, ROUND, SWAPXY, CAUSALK>,
                         cudaFuncAttributeMaxDynamicSharedMemorySize, SMEM1);
    dim3 grid;
    if (SWAPXY) grid = dim3(cdiv(M, BM1), cdiv(N, BN1), Z);
    else        grid = dim3(cdiv(N, BN1), cdiv(M, BM1), Z);
    gemm_mma<RELU, RESID, BIAS, CAUSAL, ROUND, SWAPXY, CAUSALK><<<grid, 128, SMEM1>>>(
        A, B, bias, Cin, C, M, N, K, lda, ldb, ldc,
        nz2, sA1, sA2, sB1, sB2, sC1, sC2, alpha);
}

static void tr(const float* in, float* out, int R, int C, int ldi, int ldo,
               int Z, int nz2, long sI1, long sI2, long sO1, long sO2)
{
    dim3 grid(cdiv(C, 32), cdiv(R, 32), Z);
    transpose_k<<<grid, dim3(32, 8)>>>(in, out, R, C, ldi, ldo, nz2, sI1, sI2, sO1, sO2);
}

// ============ orchestration ============
extern "C" void kernel_launch(void* const* d_in, const int* in_sizes, int n_in,
                              void* d_out, int out_size) {
    const int*   idx   = (const int*)  d_in[0];
    const float* emb   = (const float*)d_in[1];
    const float* cls_b = (const float*)d_in[2];
    const float* ln1_s = (const float*)d_in[3];
    const float* ln1_b = (const float*)d_in[4];
    const float* wq    = (const float*)d_in[5];
    const float* bq    = (const float*)d_in[6];
    const float* wk    = (const float*)d_in[7];
    const float* bk    = (const float*)d_in[8];
    const float* wv    = (const float*)d_in[9];
    const float* bv    = (const float*)d_in[10];
    const float* wo    = (const float*)d_in[11];
    const float* bo    = (const float*)d_in[12];
    const float* ln2_s = (const float*)d_in[13];
    const float* ln2_b = (const float*)d_in[14];
    const float* w1    = (const float*)d_in[15];
    const float* b1    = (const float*)d_in[16];
    const float* w2    = (const float*)d_in[17];
    const float* b2    = (const float*)d_in[18];
    const float* lnf_s = (const float*)d_in[19];
    const float* lnf_b = (const float*)d_in[20];
    float* out = (float*)d_out;

    float *gx, *gh, *gqkv, *go, *gff, *gatt, *gvT, *gwqkv, *gwoT, *gw1T, *gw2T, *gbq, *gembr;
    cudaGetSymbolAddress((void**)&gx,   g_x);
    cudaGetSymbolAddress((void**)&gh,   g_h);
    cudaGetSymbolAddress((void**)&gqkv, g_qkv);
    cudaGetSymbolAddress((void**)&go,   g_o);
    cudaGetSymbolAddress((void**)&gff,  g_ff);
    cudaGetSymbolAddress((void**)&gatt, g_att);
    cudaGetSymbolAddress((void**)&gvT,  g_vT);
    cudaGetSymbolAddress((void**)&gwqkv,g_wqkv);
    cudaGetSymbolAddress((void**)&gwoT, g_woT);
    cudaGetSymbolAddress((void**)&gw1T, g_w1T);
    cudaGetSymbolAddress((void**)&gw2T, g_w2T);
    cudaGetSymbolAddress((void**)&gbq,  g_bqkv);
    cudaGetSymbolAddress((void**)&gembr,g_embr);

    embed_k<<<cdiv(BSZ_*D_, 256), 256>>>(idx, emb, bq, bk, bv);
    tr(wq, gwqkv,                   D_, DH_, DH_, D_, NL_*H_, H_,
       (long)H_*D_*DH_, (long)D_*DH_, (long)3*D_*D_, (long)DH_*D_);
    tr(wk, gwqkv + (size_t)D_*D_,   D_, DH_, DH_, D_, NL_*H_, H_,
       (long)H_*D_*DH_, (long)D_*DH_, (long)3*D_*D_, (long)DH_*D_);
    tr(wv, gwqkv + (size_t)2*D_*D_, D_, DH_, DH_, D_, NL_*H_, H_,
       (long)H_*D_*DH_, (long)D_*DH_, (long)3*D_*D_, (long)DH_*D_);
    tr(wo, gwoT, D_, D_, D_, D_, NL_, 1, (long)D_*D_, 0, (long)D_*D_, 0);
    tr(w1, gw1T, D_, DFF_, DFF_, D_, NL_, 1, (long)D_*DFF_, 0, (long)DFF_*D_, 0);
    tr(w2, gw2T, DFF_, D_, D_, DFF_, NL_, 1, (long)DFF_*D_, 0, (long)D_*DFF_, 0);
    roundcpy_k<<<cdiv(V_*D_, 256), 256>>>(emb, gembr, (size_t)V_*D_);

    const long sQ  = (long)S_ * 3 * D_;
    const long sAT = (long)H_ * S_ * S_;

    for (int l = 0; l < NL_; l++) {
        ln_k<<<BSZ_, 256>>>(gx, gh, ln1_s + l*D_, ln1_b + l*D_);

        // qkv: [2048,1024] @ [3072,1024]^T   (SWAPXY: M-tiles=16 < N-tiles=24)
        tc_gemm<false,false,true,false,true,true,false>(gh, gwqkv + (size_t)l*3*D_*D_, gbq + l*3*D_,
                                                        nullptr, gqkv,
                                                        BSZ_, 3*D_, D_, D_, D_, 3*D_);

        // scores = 1/8 * q @ k^T per (b,h), causal tile skip (square grid, no swap)
        tc_gemm<false,false,false,true,false,false,false>(gqkv, gqkv + D_, nullptr, nullptr, gatt,
                                                          S_, S_, DH_, 3*D_, 3*D_, S_, 0.125f,
                                                          NB_*H_, H_,
                                                          sQ, DH_, sQ, DH_,
                                                          sAT, (long)S_*S_);

        softmax_k<<<NB_*H_*S_, 256>>>(gatt);

        // V^T per (b,h)
        tr(gqkv + 2*D_, gvT, S_, DH_, 3*D_, S_, NB_*H_, H_,
           sQ, DH_, (long)H_*DH_*S_, (long)DH_*S_);

        // o = P @ (V^T)^T with causal K-trim
        tc_gemm<false,false,false,false,true,false,true>(gatt, gvT, nullptr, nullptr, go,
                                                         S_, DH_, S_, S_, S_, D_, 1.f,
                                                         NB_*H_, H_,
                                                         sAT, (long)S_*S_,
                                                         (long)H_*DH_*S_, (long)DH_*S_,
                                                         (long)S_*D_, DH_);

        // x += o @ wo^T + bo  (square-ish: 16x8 tiles, swap puts M first anyway)
        tc_gemm<false,true,true,false,false,true,false>(go, gwoT + (size_t)l*D_*D_, bo + l*D_, gx, gx,
                                                        BSZ_, D_, D_, D_, D_, D_);

        ln_k<<<BSZ_, 256>>>(gx, gh, ln2_s + l*D_, ln2_b + l*D_);

        // ff = relu(h @ w1 + b1)   (SWAPXY: 16 M-tiles vs 32 N-tiles)
        tc_gemm<true,false,true,false,true,true,false>(gh, gw1T + (size_t)l*DFF_*D_, b1 + l*DFF_,
                                                       nullptr, gff,
                                                       BSZ_, DFF_, D_, D_, D_, DFF_);
        // x += ff @ w2 + b2
        tc_gemm<false,true,true,false,false,true,false>(gff, gw2T + (size_t)l*D_*DFF_, b2 + l*D_, gx, gx,
                                                        BSZ_, D_, DFF_, DFF_, DFF_, D_);
    }

    ln_k<<<BSZ_, 256>>>(gx, gh, lnf_s, lnf_b);

    // logits = h @ emb^T + cls_b   (SWAPXY: 16 M-tiles vs 250 N-tiles — big L2 win)
    tc_gemm<false,false,true,false,false,true,false>(gh, gembr, cls_b, nullptr, out,
                                                     BSZ_, V_, D_, D_, D_, V_);
}

// round 9
// speedup vs baseline: 1.2041x; 1.0118x over previous
#include <cuda_runtime.h>
#include <math.h>
#include <cstdint>

// ---------------- problem constants ----------------
#define D_   1024
#define H_   16
#define DH_  64
#define NL_  4
#define DFF_ 4096
#define V_   32000
#define S_   1024
#define NB_  2
#define BSZ_ (NB_*S_)

static inline int cdiv(int a, int b) { return (a + b - 1) / b; }

// ---------------- scratch ----------------
__device__ float g_x   [BSZ_*D_];
__device__ float g_h   [BSZ_*D_];
__device__ float g_qkv [BSZ_*3*D_];
__device__ float g_o   [BSZ_*D_];
__device__ float g_ff  [BSZ_*DFF_];
__device__ float g_vT  [(size_t)NB_*H_*DH_*S_];
__device__ float g_wqkv[(size_t)NL_*3*D_*D_];
__device__ float g_woT [(size_t)NL_*D_*D_];
__device__ float g_w1T [(size_t)NL_*DFF_*D_];
__device__ float g_w2T [(size_t)NL_*D_*DFF_];
__device__ float g_bqkv[NL_*3*D_];
__device__ float g_embr[(size_t)V_*D_];

// ---------------- helpers ----------------
__device__ __forceinline__ float tf32r(float x) {
    uint32_t u;
    asm("cvt.rna.tf32.f32 %0, %1;" : "=r"(u) : "f"(x));
    return __uint_as_float(u);
}
__device__ __forceinline__ void mma1688(float* d, const uint32_t* a, const uint32_t* b) {
    asm volatile(
        "mma.sync.aligned.m16n8k8.row.col.f32.tf32.tf32.f32 "
        "{%0,%1,%2,%3}, {%4,%5,%6,%7}, {%8,%9}, {%0,%1,%2,%3};"
        : "+f"(d[0]), "+f"(d[1]), "+f"(d[2]), "+f"(d[3])
        : "r"(a[0]), "r"(a[1]), "r"(a[2]), "r"(a[3]), "r"(b[0]), "r"(b[1]));
}
__device__ __forceinline__ uint32_t smem_u32(const void* p) {
    uint32_t a;
    asm("{ .reg .u64 t; cvta.to.shared.u64 t, %1; cvt.u32.u64 %0, t; }" : "=r"(a) : "l"(p));
    return a;
}
__device__ __forceinline__ void cpa16(uint32_t dst, const float* src, bool pred) {
    int sz = pred ? 16 : 0;
    asm volatile("cp.async.cg.shared.global [%0], [%1], 16, %2;"
                 :: "r"(dst), "l"(src), "r"(sz) : "memory");
}
#define CPA_COMMIT() asm volatile("cp.async.commit_group;" ::: "memory")
#define CPA_WAIT1()  asm volatile("cp.async.wait_group 1;" ::: "memory")
#define CPA_WAIT0()  asm volatile("cp.async.wait_group 0;" ::: "memory")

constexpr int BK = 32, LDS_ = 36, NSTAGE = 3;
constexpr int BM1 = 128, BN1 = 128;
constexpr int STG1 = 2 * BM1 * LDS_;
constexpr int SMEM1 = NSTAGE * STG1 * 4;     // 110,592 B -> 2 CTAs/SM

// ============ tf32 mma.sync GEMM (R5-proven) ============
template<bool RELU, bool RESID, bool BIAS, bool ROUND>
__global__ void __launch_bounds__(128) gemm_mma(
    const float* __restrict__ Ag, const float* __restrict__ Bg,
    const float* __restrict__ biasg, const float* __restrict__ Cing,
    float* __restrict__ Cg,
    int M, int N, int K, int lda, int ldb, int ldc, float alpha)
{
    int row0 = blockIdx.y * BM1;
    int col0 = blockIdx.x * BN1;

    const float* A   = Ag;
    const float* B   = Bg;
    float*       C   = Cg;
    const float* Cin = Cing;

    extern __shared__ float sm[];
    uint32_t sm0 = smem_u32(sm);

    int tid = threadIdx.x;
    int wid = tid >> 5, lane = tid & 31;
    int wm = wid >> 1, wn = wid & 1;
    int gid = lane >> 2, tig = lane & 3;

    int cr = tid >> 3;
    int cc = (tid & 7) * 4;

    float acc[4][8][4];
    #pragma unroll
    for (int a = 0; a < 4; a++)
        #pragma unroll
        for (int b = 0; b < 8; b++)
            #pragma unroll
            for (int c = 0; c < 4; c++) acc[a][b][c] = 0.f;

    int KT = K / BK;

    auto issue = [&](int kt, int slot) {
        int k0 = kt * BK;
        uint32_t abase = sm0 + (uint32_t)slot * STG1 * 4;
        uint32_t bbase = abase + BM1 * LDS_ * 4;
        #pragma unroll
        for (int i = 0; i < 8; i++) {
            int r = cr + i * 16;
            int gm = row0 + r;
            const float* pa = A + (size_t)(gm < M ? gm : 0) * lda + k0 + cc;
            cpa16(abase + (r * LDS_ + cc) * 4, pa, gm < M);
            int gn = col0 + r;
            const float* pb = B + (size_t)(gn < N ? gn : 0) * ldb + k0 + cc;
            cpa16(bbase + (r * LDS_ + cc) * 4, pb, gn < N);
        }
    };

    int nPre = KT < (NSTAGE - 1) ? KT : (NSTAGE - 1);
    for (int p = 0; p < nPre; p++) { issue(p, p); CPA_COMMIT(); }

    for (int kt = 0; kt < KT; kt++) {
        CPA_WAIT1();
        __syncthreads();
        int nxt = kt + NSTAGE - 1;
        if (nxt < KT) issue(nxt, nxt % NSTAGE);
        CPA_COMMIT();

        const float* As = sm + (kt % NSTAGE) * STG1;
        const float* Bs = As + BM1 * LDS_;
        const float* Ab = As + (wm * 64 + gid) * LDS_;
        const float* Bb = Bs + (wn * 64 + gid) * LDS_;

        #pragma unroll
        for (int ks = 0; ks < 4; ks++) {
            int kc = ks * 8 + tig;
            uint32_t af[4][4], bf[8][2];
            #pragma unroll
            for (int mt = 0; mt < 4; mt++) {
                const float* p = Ab + mt * 16 * LDS_;
                af[mt][0] = __float_as_uint(p[kc]);
                af[mt][1] = __float_as_uint(p[8 * LDS_ + kc]);
                af[mt][2] = __float_as_uint(p[kc + 4]);
                af[mt][3] = __float_as_uint(p[8 * LDS_ + kc + 4]);
            }
            #pragma unroll
            for (int nt = 0; nt < 8; nt++) {
                const float* p = Bb + nt * 8 * LDS_;
                bf[nt][0] = __float_as_uint(p[kc]);
                bf[nt][1] = __float_as_uint(p[kc + 4]);
            }
            #pragma unroll
            for (int mt = 0; mt < 4; mt++)
                #pragma unroll
                for (int nt = 0; nt < 8; nt++)
                    mma1688(acc[mt][nt], af[mt], bf[nt]);
        }
    }

    #pragma unroll
    for (int mt = 0; mt < 4; mt++) {
        #pragma unroll
        for (int half = 0; half < 2; half++) {
            int gm = row0 + wm * 64 + mt * 16 + gid + half * 8;
            if (gm >= M) continue;
            #pragma unroll
            for (int nt = 0; nt < 8; nt++) {
                int gn = col0 + wn * 64 + nt * 8 + 2 * tig;
                if (gn >= N) continue;
                float v0 = acc[mt][nt][half * 2 + 0] * alpha;
                float v1 = acc[mt][nt][half * 2 + 1] * alpha;
                if (BIAS)  { v0 += biasg[gn]; v1 += biasg[gn + 1]; }
                if (RESID) {
                    const float* ci = Cin + (size_t)gm * ldc + gn;
                    v0 += ci[0]; v1 += ci[1];
                }
                if (RELU) { v0 = fmaxf(v0, 0.f); v1 = fmaxf(v1, 0.f); }
                if (ROUND) { v0 = tf32r(v0); v1 = tf32r(v1); }
                *(float2*)(C + (size_t)gm * ldc + gn) = make_float2(v0, v1);
            }
        }
    }
}

// ============ fused flash attention ============
// grid.x = (b*H+h)*8 + qblock ; 128 threads; Q block 128 rows, KV chunks of 128.
constexpr int FQ_LD = 68, FV_LD = 132, FP_LD = 132;
constexpr int OFF_Q = 0;
constexpr int OFF_K = 128 * FQ_LD;                 // 8704
constexpr int OFF_V = OFF_K + 128 * FQ_LD;         // 17408
constexpr int OFF_P = OFF_V + 64 * FV_LD;          // 25856
constexpr int ATT_SMEM = (OFF_P + 128 * FP_LD) * 4;  // 171,008 B

__global__ void __launch_bounds__(128) attn_k(const float* __restrict__ qkv,
                                              float* __restrict__ og) {
    extern __shared__ float sm[];
    float* smQ = sm + OFF_Q;
    float* smK = sm + OFF_K;
    float* smV = sm + OFF_V;
    float* smP = sm + OFF_P;
    uint32_t sb = smem_u32(sm);

    int z  = blockIdx.x;
    int qb = z & 7, bh = z >> 3;
    int b  = bh >> 4, h = bh & 15;
    int row0 = qb * 128;
    const float* qp = qkv + (size_t)b * S_ * 3 * D_ + (size_t)h * DH_;
    const float* kp = qp + D_;
    const float* vt = g_vT + (size_t)bh * DH_ * S_;

    int tid = threadIdx.x, wid = tid >> 5, lane = tid & 31;
    int gid = lane >> 2, tig = lane & 3;
    int wr  = wid * 32;

    float oacc[2][8][4];
    #pragma unroll
    for (int mt = 0; mt < 2; mt++)
        #pragma unroll
        for (int nt = 0; nt < 8; nt++)
            #pragma unroll
            for (int d = 0; d < 4; d++) oacc[mt][nt][d] = 0.f;
    float mrow[2][2] = {{-1e30f, -1e30f}, {-1e30f, -1e30f}};
    float lrow[2][2] = {{0.f, 0.f}, {0.f, 0.f}};

    // Q load (once) + K chunk 0
    #pragma unroll
    for (int i = 0; i < 16; i++) {
        int t = tid + i * 128; int r = t >> 4, c = (t & 15) * 4;
        cpa16(sb + (OFF_Q + r * FQ_LD + c) * 4, qp + (size_t)(row0 + r) * 3 * D_ + c, true);
    }
    CPA_COMMIT();
    #pragma unroll
    for (int i = 0; i < 16; i++) {
        int t = tid + i * 128; int r = t >> 4, c = (t & 15) * 4;
        cpa16(sb + (OFF_K + r * FQ_LD + c) * 4, kp + (size_t)r * 3 * D_ + c, true);
    }
    CPA_COMMIT();

    int nch = qb + 1;
    for (int c = 0; c < nch; c++) {
        CPA_WAIT0();
        __syncthreads();          // K_c visible; V region free (all warps past previous P@V)
        // prefetch V_c
        #pragma unroll
        for (int i = 0; i < 16; i++) {
            int t = tid + i * 128; int r = t >> 5, cc = (t & 31) * 4;
            cpa16(sb + (OFF_V + r * FV_LD + cc) * 4, vt + (size_t)r * S_ + c * 128 + cc, true);
        }
        CPA_COMMIT();

        // ---- S = Q @ K^T ----
        float sacc[2][16][4];
        #pragma unroll
        for (int mt = 0; mt < 2; mt++)
            #pragma unroll
            for (int nt = 0; nt < 16; nt++)
                #pragma unroll
                for (int d = 0; d < 4; d++) sacc[mt][nt][d] = 0.f;
        #pragma unroll
        for (int ks = 0; ks < 8; ks++) {
            int kc = ks * 8 + tig;
            uint32_t af[2][4];
            #pragma unroll
            for (int mt = 0; mt < 2; mt++) {
                const float* p = smQ + (wr + 16 * mt + gid) * FQ_LD;
                af[mt][0] = __float_as_uint(p[kc]);
                af[mt][1] = __float_as_uint(p[8 * FQ_LD + kc]);
                af[mt][2] = __float_as_uint(p[kc + 4]);
                af[mt][3] = __float_as_uint(p[8 * FQ_LD + kc + 4]);
            }
            #pragma unroll
            for (int nt = 0; nt < 16; nt++) {
                const float* pb = smK + (nt * 8 + gid) * FQ_LD;
                uint32_t bf[2] = {__float_as_uint(pb[kc]), __float_as_uint(pb[kc + 4])};
                mma1688(sacc[0][nt], af[0], bf);
                mma1688(sacc[1][nt], af[1], bf);
            }
        }

        // ---- scale + causal mask + online softmax ----
        bool diag = (c == qb);
        #pragma unroll
        for (int mt = 0; mt < 2; mt++) {
            #pragma unroll
            for (int half = 0; half < 2; half++) {
                int d0 = 2 * half;
                int ig = row0 + wr + 16 * mt + 8 * half + gid;
                float mx = -1e30f;
                #pragma unroll
                for (int nt = 0; nt < 16; nt++) {
                    float a = sacc[mt][nt][d0]     * 0.125f;
                    float e = sacc[mt][nt][d0 + 1] * 0.125f;
                    if (diag) {
                        int j = c * 128 + nt * 8 + 2 * tig;
                        if (j     > ig) a = -1e30f;
                        if (j + 1 > ig) e = -1e30f;
                    }
                    sacc[mt][nt][d0]     = a;
                    sacc[mt][nt][d0 + 1] = e;
                    mx = fmaxf(mx, fmaxf(a, e));
                }
                mx = fmaxf(mx, __shfl_xor_sync(0xffffffffu, mx, 1));
                mx = fmaxf(mx, __shfl_xor_sync(0xffffffffu, mx, 2));
                float mnew = fmaxf(mrow[mt][half], mx);
                float scl  = __expf(mrow[mt][half] - mnew);
                mrow[mt][half] = mnew;
                float ps = 0.f;
                int prow = wr + 16 * mt + 8 * half + gid;
                #pragma unroll
                for (int nt = 0; nt < 16; nt++) {
                    float p0 = __expf(sacc[mt][nt][d0]     - mnew);
                    float p1 = __expf(sacc[mt][nt][d0 + 1] - mnew);
                    ps += p0 + p1;
                    *(float2*)&smP[prow * FP_LD + nt * 8 + 2 * tig] =
                        make_float2(tf32r(p0), tf32r(p1));
                }
                ps += __shfl_xor_sync(0xffffffffu, ps, 1);
                ps += __shfl_xor_sync(0xffffffffu, ps, 2);
                lrow[mt][half] = lrow[mt][half] * scl + ps;
                #pragma unroll
                for (int nt = 0; nt < 8; nt++) {
                    oacc[mt][nt][d0]     *= scl;
                    oacc[mt][nt][d0 + 1] *= scl;
                }
            }
        }
        __syncwarp();

        CPA_WAIT0();               // V_c arrived
        __syncthreads();           // all warps done reading K -> safe to overwrite
        if (c + 1 < nch) {
            #pragma unroll
            for (int i = 0; i < 16; i++) {
                int t = tid + i * 128; int r = t >> 4, cc = (t & 15) * 4;
                cpa16(sb + (OFF_K + r * FQ_LD + cc) * 4,
                      kp + (size_t)((c + 1) * 128 + r) * 3 * D_ + cc, true);
            }
            CPA_COMMIT();
        }

        // ---- O += P @ V ----
        #pragma unroll
        for (int ks = 0; ks < 16; ks++) {
            int kc = ks * 8 + tig;
            uint32_t af[2][4];
            #pragma unroll
            for (int mt = 0; mt < 2; mt++) {
                const float* p = smP + (wr + 16 * mt + gid) * FP_LD;
                af[mt][0] = __float_as_uint(p[kc]);
                af[mt][1] = __float_as_uint(p[8 * FP_LD + kc]);
                af[mt][2] = __float_as_uint(p[kc + 4]);
                af[mt][3] = __float_as_uint(p[8 * FP_LD + kc + 4]);
            }
            #pragma unroll
            for (int nt = 0; nt < 8; nt++) {
                const float* pb = smV + (nt * 8 + gid) * FV_LD;
                uint32_t bf[2] = {__float_as_uint(pb[kc]), __float_as_uint(pb[kc + 4])};
                mma1688(oacc[0][nt], af[0], bf);
                mma1688(oacc[1][nt], af[1], bf);
            }
        }
        // next-iteration top barrier protects V from early overwrite
    }

    // ---- epilogue: O /= l, write ----
    #pragma unroll
    for (int mt = 0; mt < 2; mt++) {
        #pragma unroll
        for (int half = 0; half < 2; half++) {
            float inv = 1.f / lrow[mt][half];
            int rg = row0 + wr + 16 * mt + 8 * half + gid;
            float* orow = og + ((size_t)b * S_ + rg) * D_ + h * DH_;
            #pragma unroll
            for (int nt = 0; nt < 8; nt++) {
                float p0 = tf32r(oacc[mt][nt][2 * half]     * inv);
                float p1 = tf32r(oacc[mt][nt][2 * half + 1] * inv);
                *(float2*)&orow[nt * 8 + 2 * tig] = make_float2(p0, p1);
            }
        }
    }
}

// ============ auxiliary kernels ============
__global__ void embed_k(const int* __restrict__ idx, const float* __restrict__ emb,
                        const float* __restrict__ bq, const float* __restrict__ bk,
                        const float* __restrict__ bv) {
    int t = blockIdx.x * blockDim.x + threadIdx.x;
    if (t < NL_ * 3 * D_) {
        int l = t / (3 * D_), r = t - l * 3 * D_;
        float v = (r < D_) ? bq[l * D_ + r] : (r < 2 * D_) ? bk[l * D_ + r - D_] : bv[l * D_ + r - 2 * D_];
        g_bqkv[t] = v;
    }
    if (t >= BSZ_ * D_) return;
    int d = t & (D_ - 1);
    int bs = t >> 10;
    int s = bs & (S_ - 1);
    int tok = idx[bs];
    int i2 = d & ~1;
    float freq = __expf((float)i2 * (-9.210340371976184f / (float)D_));
    float ang = (float)s * freq;
    float pe = (d & 1) ? cosf(ang) : sinf(ang);
    g_x[t] = emb[(size_t)tok * D_ + d] * 32.0f + pe;
}

__global__ void roundcpy_k(const float* __restrict__ in, float* __restrict__ out, size_t n) {
    size_t i = (size_t)blockIdx.x * blockDim.x + threadIdx.x;
    if (i < n) out[i] = tf32r(in[i]);
}

__global__ void ln_k(const float* __restrict__ in, float* __restrict__ out,
                     const float* __restrict__ sc, const float* __restrict__ bi) {
    int row = blockIdx.x;
    const float* x = in + (size_t)row * D_;
    int tid = threadIdx.x;
    float s = 0.f, ss = 0.f;
    for (int i = tid; i < D_; i += 256) { float v = x[i]; s += v; ss = fmaf(v, v, ss); }
    __shared__ float rs[8], rq[8];
    #pragma unroll
    for (int o = 16; o > 0; o >>= 1) {
        s  += __shfl_xor_sync(0xffffffffu, s,  o);
        ss += __shfl_xor_sync(0xffffffffu, ss, o);
    }
    if ((tid & 31) == 0) { rs[tid >> 5] = s; rq[tid >> 5] = ss; }
    __syncthreads();
    if (tid < 32) {
        float a = (tid < 8) ? rs[tid] : 0.f;
        float b = (tid < 8) ? rq[tid] : 0.f;
        #pragma unroll
        for (int o = 4; o > 0; o >>= 1) {
            a += __shfl_xor_sync(0xffffffffu, a, o);
            b += __shfl_xor_sync(0xffffffffu, b, o);
        }
        if (tid == 0) { rs[0] = a; rq[0] = b; }
    }
    __syncthreads();
    float mean = rs[0] * (1.0f / D_);
    float var  = rq[0] * (1.0f / D_) - mean * mean;
    float inv  = rsqrtf(var + 1e-5f);
    for (int i = tid; i < D_; i += 256)
        out[(size_t)row * D_ + i] = tf32r((x[i] - mean) * inv * sc[i] + bi[i]);
}

__global__ void transpose_k(const float* __restrict__ in, float* __restrict__ out,
                            int R, int C, int ldi, int ldo,
                            int nz2, long sI1, long sI2, long sO1, long sO2)
{
    int z = blockIdx.z, z1 = z / nz2, z2 = z - z1 * nz2;
    in  += z1 * sI1 + z2 * sI2;
    out += z1 * sO1 + z2 * sO2;
    __shared__ float t[32][33];
    int c0 = blockIdx.x * 32, r0 = blockIdx.y * 32;
    int x = threadIdx.x, y = threadIdx.y;
    #pragma unroll
    for (int i = 0; i < 32; i += 8) {
        int r = r0 + y + i;
        if (r < R && c0 + x < C) t[y + i][x] = in[(size_t)r * ldi + c0 + x];
    }
    __syncthreads();
    #pragma unroll
    for (int i = 0; i < 32; i += 8) {
        int c = c0 + y + i;
        if (c < C && r0 + x < R) out[(size_t)c * ldo + r0 + x] = tf32r(t[x][y + i]);
    }
}

// ============ launch helpers ============
template<bool RELU, bool RESID, bool BIAS, bool ROUND>
static void tc_gemm(const float* A, const float* B, const float* bias, const float* Cin, float* C,
                    int M, int N, int K, int lda, int ldb, int ldc, float alpha = 1.f)
{
    cudaFuncSetAttribute(gemm_mma<RELU, RESID, BIAS, ROUND>,
                         cudaFuncAttributeMaxDynamicSharedMemorySize, SMEM1);
    dim3 grid(cdiv(N, BN1), cdiv(M, BM1), 1);
    gemm_mma<RELU, RESID, BIAS, ROUND><<<grid, 128, SMEM1>>>(
        A, B, bias, Cin, C, M, N, K, lda, ldb, ldc, alpha);
}

static void tr(const float* in, float* out, int R, int C, int ldi, int ldo,
               int Z, int nz2, long sI1, long sI2, long sO1, long sO2)
{
    dim3 grid(cdiv(C, 32), cdiv(R, 32), Z);
    transpose_k<<<grid, dim3(32, 8)>>>(in, out, R, C, ldi, ldo, nz2, sI1, sI2, sO1, sO2);
}

// ============ orchestration ============
extern "C" void kernel_launch(void* const* d_in, const int* in_sizes, int n_in,
                              void* d_out, int out_size) {
    const int*   idx   = (const int*)  d_in[0];
    const float* emb   = (const float*)d_in[1];
    const float* cls_b = (const float*)d_in[2];
    const float* ln1_s = (const float*)d_in[3];
    const float* ln1_b = (const float*)d_in[4];
    const float* wq    = (const float*)d_in[5];
    const float* bq    = (const float*)d_in[6];
    const float* wk    = (const float*)d_in[7];
    const float* bk    = (const float*)d_in[8];
    const float* wv    = (const float*)d_in[9];
    const float* bv    = (const float*)d_in[10];
    const float* wo    = (const float*)d_in[11];
    const float* bo    = (const float*)d_in[12];
    const float* ln2_s = (const float*)d_in[13];
    const float* ln2_b = (const float*)d_in[14];
    const float* w1    = (const float*)d_in[15];
    const float* b1    = (const float*)d_in[16];
    const float* w2    = (const float*)d_in[17];
    const float* b2    = (const float*)d_in[18];
    const float* lnf_s = (const float*)d_in[19];
    const float* lnf_b = (const float*)d_in[20];
    float* out = (float*)d_out;

    float *gx, *gh, *gqkv, *go, *gff, *gvT, *gwqkv, *gwoT, *gw1T, *gw2T, *gbq, *gembr;
    cudaGetSymbolAddress((void**)&gx,   g_x);
    cudaGetSymbolAddress((void**)&gh,   g_h);
    cudaGetSymbolAddress((void**)&gqkv, g_qkv);
    cudaGetSymbolAddress((void**)&go,   g_o);
    cudaGetSymbolAddress((void**)&gff,  g_ff);
    cudaGetSymbolAddress((void**)&gvT,  g_vT);
    cudaGetSymbolAddress((void**)&gwqkv,g_wqkv);
    cudaGetSymbolAddress((void**)&gwoT, g_woT);
    cudaGetSymbolAddress((void**)&gw1T, g_w1T);
    cudaGetSymbolAddress((void**)&gw2T, g_w2T);
    cudaGetSymbolAddress((void**)&gbq,  g_bqkv);
    cudaGetSymbolAddress((void**)&gembr,g_embr);

    cudaFuncSetAttribute(attn_k, cudaFuncAttributeMaxDynamicSharedMemorySize, ATT_SMEM);

    embed_k<<<cdiv(BSZ_*D_, 256), 256>>>(idx, emb, bq, bk, bv);
    tr(wq, gwqkv,                   D_, DH_, DH_, D_, NL_*H_, H_,
       (long)H_*D_*DH_, (long)D_*DH_, (long)3*D_*D_, (long)DH_*D_);
    tr(wk, gwqkv + (size_t)D_*D_,   D_, DH_, DH_, D_, NL_*H_, H_,
       (long)H_*D_*DH_, (long)D_*DH_, (long)3*D_*D_, (long)DH_*D_);
    tr(wv, gwqkv + (size_t)2*D_*D_, D_, DH_, DH_, D_, NL_*H_, H_,
       (long)H_*D_*DH_, (long)D_*DH_, (long)3*D_*D_, (long)DH_*D_);
    tr(wo, gwoT, D_, D_, D_, D_, NL_, 1, (long)D_*D_, 0, (long)D_*D_, 0);
    tr(w1, gw1T, D_, DFF_, DFF_, D_, NL_, 1, (long)D_*DFF_, 0, (long)DFF_*D_, 0);
    tr(w2, gw2T, DFF_, D_, D_, DFF_, NL_, 1, (long)DFF_*D_, 0, (long)D_*DFF_, 0);
    roundcpy_k<<<cdiv(V_*D_, 256), 256>>>(emb, gembr, (size_t)V_*D_);

    const long sQ = (long)S_ * 3 * D_;

    for (int l = 0; l < NL_; l++) {
        ln_k<<<BSZ_, 256>>>(gx, gh, ln1_s + l*D_, ln1_b + l*D_);

        // qkv: [2048,1024] @ [3072,1024]^T  (outputs tf32-rounded)
        tc_gemm<false,false,true,true>(gh, gwqkv + (size_t)l*3*D_*D_, gbq + l*3*D_, nullptr, gqkv,
                                       BSZ_, 3*D_, D_, D_, D_, 3*D_);

        // V^T per (b,h) (rounded)
        tr(gqkv + 2*D_, gvT, S_, DH_, 3*D_, S_, NB_*H_, H_,
           sQ, DH_, (long)H_*DH_*S_, (long)DH_*S_);

        // fused attention: QK^T + causal softmax + PV
        attn_k<<<NB_*H_*8, 128, ATT_SMEM>>>(gqkv, go);

        // x += o @ wo^T + bo
        tc_gemm<false,true,true,false>(go, gwoT + (size_t)l*D_*D_, bo + l*D_, gx, gx,
                                       BSZ_, D_, D_, D_, D_, D_);

        ln_k<<<BSZ_, 256>>>(gx, gh, ln2_s + l*D_, ln2_b + l*D_);

        tc_gemm<true,false,true,true>(gh, gw1T + (size_t)l*DFF_*D_, b1 + l*DFF_, nullptr, gff,
                                      BSZ_, DFF_, D_, D_, D_, DFF_);
        tc_gemm<false,true,true,false>(gff, gw2T + (size_t)l*D_*DFF_, b2 + l*D_, gx, gx,
                                       BSZ_, D_, DFF_, DFF_, DFF_, D_);
    }

    ln_k<<<BSZ_, 256>>>(gx, gh, lnf_s, lnf_b);

    tc_gemm<false,false,true,false>(gh, gembr, cls_b, nullptr, out,
                                    BSZ_, V_, D_, D_, D_, V_);
}

// round 11
// speedup vs baseline: 2.0787x; 1.7263x over previous
#include <cuda_runtime.h>
#include <cuda_fp16.h>
#include <math.h>
#include <cstdint>

// ---------------- problem constants ----------------
#define D_   1024
#define H_   16
#define DH_  64
#define NL_  4
#define DFF_ 4096
#define V_   32000
#define S_   1024
#define NB_  2
#define BSZ_ (NB_*S_)

static inline int cdiv(int a, int b) { return (a + b - 1) / b; }

// ---------------- scratch ----------------
__device__ float  g_x   [BSZ_*D_];                 // residual (fp32)
__device__ __half g_h   [BSZ_*D_];                 // LN output
__device__ __half g_qkv [BSZ_*3*D_];
__device__ __half g_o   [BSZ_*D_];
__device__ __half g_ff  [BSZ_*DFF_];
__device__ __half g_vT  [(size_t)NB_*H_*DH_*S_];
__device__ __half g_wqkv[(size_t)NL_*3*D_*D_];
__device__ __half g_woT [(size_t)NL_*D_*D_];
__device__ __half g_w1T [(size_t)NL_*DFF_*D_];
__device__ __half g_w2T [(size_t)NL_*D_*DFF_];
__device__ float  g_bqkv[NL_*3*D_];
__device__ __half g_embr[(size_t)V_*D_];

// ---------------- helpers ----------------
__device__ __forceinline__ void mma16816(float* d, const uint32_t* a, const uint32_t* b) {
    asm volatile(
        "mma.sync.aligned.m16n8k16.row.col.f32.f16.f16.f32 "
        "{%0,%1,%2,%3}, {%4,%5,%6,%7}, {%8,%9}, {%0,%1,%2,%3};"
        : "+f"(d[0]), "+f"(d[1]), "+f"(d[2]), "+f"(d[3])
        : "r"(a[0]), "r"(a[1]), "r"(a[2]), "r"(a[3]), "r"(b[0]), "r"(b[1]));
}
__device__ __forceinline__ uint32_t smem_u32(const void* p) {
    uint32_t a;
    asm("{ .reg .u64 t; cvta.to.shared.u64 t, %1; cvt.u32.u64 %0, t; }" : "=r"(a) : "l"(p));
    return a;
}
__device__ __forceinline__ void cpa16(uint32_t dst, const void* src, bool pred) {
    int sz = pred ? 16 : 0;
    asm volatile("cp.async.cg.shared.global [%0], [%1], 16, %2;"
                 :: "r"(dst), "l"(src), "r"(sz) : "memory");
}
#define CPA_COMMIT() asm volatile("cp.async.commit_group;" ::: "memory")
#define CPA_WAIT1()  asm volatile("cp.async.wait_group 1;" ::: "memory")
#define CPA_WAIT0()  asm volatile("cp.async.wait_group 0;" ::: "memory")
__device__ __forceinline__ uint32_t ldh2(const __half* p) { return *(const uint32_t*)p; }

// ============ fp16 mma GEMM: 128x128 tile, BK=32, 3-stage cp.async ============
constexpr int BKH = 32, LDSH = 40, NSTAGE = 3;
constexpr int BM1 = 128, BN1 = 128;
constexpr int STGH  = 2 * BM1 * LDSH;            // halves per stage
constexpr int SMEMH = NSTAGE * STGH * 2;         // 61,440 B -> 3 CTAs/SM

// C = alpha*A@B^T (+bias fp32)(+Cin fp32)(relu); A [M,K] half rm, B [N,K] half K-major.
// HALF_OUT: C is __half*, else float*.
template<bool RELU, bool RESID, bool BIAS, bool HALF_OUT>
__global__ void __launch_bounds__(128) gemm_h(
    const __half* __restrict__ A, const __half* __restrict__ B,
    const float* __restrict__ biasg, const float* __restrict__ Cin,
    void* __restrict__ Cg,
    int M, int N, int K, int lda, int ldb, int ldc, float alpha)
{
    int row0 = blockIdx.y * BM1;
    int col0 = blockIdx.x * BN1;

    extern __shared__ __half smh[];
    uint32_t sm0 = smem_u32(smh);

    int tid = threadIdx.x;
    int wid = tid >> 5, lane = tid & 31;
    int wm = wid >> 1, wn = wid & 1;
    int gid = lane >> 2, tig = lane & 3;

    int cr = tid >> 2;                 // 0..31
    int cc = (tid & 3) * 8;            // half offset within 32

    float acc[4][8][4];
    #pragma unroll
    for (int a = 0; a < 4; a++)
        #pragma unroll
        for (int b = 0; b < 8; b++)
            #pragma unroll
            for (int c = 0; c < 4; c++) acc[a][b][c] = 0.f;

    int KT = K / BKH;

    auto issue = [&](int kt, int slot) {
        int k0 = kt * BKH;
        uint32_t abase = sm0 + (uint32_t)slot * STGH * 2;
        uint32_t bbase = abase + BM1 * LDSH * 2;
        #pragma unroll
        for (int i = 0; i < 4; i++) {
            int r = cr + i * 32;
            int gm = row0 + r;
            cpa16(abase + (r * LDSH + cc) * 2,
                  A + (size_t)(gm < M ? gm : 0) * lda + k0 + cc, gm < M);
            int gn = col0 + r;
            cpa16(bbase + (r * LDSH + cc) * 2,
                  B + (size_t)(gn < N ? gn : 0) * ldb + k0 + cc, gn < N);
        }
    };

    int nPre = KT < (NSTAGE - 1) ? KT : (NSTAGE - 1);
    for (int p = 0; p < nPre; p++) { issue(p, p); CPA_COMMIT(); }

    for (int kt = 0; kt < KT; kt++) {
        CPA_WAIT1();
        __syncthreads();
        int nxt = kt + NSTAGE - 1;
        if (nxt < KT) issue(nxt, nxt % NSTAGE);
        CPA_COMMIT();

        const __half* As = smh + (kt % NSTAGE) * STGH;
        const __half* Bs = As + BM1 * LDSH;
        const __half* Ab = As + (wm * 64 + gid) * LDSH;
        const __half* Bb = Bs + (wn * 64 + gid) * LDSH;

        #pragma unroll
        for (int ks = 0; ks < 2; ks++) {
            int kc = ks * 16 + 2 * tig;
            uint32_t af[4][4], bf[8][2];
            #pragma unroll
            for (int mt = 0; mt < 4; mt++) {
                const __half* p = Ab + mt * 16 * LDSH;
                af[mt][0] = ldh2(p + kc);
                af[mt][1] = ldh2(p + 8 * LDSH + kc);
                af[mt][2] = ldh2(p + kc + 8);
                af[mt][3] = ldh2(p + 8 * LDSH + kc + 8);
            }
            #pragma unroll
            for (int nt = 0; nt < 8; nt++) {
                const __half* p = Bb + nt * 8 * LDSH;
                bf[nt][0] = ldh2(p + kc);
                bf[nt][1] = ldh2(p + kc + 8);
            }
            #pragma unroll
            for (int mt = 0; mt < 4; mt++)
                #pragma unroll
                for (int nt = 0; nt < 8; nt++)
                    mma16816(acc[mt][nt], af[mt], bf[nt]);
        }
    }

    #pragma unroll
    for (int mt = 0; mt < 4; mt++) {
        #pragma unroll
        for (int half = 0; half < 2; half++) {
            int gm = row0 + wm * 64 + mt * 16 + gid + half * 8;
            if (gm >= M) continue;
            #pragma unroll
            for (int nt = 0; nt < 8; nt++) {
                int gn = col0 + wn * 64 + nt * 8 + 2 * tig;
                if (gn >= N) continue;
                float v0 = acc[mt][nt][half * 2 + 0] * alpha;
                float v1 = acc[mt][nt][half * 2 + 1] * alpha;
                if (BIAS)  { v0 += biasg[gn]; v1 += biasg[gn + 1]; }
                if (RESID) {
                    const float* ci = Cin + (size_t)gm * ldc + gn;
                    v0 += ci[0]; v1 += ci[1];
                }
                if (RELU) { v0 = fmaxf(v0, 0.f); v1 = fmaxf(v1, 0.f); }
                if (HALF_OUT) {
                    __half* cp = (__half*)Cg + (size_t)gm * ldc + gn;
                    *(__half2*)cp = __halves2half2(__float2half_rn(v0), __float2half_rn(v1));
                } else {
                    float* cp = (float*)Cg + (size_t)gm * ldc + gn;
                    *(float2*)cp = make_float2(v0, v1);
                }
            }
        }
    }
}

// ============ fused flash attention (fp16 operands, fp32 accum) ============
constexpr int FQ_LDH = 72, FV_LDH = 136, FP_LDH = 136;
constexpr int OFF_Q = 0;
constexpr int OFF_K = 128 * FQ_LDH;                 // 9216
constexpr int OFF_V = OFF_K + 128 * FQ_LDH;         // 18432
constexpr int OFF_P = OFF_V + 64 * FV_LDH;          // 27136
constexpr int ATT_SMEM = (OFF_P + 128 * FP_LDH) * 2;  // 89,088 B -> 2 CTAs/SM

__global__ void __launch_bounds__(128) attn_k(const __half* __restrict__ qkv,
                                              __half* __restrict__ og) {
    extern __shared__ __half smh[];
    __half* smQ = smh + OFF_Q;
    __half* smK = smh + OFF_K;
    __half* smV = smh + OFF_V;
    __half* smP = smh + OFF_P;
    uint32_t sb = smem_u32(smh);

    int z  = blockIdx.x;
    int qb = z & 7, bh = z >> 3;
    int b  = bh >> 4, h = bh & 15;
    int row0 = qb * 128;
    const __half* qp = qkv + (size_t)b * S_ * 3 * D_ + (size_t)h * DH_;
    const __half* kp = qp + D_;
    const __half* vt = g_vT + (size_t)bh * DH_ * S_;

    int tid = threadIdx.x, wid = tid >> 5, lane = tid & 31;
    int gid = lane >> 2, tig = lane & 3;
    int wr  = wid * 32;

    float oacc[2][8][4];
    #pragma unroll
    for (int mt = 0; mt < 2; mt++)
        #pragma unroll
        for (int nt = 0; nt < 8; nt++)
            #pragma unroll
            for (int d = 0; d < 4; d++) oacc[mt][nt][d] = 0.f;
    float mrow[2][2] = {{-1e30f, -1e30f}, {-1e30f, -1e30f}};
    float lrow[2][2] = {{0.f, 0.f}, {0.f, 0.f}};

    // Q load (once) + K chunk 0 : rows of 64 halves = 128B = 8x16B
    #pragma unroll
    for (int i = 0; i < 8; i++) {
        int t = tid + i * 128; int r = t >> 3, c = (t & 7) * 8;
        cpa16(sb + (OFF_Q + r * FQ_LDH + c) * 2, qp + (size_t)(row0 + r) * 3 * D_ + c, true);
    }
    CPA_COMMIT();
    #pragma unroll
    for (int i = 0; i < 8; i++) {
        int t = tid + i * 128; int r = t >> 3, c = (t & 7) * 8;
        cpa16(sb + (OFF_K + r * FQ_LDH + c) * 2, kp + (size_t)r * 3 * D_ + c, true);
    }
    CPA_COMMIT();

    int nch = qb + 1;
    for (int c = 0; c < nch; c++) {
        CPA_WAIT0();
        __syncthreads();
        // prefetch V_c : 64 rows x 128 halves (256B) = 16x16B per row
        #pragma unroll
        for (int i = 0; i < 8; i++) {
            int t = tid + i * 128; int r = t >> 4, cc = (t & 15) * 8;
            cpa16(sb + (OFF_V + r * FV_LDH + cc) * 2, vt + (size_t)r * S_ + c * 128 + cc, true);
        }
        CPA_COMMIT();

        // ---- S = Q @ K^T  (K=64, 4 ksteps of 16) ----
        float sacc[2][16][4];
        #pragma unroll
        for (int mt = 0; mt < 2; mt++)
            #pragma unroll
            for (int nt = 0; nt < 16; nt++)
                #pragma unroll
                for (int d = 0; d < 4; d++) sacc[mt][nt][d] = 0.f;
        #pragma unroll
        for (int ks = 0; ks < 4; ks++) {
            int kc = ks * 16 + 2 * tig;
            uint32_t af[2][4];
            #pragma unroll
            for (int mt = 0; mt < 2; mt++) {
                const __half* p = smQ + (wr + 16 * mt + gid) * FQ_LDH;
                af[mt][0] = ldh2(p + kc);
                af[mt][1] = ldh2(p + 8 * FQ_LDH + kc);
                af[mt][2] = ldh2(p + kc + 8);
                af[mt][3] = ldh2(p + 8 * FQ_LDH + kc + 8);
            }
            #pragma unroll
            for (int nt = 0; nt < 16; nt++) {
                const __half* pb = smK + (nt * 8 + gid) * FQ_LDH;
                uint32_t bf[2] = {ldh2(pb + kc), ldh2(pb + kc + 8)};
                mma16816(sacc[0][nt], af[0], bf);
                mma16816(sacc[1][nt], af[1], bf);
            }
        }

        // ---- scale + causal mask + online softmax ----
        bool diag = (c == qb);
        #pragma unroll
        for (int mt = 0; mt < 2; mt++) {
            #pragma unroll
            for (int half = 0; half < 2; half++) {
                int d0 = 2 * half;
                int ig = row0 + wr + 16 * mt + 8 * half + gid;
                float mx = -1e30f;
                #pragma unroll
                for (int nt = 0; nt < 16; nt++) {
                    float a = sacc[mt][nt][d0]     * 0.125f;
                    float e = sacc[mt][nt][d0 + 1] * 0.125f;
                    if (diag) {
                        int j = c * 128 + nt * 8 + 2 * tig;
                        if (j     > ig) a = -1e30f;
                        if (j + 1 > ig) e = -1e30f;
                    }
                    sacc[mt][nt][d0]     = a;
                    sacc[mt][nt][d0 + 1] = e;
                    mx = fmaxf(mx, fmaxf(a, e));
                }
                mx = fmaxf(mx, __shfl_xor_sync(0xffffffffu, mx, 1));
                mx = fmaxf(mx, __shfl_xor_sync(0xffffffffu, mx, 2));
                float mnew = fmaxf(mrow[mt][half], mx);
                float scl  = __expf(mrow[mt][half] - mnew);
                mrow[mt][half] = mnew;
                float ps = 0.f;
                int prow = wr + 16 * mt + 8 * half + gid;
                #pragma unroll
                for (int nt = 0; nt < 16; nt++) {
                    float p0 = __expf(sacc[mt][nt][d0]     - mnew);
                    float p1 = __expf(sacc[mt][nt][d0 + 1] - mnew);
                    ps += p0 + p1;
                    *(__half2*)&smP[prow * FP_LDH + nt * 8 + 2 * tig] =
                        __halves2half2(__float2half_rn(p0), __float2half_rn(p1));
                }
                ps += __shfl_xor_sync(0xffffffffu, ps, 1);
                ps += __shfl_xor_sync(0xffffffffu, ps, 2);
                lrow[mt][half] = lrow[mt][half] * scl + ps;
                #pragma unroll
                for (int nt = 0; nt < 8; nt++) {
                    oacc[mt][nt][d0]     *= scl;
                    oacc[mt][nt][d0 + 1] *= scl;
                }
            }
        }
        __syncwarp();

        CPA_WAIT0();               // V_c arrived
        __syncthreads();           // all warps done with K -> safe to overwrite
        if (c + 1 < nch) {
            #pragma unroll
            for (int i = 0; i < 8; i++) {
                int t = tid + i * 128; int r = t >> 3, cc = (t & 7) * 8;
                cpa16(sb + (OFF_K + r * FQ_LDH + cc) * 2,
                      kp + (size_t)((c + 1) * 128 + r) * 3 * D_ + cc, true);
            }
            CPA_COMMIT();
        }

        // ---- O += P @ V  (K=128, 8 ksteps) ----
        #pragma unroll
        for (int ks = 0; ks < 8; ks++) {
            int kc = ks * 16 + 2 * tig;
            uint32_t af[2][4];
            #pragma unroll
            for (int mt = 0; mt < 2; mt++) {
                const __half* p = smP + (wr + 16 * mt + gid) * FP_LDH;
                af[mt][0] = ldh2(p + kc);
                af[mt][1] = ldh2(p + 8 * FP_LDH + kc);
                af[mt][2] = ldh2(p + kc + 8);
                af[mt][3] = ldh2(p + 8 * FP_LDH + kc + 8);
            }
            #pragma unroll
            for (int nt = 0; nt < 8; nt++) {
                const __half* pb = smV + (nt * 8 + gid) * FV_LDH;
                uint32_t bf[2] = {ldh2(pb + kc), ldh2(pb + kc + 8)};
                mma16816(oacc[0][nt], af[0], bf);
                mma16816(oacc[1][nt], af[1], bf);
            }
        }
    }

    // ---- epilogue: O /= l, write half ----
    #pragma unroll
    for (int mt = 0; mt < 2; mt++) {
        #pragma unroll
        for (int half = 0; half < 2; half++) {
            float inv = 1.f / lrow[mt][half];
            int rg = row0 + wr + 16 * mt + 8 * half + gid;
            __half* orow = og + ((size_t)b * S_ + rg) * D_ + h * DH_;
            #pragma unroll
            for (int nt = 0; nt < 8; nt++) {
                float p0 = oacc[mt][nt][2 * half]     * inv;
                float p1 = oacc[mt][nt][2 * half + 1] * inv;
                *(__half2*)&orow[nt * 8 + 2 * tig] =
                    __halves2half2(__float2half_rn(p0), __float2half_rn(p1));
            }
        }
    }
}

// ============ auxiliary kernels ============
__global__ void embed_k(const int* __restrict__ idx, const float* __restrict__ emb,
                        const float* __restrict__ bq, const float* __restrict__ bk,
                        const float* __restrict__ bv) {
    int t = blockIdx.x * blockDim.x + threadIdx.x;
    if (t < NL_ * 3 * D_) {
        int l = t / (3 * D_), r = t - l * 3 * D_;
        float v = (r < D_) ? bq[l * D_ + r] : (r < 2 * D_) ? bk[l * D_ + r - D_] : bv[l * D_ + r - 2 * D_];
        g_bqkv[t] = v;
    }
    if (t >= BSZ_ * D_) return;
    int d = t & (D_ - 1);
    int bs = t >> 10;
    int s = bs & (S_ - 1);
    int tok = idx[bs];
    int i2 = d & ~1;
    float freq = __expf((float)i2 * (-9.210340371976184f / (float)D_));
    float ang = (float)s * freq;
    float pe = (d & 1) ? cosf(ang) : sinf(ang);
    g_x[t] = emb[(size_t)tok * D_ + d] * 32.0f + pe;
}

__global__ void roundcpy_k(const float* __restrict__ in, __half* __restrict__ out, size_t n) {
    size_t i = (size_t)blockIdx.x * blockDim.x + threadIdx.x;
    if (i < n) out[i] = __float2half_rn(in[i]);
}

__global__ void ln_k(const float* __restrict__ in, __half* __restrict__ out,
                     const float* __restrict__ sc, const float* __restrict__ bi) {
    int row = blockIdx.x;
    const float* x = in + (size_t)row * D_;
    int tid = threadIdx.x;
    float s = 0.f, ss = 0.f;
    for (int i = tid; i < D_; i += 256) { float v = x[i]; s += v; ss = fmaf(v, v, ss); }
    __shared__ float rs[8], rq[8];
    #pragma unroll
    for (int o = 16; o > 0; o >>= 1) {
        s  += __shfl_xor_sync(0xffffffffu, s,  o);
        ss += __shfl_xor_sync(0xffffffffu, ss, o);
    }
    if ((tid & 31) == 0) { rs[tid >> 5] = s; rq[tid >> 5] = ss; }
    __syncthreads();
    if (tid < 32) {
        float a = (tid < 8) ? rs[tid] : 0.f;
        float b = (tid < 8) ? rq[tid] : 0.f;
        #pragma unroll
        for (int o = 4; o > 0; o >>= 1) {
            a += __shfl_xor_sync(0xffffffffu, a, o);
            b += __shfl_xor_sync(0xffffffffu, b, o);
        }
        if (tid == 0) { rs[0] = a; rq[0] = b; }
    }
    __syncthreads();
    float mean = rs[0] * (1.0f / D_);
    float var  = rq[0] * (1.0f / D_) - mean * mean;
    float inv  = rsqrtf(var + 1e-5f);
    for (int i = tid; i < D_; i += 256)
        out[(size_t)row * D_ + i] = __float2half_rn((x[i] - mean) * inv * sc[i] + bi[i]);
}

template<typename Tin>
__global__ void transpose_k(const Tin* __restrict__ in, __half* __restrict__ out,
                            int R, int C, int ldi, int ldo,
                            int nz2, long sI1, long sI2, long sO1, long sO2)
{
    int z = blockIdx.z, z1 = z / nz2, z2 = z - z1 * nz2;
    in  += z1 * sI1 + z2 * sI2;
    out += z1 * sO1 + z2 * sO2;
    __shared__ float t[32][33];
    int c0 = blockIdx.x * 32, r0 = blockIdx.y * 32;
    int x = threadIdx.x, y = threadIdx.y;
    #pragma unroll
    for (int i = 0; i < 32; i += 8) {
        int r = r0 + y + i;
        if (r < R && c0 + x < C) t[y + i][x] = (float)in[(size_t)r * ldi + c0 + x];
    }
    __syncthreads();
    #pragma unroll
    for (int i = 0; i < 32; i += 8) {
        int c = c0 + y + i;
        if (c < C && r0 + x < R) out[(size_t)c * ldo + r0 + x] = __float2half_rn(t[x][y + i]);
    }
}

// ============ launch helpers ============
template<bool RELU, bool RESID, bool BIAS, bool HALF_OUT>
static void tc_gemm(const __half* A, const __half* B, const float* bias, const float* Cin, void* C,
                    int M, int N, int K, int lda, int ldb, int ldc, float alpha = 1.f)
{
    cudaFuncSetAttribute(gemm_h<RELU, RESID, BIAS, HALF_OUT>,
                         cudaFuncAttributeMaxDynamicSharedMemorySize, SMEMH);
    dim3 grid(cdiv(N, BN1), cdiv(M, BM1), 1);
    gemm_h<RELU, RESID, BIAS, HALF_OUT><<<grid, 128, SMEMH>>>(
        A, B, bias, Cin, C, M, N, K, lda, ldb, ldc, alpha);
}

template<typename Tin>
static void tr(const Tin* in, __half* out, int R, int C, int ldi, int ldo,
               int Z, int nz2, long sI1, long sI2, long sO1, long sO2)
{
    dim3 grid(cdiv(C, 32), cdiv(R, 32), Z);
    transpose_k<Tin><<<grid, dim3(32, 8)>>>(in, out, R, C, ldi, ldo, nz2, sI1, sI2, sO1, sO2);
}

// ============ orchestration ============
extern "C" void kernel_launch(void* const* d_in, const int* in_sizes, int n_in,
                              void* d_out, int out_size) {
    const int*   idx   = (const int*)  d_in[0];
    const float* emb   = (const float*)d_in[1];
    const float* cls_b = (const float*)d_in[2];
    const float* ln1_s = (const float*)d_in[3];
    const float* ln1_b = (const float*)d_in[4];
    const float* wq    = (const float*)d_in[5];
    const float* bq    = (const float*)d_in[6];
    const float* wk    = (const float*)d_in[7];
    const float* bk    = (const float*)d_in[8];
    const float* wv    = (const float*)d_in[9];
    const float* bv    = (const float*)d_in[10];
    const float* wo    = (const float*)d_in[11];
    const float* bo    = (const float*)d_in[12];
    const float* ln2_s = (const float*)d_in[13];
    const float* ln2_b = (const float*)d_in[14];
    const float* w1    = (const float*)d_in[15];
    const float* b1    = (const float*)d_in[16];
    const float* w2    = (const float*)d_in[17];
    const float* b2    = (const float*)d_in[18];
    const float* lnf_s = (const float*)d_in[19];
    const float* lnf_b = (const float*)d_in[20];
    float* out = (float*)d_out;

    float *gx, *gbq;
    __half *gh, *gqkv, *go, *gff, *gvT, *gwqkv, *gwoT, *gw1T, *gw2T, *gembr;
    cudaGetSymbolAddress((void**)&gx,   g_x);
    cudaGetSymbolAddress((void**)&gh,   g_h);
    cudaGetSymbolAddress((void**)&gqkv, g_qkv);
    cudaGetSymbolAddress((void**)&go,   g_o);
    cudaGetSymbolAddress((void**)&gff,  g_ff);
    cudaGetSymbolAddress((void**)&gvT,  g_vT);
    cudaGetSymbolAddress((void**)&gwqkv,g_wqkv);
    cudaGetSymbolAddress((void**)&gwoT, g_woT);
    cudaGetSymbolAddress((void**)&gw1T, g_w1T);
    cudaGetSymbolAddress((void**)&gw2T, g_w2T);
    cudaGetSymbolAddress((void**)&gbq,  g_bqkv);
    cudaGetSymbolAddress((void**)&gembr,g_embr);

    cudaFuncSetAttribute(attn_k, cudaFuncAttributeMaxDynamicSharedMemorySize, ATT_SMEM);

    embed_k<<<cdiv(BSZ_*D_, 256), 256>>>(idx, emb, bq, bk, bv);
    tr<float>(wq, gwqkv,                   D_, DH_, DH_, D_, NL_*H_, H_,
              (long)H_*D_*DH_, (long)D_*DH_, (long)3*D_*D_, (long)DH_*D_);
    tr<float>(wk, gwqkv + (size_t)D_*D_,   D_, DH_, DH_, D_, NL_*H_, H_,
              (long)H_*D_*DH_, (long)D_*DH_, (long)3*D_*D_, (long)DH_*D_);
    tr<float>(wv, gwqkv + (size_t)2*D_*D_, D_, DH_, DH_, D_, NL_*H_, H_,
              (long)H_*D_*DH_, (long)D_*DH_, (long)3*D_*D_, (long)DH_*D_);
    tr<float>(wo, gwoT, D_, D_, D_, D_, NL_, 1, (long)D_*D_, 0, (long)D_*D_, 0);
    tr<float>(w1, gw1T, D_, DFF_, DFF_, D_, NL_, 1, (long)D_*DFF_, 0, (long)DFF_*D_, 0);
    tr<float>(w2, gw2T, DFF_, D_, D_, DFF_, NL_, 1, (long)DFF_*D_, 0, (long)D_*DFF_, 0);
    roundcpy_k<<<cdiv(V_*D_, 256), 256>>>(emb, gembr, (size_t)V_*D_);

    const long sQ = (long)S_ * 3 * D_;

    for (int l = 0; l < NL_; l++) {
        ln_k<<<BSZ_, 256>>>(gx, gh, ln1_s + l*D_, ln1_b + l*D_);

        // qkv: [2048,1024] @ [3072,1024]^T -> half
        tc_gemm<false,false,true,true>(gh, gwqkv + (size_t)l*3*D_*D_, gbq + l*3*D_, nullptr, gqkv,
                                       BSZ_, 3*D_, D_, D_, D_, 3*D_);

        // V^T per (b,h)
        tr<__half>(gqkv + 2*D_, gvT, S_, DH_, 3*D_, S_, NB_*H_, H_,
                   sQ, DH_, (long)H_*DH_*S_, (long)DH_*S_);

        // fused attention
        attn_k<<<NB_*H_*8, 128, ATT_SMEM>>>(gqkv, go);

        // x += o @ wo^T + bo  (fp32 out)
        tc_gemm<false,true,true,false>(go, gwoT + (size_t)l*D_*D_, bo + l*D_, gx, gx,
                                       BSZ_, D_, D_, D_, D_, D_);

        ln_k<<<BSZ_, 256>>>(gx, gh, ln2_s + l*D_, ln2_b + l*D_);

        // ff = relu(h @ w1 + b1) -> half
        tc_gemm<true,false,true,true>(gh, gw1T + (size_t)l*DFF_*D_, b1 + l*DFF_, nullptr, gff,
                                      BSZ_, DFF_, D_, D_, D_, DFF_);
        // x += ff @ w2 + b2 (fp32 out)
        tc_gemm<false,true,true,false>(gff, gw2T + (size_t)l*D_*DFF_, b2 + l*D_, gx, gx,
                                       BSZ_, D_, DFF_, DFF_, DFF_, D_);
    }

    ln_k<<<BSZ_, 256>>>(gx, gh, lnf_s, lnf_b);

    // logits = h @ emb^T + cls_b (fp32 out)
    tc_gemm<false,false,true,false>(gh, gembr, cls_b, nullptr, out,
                                    BSZ_, V_, D_, D_, D_, V_);
}

// round 12
// speedup vs baseline: 2.4423x; 1.1749x over previous
#include <cuda_runtime.h>
#include <cuda_fp16.h>
#include <math.h>
#include <cstdint>

// ---------------- problem constants ----------------
#define D_   1024
#define H_   16
#define DH_  64
#define NL_  4
#define DFF_ 4096
#define V_   32000
#define S_   1024
#define NB_  2
#define BSZ_ (NB_*S_)

static inline int cdiv(int a, int b) { return (a + b - 1) / b; }

// ---------------- scratch ----------------
__device__ float  g_x   [BSZ_*D_];
__device__ __half g_h   [BSZ_*D_];
__device__ __half g_qkv [BSZ_*3*D_];
__device__ __half g_o   [BSZ_*D_];
__device__ __half g_ff  [BSZ_*DFF_];
__device__ __half g_vT  [(size_t)NB_*H_*DH_*S_];
__device__ __half g_wqkv[(size_t)NL_*3*D_*D_];
__device__ __half g_woT [(size_t)NL_*D_*D_];
__device__ __half g_w1T [(size_t)NL_*DFF_*D_];
__device__ __half g_w2T [(size_t)NL_*D_*DFF_];
__device__ float  g_bqkv[NL_*3*D_];
__device__ __half g_embr[(size_t)V_*D_];

// ---------------- helpers ----------------
__device__ __forceinline__ void mma16816(float* d, const uint32_t* a, const uint32_t* b) {
    asm volatile(
        "mma.sync.aligned.m16n8k16.row.col.f32.f16.f16.f32 "
        "{%0,%1,%2,%3}, {%4,%5,%6,%7}, {%8,%9}, {%0,%1,%2,%3};"
        : "+f"(d[0]), "+f"(d[1]), "+f"(d[2]), "+f"(d[3])
        : "r"(a[0]), "r"(a[1]), "r"(a[2]), "r"(a[3]), "r"(b[0]), "r"(b[1]));
}
__device__ __forceinline__ void ldsm4(uint32_t& r0, uint32_t& r1, uint32_t& r2, uint32_t& r3,
                                      uint32_t addr) {
    asm volatile("ldmatrix.sync.aligned.m8n8.x4.shared.b16 {%0,%1,%2,%3}, [%4];"
                 : "=r"(r0), "=r"(r1), "=r"(r2), "=r"(r3) : "r"(addr));
}
__device__ __forceinline__ uint32_t smem_u32(const void* p) {
    uint32_t a;
    asm("{ .reg .u64 t; cvta.to.shared.u64 t, %1; cvt.u32.u64 %0, t; }" : "=r"(a) : "l"(p));
    return a;
}
__device__ __forceinline__ void cpa16(uint32_t dst, const void* src, bool pred) {
    int sz = pred ? 16 : 0;
    asm volatile("cp.async.cg.shared.global [%0], [%1], 16, %2;"
                 :: "r"(dst), "l"(src), "r"(sz) : "memory");
}
#define CPA_COMMIT() asm volatile("cp.async.commit_group;" ::: "memory")
#define CPA_WAIT1()  asm volatile("cp.async.wait_group 1;" ::: "memory")
#define CPA_WAIT0()  asm volatile("cp.async.wait_group 0;" ::: "memory")
__device__ __forceinline__ uint32_t ldh2(const __half* p) { return *(const uint32_t*)p; }

// ============ fp16 mma GEMM: 128x128 tile, BK=32, 3-stage cp.async, ldmatrix ============
constexpr int BKH = 32, LDSH = 40, NSTAGE = 3;
constexpr int BM1 = 128, BN1 = 128;
constexpr int STGH  = 2 * BM1 * LDSH;            // halves per stage
constexpr int SMEMH = NSTAGE * STGH * 2;         // 61,440 B -> 3 CTAs/SM

template<bool RELU, bool RESID, bool BIAS, bool HALF_OUT>
__global__ void __launch_bounds__(128) gemm_h(
    const __half* __restrict__ A, const __half* __restrict__ B,
    const float* __restrict__ biasg, const float* __restrict__ Cin,
    void* __restrict__ Cg,
    int M, int N, int K, int lda, int ldb, int ldc, float alpha)
{
    int row0 = blockIdx.y * BM1;
    int col0 = blockIdx.x * BN1;

    extern __shared__ __half smh[];
    uint32_t sm0 = smem_u32(smh);

    int tid = threadIdx.x;
    int wid = tid >> 5, lane = tid & 31;
    int wm = wid >> 1, wn = wid & 1;
    int gid = lane >> 2, tig = lane & 3;

    int cr = tid >> 2;
    int cc = (tid & 3) * 8;

    // ldmatrix per-thread base addresses (bytes, stage-0)
    //   A op (mt): matrices (m0-7,k0),(m8-15,k0),(m0-7,k8),(m8-15,k8)
    int arow = wm * 64 + (lane & 15);
    int acolh = (lane & 16) ? 8 : 0;
    uint32_t aBase[4];
    #pragma unroll
    for (int mt = 0; mt < 4; mt++)
        aBase[mt] = sm0 + ((arow + mt * 16) * LDSH + acolh) * 2;
    //   B op (p): matrices (n=2p*8.., k0),(same n, k8),(n+8.., k0),(n+8.., k8)
    int brow = wn * 64 + ((lane & 16) ? 8 : 0) + (lane & 7);
    int bcolh = (lane & 8) ? 8 : 0;
    uint32_t bBase[4];
    #pragma unroll
    for (int p = 0; p < 4; p++)
        bBase[p] = sm0 + (BM1 * LDSH + (brow + p * 16) * LDSH + bcolh) * 2;

    float acc[4][8][4];
    #pragma unroll
    for (int a = 0; a < 4; a++)
        #pragma unroll
        for (int b = 0; b < 8; b++)
            #pragma unroll
            for (int c = 0; c < 4; c++) acc[a][b][c] = 0.f;

    int KT = K / BKH;

    auto issue = [&](int kt, int slot) {
        int k0 = kt * BKH;
        uint32_t abase = sm0 + (uint32_t)slot * STGH * 2;
        uint32_t bbase = abase + BM1 * LDSH * 2;
        #pragma unroll
        for (int i = 0; i < 4; i++) {
            int r = cr + i * 32;
            int gm = row0 + r;
            cpa16(abase + (r * LDSH + cc) * 2,
                  A + (size_t)(gm < M ? gm : 0) * lda + k0 + cc, gm < M);
            int gn = col0 + r;
            cpa16(bbase + (r * LDSH + cc) * 2,
                  B + (size_t)(gn < N ? gn : 0) * ldb + k0 + cc, gn < N);
        }
    };

    int nPre = KT < (NSTAGE - 1) ? KT : (NSTAGE - 1);
    for (int p = 0; p < nPre; p++) { issue(p, p); CPA_COMMIT(); }

    for (int kt = 0; kt < KT; kt++) {
        CPA_WAIT1();
        __syncthreads();
        int nxt = kt + NSTAGE - 1;
        if (nxt < KT) issue(nxt, nxt % NSTAGE);
        CPA_COMMIT();

        uint32_t stg = (uint32_t)(kt % NSTAGE) * STGH * 2;

        #pragma unroll
        for (int ks = 0; ks < 2; ks++) {
            uint32_t koff = stg + ks * 32;        // ks*16 halves
            uint32_t af[4][4], bf[8][2];
            #pragma unroll
            for (int mt = 0; mt < 4; mt++)
                ldsm4(af[mt][0], af[mt][1], af[mt][2], af[mt][3], aBase[mt] + koff);
            #pragma unroll
            for (int p = 0; p < 4; p++)
                ldsm4(bf[2*p][0], bf[2*p][1], bf[2*p+1][0], bf[2*p+1][1], bBase[p] + koff);
            #pragma unroll
            for (int mt = 0; mt < 4; mt++)
                #pragma unroll
                for (int nt = 0; nt < 8; nt++)
                    mma16816(acc[mt][nt], af[mt], bf[nt]);
        }
    }

    #pragma unroll
    for (int mt = 0; mt < 4; mt++) {
        #pragma unroll
        for (int half = 0; half < 2; half++) {
            int gm = row0 + wm * 64 + mt * 16 + gid + half * 8;
            if (gm >= M) continue;
            #pragma unroll
            for (int nt = 0; nt < 8; nt++) {
                int gn = col0 + wn * 64 + nt * 8 + 2 * tig;
                if (gn >= N) continue;
                float v0 = acc[mt][nt][half * 2 + 0] * alpha;
                float v1 = acc[mt][nt][half * 2 + 1] * alpha;
                if (BIAS)  { v0 += biasg[gn]; v1 += biasg[gn + 1]; }
                if (RESID) {
                    const float* ci = Cin + (size_t)gm * ldc + gn;
                    v0 += ci[0]; v1 += ci[1];
                }
                if (RELU) { v0 = fmaxf(v0, 0.f); v1 = fmaxf(v1, 0.f); }
                if (HALF_OUT) {
                    __half* cp = (__half*)Cg + (size_t)gm * ldc + gn;
                    *(__half2*)cp = __halves2half2(__float2half_rn(v0), __float2half_rn(v1));
                } else {
                    float* cp = (float*)Cg + (size_t)gm * ldc + gn;
                    *(float2*)cp = make_float2(v0, v1);
                }
            }
        }
    }
}

// ============ fused flash attention (fp16 operands, fp32 accum) ============
constexpr int FQ_LDH = 72, FV_LDH = 136, FP_LDH = 136;
constexpr int OFF_Q = 0;
constexpr int OFF_K = 128 * FQ_LDH;
constexpr int OFF_V = OFF_K + 128 * FQ_LDH;
constexpr int OFF_P = OFF_V + 64 * FV_LDH;
constexpr int ATT_SMEM = (OFF_P + 128 * FP_LDH) * 2;   // 89,088 B

__global__ void __launch_bounds__(128) attn_k(const __half* __restrict__ qkv,
                                              __half* __restrict__ og) {
    extern __shared__ __half smh[];
    __half* smQ = smh + OFF_Q;
    __half* smK = smh + OFF_K;
    __half* smV = smh + OFF_V;
    __half* smP = smh + OFF_P;
    uint32_t sb = smem_u32(smh);

    int z  = blockIdx.x;
    int qb = z & 7, bh = z >> 3;
    int b  = bh >> 4, h = bh & 15;
    int row0 = qb * 128;
    const __half* qp = qkv + (size_t)b * S_ * 3 * D_ + (size_t)h * DH_;
    const __half* kp = qp + D_;
    const __half* vt = g_vT + (size_t)bh * DH_ * S_;

    int tid = threadIdx.x, wid = tid >> 5, lane = tid & 31;
    int gid = lane >> 2, tig = lane & 3;
    int wr  = wid * 32;

    float oacc[2][8][4];
    #pragma unroll
    for (int mt = 0; mt < 2; mt++)
        #pragma unroll
        for (int nt = 0; nt < 8; nt++)
            #pragma unroll
            for (int d = 0; d < 4; d++) oacc[mt][nt][d] = 0.f;
    float mrow[2][2] = {{-1e30f, -1e30f}, {-1e30f, -1e30f}};
    float lrow[2][2] = {{0.f, 0.f}, {0.f, 0.f}};

    #pragma unroll
    for (int i = 0; i < 8; i++) {
        int t = tid + i * 128; int r = t >> 3, c = (t & 7) * 8;
        cpa16(sb + (OFF_Q + r * FQ_LDH + c) * 2, qp + (size_t)(row0 + r) * 3 * D_ + c, true);
    }
    CPA_COMMIT();
    #pragma unroll
    for (int i = 0; i < 8; i++) {
        int t = tid + i * 128; int r = t >> 3, c = (t & 7) * 8;
        cpa16(sb + (OFF_K + r * FQ_LDH + c) * 2, kp + (size_t)r * 3 * D_ + c, true);
    }
    CPA_COMMIT();

    int nch = qb + 1;
    for (int c = 0; c < nch; c++) {
        CPA_WAIT0();
        __syncthreads();
        #pragma unroll
        for (int i = 0; i < 8; i++) {
            int t = tid + i * 128; int r = t >> 4, cc = (t & 15) * 8;
            cpa16(sb + (OFF_V + r * FV_LDH + cc) * 2, vt + (size_t)r * S_ + c * 128 + cc, true);
        }
        CPA_COMMIT();

        float sacc[2][16][4];
        #pragma unroll
        for (int mt = 0; mt < 2; mt++)
            #pragma unroll
            for (int nt = 0; nt < 16; nt++)
                #pragma unroll
                for (int d = 0; d < 4; d++) sacc[mt][nt][d] = 0.f;
        #pragma unroll
        for (int ks = 0; ks < 4; ks++) {
            int kc = ks * 16 + 2 * tig;
            uint32_t af[2][4];
            #pragma unroll
            for (int mt = 0; mt < 2; mt++) {
                const __half* p = smQ + (wr + 16 * mt + gid) * FQ_LDH;
                af[mt][0] = ldh2(p + kc);
                af[mt][1] = ldh2(p + 8 * FQ_LDH + kc);
                af[mt][2] = ldh2(p + kc + 8);
                af[mt][3] = ldh2(p + 8 * FQ_LDH + kc + 8);
            }
            #pragma unroll
            for (int nt = 0; nt < 16; nt++) {
                const __half* pb = smK + (nt * 8 + gid) * FQ_LDH;
                uint32_t bf[2] = {ldh2(pb + kc), ldh2(pb + kc + 8)};
                mma16816(sacc[0][nt], af[0], bf);
                mma16816(sacc[1][nt], af[1], bf);
            }
        }

        bool diag = (c == qb);
        #pragma unroll
        for (int mt = 0; mt < 2; mt++) {
            #pragma unroll
            for (int half = 0; half < 2; half++) {
                int d0 = 2 * half;
                int ig = row0 + wr + 16 * mt + 8 * half + gid;
                float mx = -1e30f;
                #pragma unroll
                for (int nt = 0; nt < 16; nt++) {
                    float a = sacc[mt][nt][d0]     * 0.125f;
                    float e = sacc[mt][nt][d0 + 1] * 0.125f;
                    if (diag) {
                        int j = c * 128 + nt * 8 + 2 * tig;
                        if (j     > ig) a = -1e30f;
                        if (j + 1 > ig) e = -1e30f;
                    }
                    sacc[mt][nt][d0]     = a;
                    sacc[mt][nt][d0 + 1] = e;
                    mx = fmaxf(mx, fmaxf(a, e));
                }
                mx = fmaxf(mx, __shfl_xor_sync(0xffffffffu, mx, 1));
                mx = fmaxf(mx, __shfl_xor_sync(0xffffffffu, mx, 2));
                float mnew = fmaxf(mrow[mt][half], mx);
                float scl  = __expf(mrow[mt][half] - mnew);
                mrow[mt][half] = mnew;
                float ps = 0.f;
                int prow = wr + 16 * mt + 8 * half + gid;
                #pragma unroll
                for (int nt = 0; nt < 16; nt++) {
                    float p0 = __expf(sacc[mt][nt][d0]     - mnew);
                    float p1 = __expf(sacc[mt][nt][d0 + 1] - mnew);
                    ps += p0 + p1;
                    *(__half2*)&smP[prow * FP_LDH + nt * 8 + 2 * tig] =
                        __halves2half2(__float2half_rn(p0), __float2half_rn(p1));
                }
                ps += __shfl_xor_sync(0xffffffffu, ps, 1);
                ps += __shfl_xor_sync(0xffffffffu, ps, 2);
                lrow[mt][half] = lrow[mt][half] * scl + ps;
                #pragma unroll
                for (int nt = 0; nt < 8; nt++) {
                    oacc[mt][nt][d0]     *= scl;
                    oacc[mt][nt][d0 + 1] *= scl;
                }
            }
        }
        __syncwarp();

        CPA_WAIT0();
        __syncthreads();
        if (c + 1 < nch) {
            #pragma unroll
            for (int i = 0; i < 8; i++) {
                int t = tid + i * 128; int r = t >> 3, cc = (t & 7) * 8;
                cpa16(sb + (OFF_K + r * FQ_LDH + cc) * 2,
                      kp + (size_t)((c + 1) * 128 + r) * 3 * D_ + cc, true);
            }
            CPA_COMMIT();
        }

        #pragma unroll
        for (int ks = 0; ks < 8; ks++) {
            int kc = ks * 16 + 2 * tig;
            uint32_t af[2][4];
            #pragma unroll
            for (int mt = 0; mt < 2; mt++) {
                const __half* p = smP + (wr + 16 * mt + gid) * FP_LDH;
                af[mt][0] = ldh2(p + kc);
                af[mt][1] = ldh2(p + 8 * FP_LDH + kc);
                af[mt][2] = ldh2(p + kc + 8);
                af[mt][3] = ldh2(p + 8 * FP_LDH + kc + 8);
            }
            #pragma unroll
            for (int nt = 0; nt < 8; nt++) {
                const __half* pb = smV + (nt * 8 + gid) * FV_LDH;
                uint32_t bf[2] = {ldh2(pb + kc), ldh2(pb + kc + 8)};
                mma16816(oacc[0][nt], af[0], bf);
                mma16816(oacc[1][nt], af[1], bf);
            }
        }
    }

    #pragma unroll
    for (int mt = 0; mt < 2; mt++) {
        #pragma unroll
        for (int half = 0; half < 2; half++) {
            float inv = 1.f / lrow[mt][half];
            int rg = row0 + wr + 16 * mt + 8 * half + gid;
            __half* orow = og + ((size_t)b * S_ + rg) * D_ + h * DH_;
            #pragma unroll
            for (int nt = 0; nt < 8; nt++) {
                float p0 = oacc[mt][nt][2 * half]     * inv;
                float p1 = oacc[mt][nt][2 * half + 1] * inv;
                *(__half2*)&orow[nt * 8 + 2 * tig] =
                    __halves2half2(__float2half_rn(p0), __float2half_rn(p1));
            }
        }
    }
}

// ============ auxiliary kernels ============
__global__ void embed_k(const int* __restrict__ idx, const float* __restrict__ emb,
                        const float* __restrict__ bq, const float* __restrict__ bk,
                        const float* __restrict__ bv) {
    int t = blockIdx.x * blockDim.x + threadIdx.x;
    if (t < NL_ * 3 * D_) {
        int l = t / (3 * D_), r = t - l * 3 * D_;
        float v = (r < D_) ? bq[l * D_ + r] : (r < 2 * D_) ? bk[l * D_ + r - D_] : bv[l * D_ + r - 2 * D_];
        g_bqkv[t] = v;
    }
    if (t >= BSZ_ * D_) return;
    int d = t & (D_ - 1);
    int bs = t >> 10;
    int s = bs & (S_ - 1);
    int tok = idx[bs];
    int i2 = d & ~1;
    float freq = __expf((float)i2 * (-9.210340371976184f / (float)D_));
    float ang = (float)s * freq;
    float pe = (d & 1) ? cosf(ang) : sinf(ang);
    g_x[t] = emb[(size_t)tok * D_ + d] * 32.0f + pe;
}

__global__ void roundcpy_k(const float* __restrict__ in, __half* __restrict__ out, size_t n) {
    size_t i = (size_t)blockIdx.x * blockDim.x + threadIdx.x;
    if (i < n) out[i] = __float2half_rn(in[i]);
}

__global__ void ln_k(const float* __restrict__ in, __half* __restrict__ out,
                     const float* __restrict__ sc, const float* __restrict__ bi) {
    int row = blockIdx.x;
    const float* x = in + (size_t)row * D_;
    int tid = threadIdx.x;
    float s = 0.f, ss = 0.f;
    for (int i = tid; i < D_; i += 256) { float v = x[i]; s += v; ss = fmaf(v, v, ss); }
    __shared__ float rs[8], rq[8];
    #pragma unroll
    for (int o = 16; o > 0; o >>= 1) {
        s  += __shfl_xor_sync(0xffffffffu, s,  o);
        ss += __shfl_xor_sync(0xffffffffu, ss, o);
    }
    if ((tid & 31) == 0) { rs[tid >> 5] = s; rq[tid >> 5] = ss; }
    __syncthreads();
    if (tid < 32) {
        float a = (tid < 8) ? rs[tid] : 0.f;
        float b = (tid < 8) ? rq[tid] : 0.f;
        #pragma unroll
        for (int o = 4; o > 0; o >>= 1) {
            a += __shfl_xor_sync(0xffffffffu, a, o);
            b += __shfl_xor_sync(0xffffffffu, b, o);
        }
        if (tid == 0) { rs[0] = a; rq[0] = b; }
    }
    __syncthreads();
    float mean = rs[0] * (1.0f / D_);
    float var  = rq[0] * (1.0f / D_) - mean * mean;
    float inv  = rsqrtf(var + 1e-5f);
    for (int i = tid; i < D_; i += 256)
        out[(size_t)row * D_ + i] = __float2half_rn((x[i] - mean) * inv * sc[i] + bi[i]);
}

template<typename Tin>
__global__ void transpose_k(const Tin* __restrict__ in, __half* __restrict__ out,
                            int R, int C, int ldi, int ldo,
                            int nz2, long sI1, long sI2, long sO1, long sO2)
{
    int z = blockIdx.z, z1 = z / nz2, z2 = z - z1 * nz2;
    in  += z1 * sI1 + z2 * sI2;
    out += z1 * sO1 + z2 * sO2;
    __shared__ float t[32][33];
    int c0 = blockIdx.x * 32, r0 = blockIdx.y * 32;
    int x = threadIdx.x, y = threadIdx.y;
    #pragma unroll
    for (int i = 0; i < 32; i += 8) {
        int r = r0 + y + i;
        if (r < R && c0 + x < C) t[y + i][x] = (float)in[(size_t)r * ldi + c0 + x];
    }
    __syncthreads();
    #pragma unroll
    for (int i = 0; i < 32; i += 8) {
        int c = c0 + y + i;
        if (c < C && r0 + x < R) out[(size_t)c * ldo + r0 + x] = __float2half_rn(t[x][y + i]);
    }
}

// ============ launch helpers ============
template<bool RELU, bool RESID, bool BIAS, bool HALF_OUT>
static void tc_gemm(const __half* A, const __half* B, const float* bias, const float* Cin, void* C,
                    int M, int N, int K, int lda, int ldb, int ldc, float alpha = 1.f)
{
    cudaFuncSetAttribute(gemm_h<RELU, RESID, BIAS, HALF_OUT>,
                         cudaFuncAttributeMaxDynamicSharedMemorySize, SMEMH);
    dim3 grid(cdiv(N, BN1), cdiv(M, BM1), 1);
    gemm_h<RELU, RESID, BIAS, HALF_OUT><<<grid, 128, SMEMH>>>(
        A, B, bias, Cin, C, M, N, K, lda, ldb, ldc, alpha);
}

template<typename Tin>
static void tr(const Tin* in, __half* out, int R, int C, int ldi, int ldo,
               int Z, int nz2, long sI1, long sI2, long sO1, long sO2)
{
    dim3 grid(cdiv(C, 32), cdiv(R, 32), Z);
    transpose_k<Tin><<<grid, dim3(32, 8)>>>(in, out, R, C, ldi, ldo, nz2, sI1, sI2, sO1, sO2);
}

// ============ orchestration ============
extern "C" void kernel_launch(void* const* d_in, const int* in_sizes, int n_in,
                              void* d_out, int out_size) {
    const int*   idx   = (const int*)  d_in[0];
    const float* emb   = (const float*)d_in[1];
    const float* cls_b = (const float*)d_in[2];
    const float* ln1_s = (const float*)d_in[3];
    const float* ln1_b = (const float*)d_in[4];
    const float* wq    = (const float*)d_in[5];
    const float* bq    = (const float*)d_in[6];
    const float* wk    = (const float*)d_in[7];
    const float* bk    = (const float*)d_in[8];
    const float* wv    = (const float*)d_in[9];
    const float* bv    = (const float*)d_in[10];
    const float* wo    = (const float*)d_in[11];
    const float* bo    = (const float*)d_in[12];
    const float* ln2_s = (const float*)d_in[13];
    const float* ln2_b = (const float*)d_in[14];
    const float* w1    = (const float*)d_in[15];
    const float* b1    = (const float*)d_in[16];
    const float* w2    = (const float*)d_in[17];
    const float* b2    = (const float*)d_in[18];
    const float* lnf_s = (const float*)d_in[19];
    const float* lnf_b = (const float*)d_in[20];
    float* out = (float*)d_out;

    float *gx, *gbq;
    __half *gh, *gqkv, *go, *gff, *gvT, *gwqkv, *gwoT, *gw1T, *gw2T, *gembr;
    cudaGetSymbolAddress((void**)&gx,   g_x);
    cudaGetSymbolAddress((void**)&gh,   g_h);
    cudaGetSymbolAddress((void**)&gqkv, g_qkv);
    cudaGetSymbolAddress((void**)&go,   g_o);
    cudaGetSymbolAddress((void**)&gff,  g_ff);
    cudaGetSymbolAddress((void**)&gvT,  g_vT);
    cudaGetSymbolAddress((void**)&gwqkv,g_wqkv);
    cudaGetSymbolAddress((void**)&gwoT, g_woT);
    cudaGetSymbolAddress((void**)&gw1T, g_w1T);
    cudaGetSymbolAddress((void**)&gw2T, g_w2T);
    cudaGetSymbolAddress((void**)&gbq,  g_bqkv);
    cudaGetSymbolAddress((void**)&gembr,g_embr);

    cudaFuncSetAttribute(attn_k, cudaFuncAttributeMaxDynamicSharedMemorySize, ATT_SMEM);

    embed_k<<<cdiv(BSZ_*D_, 256), 256>>>(idx, emb, bq, bk, bv);
    tr<float>(wq, gwqkv,                   D_, DH_, DH_, D_, NL_*H_, H_,
              (long)H_*D_*DH_, (long)D_*DH_, (long)3*D_*D_, (long)DH_*D_);
    tr<float>(wk, gwqkv + (size_t)D_*D_,   D_, DH_, DH_, D_, NL_*H_, H_,
              (long)H_*D_*DH_, (long)D_*DH_, (long)3*D_*D_, (long)DH_*D_);
    tr<float>(wv, gwqkv + (size_t)2*D_*D_, D_, DH_, DH_, D_, NL_*H_, H_,
              (long)H_*D_*DH_, (long)D_*DH_, (long)3*D_*D_, (long)DH_*D_);
    tr<float>(wo, gwoT, D_, D_, D_, D_, NL_, 1, (long)D_*D_, 0, (long)D_*D_, 0);
    tr<float>(w1, gw1T, D_, DFF_, DFF_, D_, NL_, 1, (long)D_*DFF_, 0, (long)DFF_*D_, 0);
    tr<float>(w2, gw2T, DFF_, D_, D_, DFF_, NL_, 1, (long)DFF_*D_, 0, (long)D_*DFF_, 0);
    roundcpy_k<<<cdiv(V_*D_, 256), 256>>>(emb, gembr, (size_t)V_*D_);

    const long sQ = (long)S_ * 3 * D_;

    for (int l = 0; l < NL_; l++) {
        ln_k<<<BSZ_, 256>>>(gx, gh, ln1_s + l*D_, ln1_b + l*D_);

        tc_gemm<false,false,true,true>(gh, gwqkv + (size_t)l*3*D_*D_, gbq + l*3*D_, nullptr, gqkv,
                                       BSZ_, 3*D_, D_, D_, D_, 3*D_);

        tr<__half>(gqkv + 2*D_, gvT, S_, DH_, 3*D_, S_, NB_*H_, H_,
                   sQ, DH_, (long)H_*DH_*S_, (long)DH_*S_);

        attn_k<<<NB_*H_*8, 128, ATT_SMEM>>>(gqkv, go);

        tc_gemm<false,true,true,false>(go, gwoT + (size_t)l*D_*D_, bo + l*D_, gx, gx,
                                       BSZ_, D_, D_, D_, D_, D_);

        ln_k<<<BSZ_, 256>>>(gx, gh, ln2_s + l*D_, ln2_b + l*D_);

        tc_gemm<true,false,true,true>(gh, gw1T + (size_t)l*DFF_*D_, b1 + l*DFF_, nullptr, gff,
                                      BSZ_, DFF_, D_, D_, D_, DFF_);
        tc_gemm<false,true,true,false>(gff, gw2T + (size_t)l*D_*DFF_, b2 + l*D_, gx, gx,
                                       BSZ_, D_, DFF_, DFF_, DFF_, D_);
    }

    ln_k<<<BSZ_, 256>>>(gx, gh, lnf_s, lnf_b);

    tc_gemm<false,false,true,false>(gh, gembr, cls_b, nullptr, out,
                                    BSZ_, V_, D_, D_, D_, V_);
}

// round 13
// speedup vs baseline: 2.5149x; 1.0297x over previous
#include <cuda_runtime.h>
#include <cuda_fp16.h>
#include <math.h>
#include <cstdint>

// ---------------- problem constants ----------------
#define D_   1024
#define H_   16
#define DH_  64
#define NL_  4
#define DFF_ 4096
#define V_   32000
#define S_   1024
#define NB_  2
#define BSZ_ (NB_*S_)

static inline int cdiv(int a, int b) { return (a + b - 1) / b; }

// ---------------- scratch ----------------
__device__ float  g_x   [BSZ_*D_];
__device__ __half g_h   [BSZ_*D_];
__device__ __half g_qkv [BSZ_*3*D_];
__device__ __half g_o   [BSZ_*D_];
__device__ __half g_ff  [BSZ_*DFF_];
__device__ __half g_vT  [(size_t)NB_*H_*DH_*S_];
__device__ __half g_wqkv[(size_t)NL_*3*D_*D_];
__device__ __half g_woT [(size_t)NL_*D_*D_];
__device__ __half g_w1T [(size_t)NL_*DFF_*D_];
__device__ __half g_w2T [(size_t)NL_*D_*DFF_];
__device__ float  g_bqkv[NL_*3*D_];
__device__ __half g_embr[(size_t)V_*D_];

// ---------------- helpers ----------------
__device__ __forceinline__ void mma16816(float* d, const uint32_t* a, const uint32_t* b) {
    asm volatile(
        "mma.sync.aligned.m16n8k16.row.col.f32.f16.f16.f32 "
        "{%0,%1,%2,%3}, {%4,%5,%6,%7}, {%8,%9}, {%0,%1,%2,%3};"
        : "+f"(d[0]), "+f"(d[1]), "+f"(d[2]), "+f"(d[3])
        : "r"(a[0]), "r"(a[1]), "r"(a[2]), "r"(a[3]), "r"(b[0]), "r"(b[1]));
}
__device__ __forceinline__ void ldsm4(uint32_t& r0, uint32_t& r1, uint32_t& r2, uint32_t& r3,
                                      uint32_t addr) {
    asm volatile("ldmatrix.sync.aligned.m8n8.x4.shared.b16 {%0,%1,%2,%3}, [%4];"
                 : "=r"(r0), "=r"(r1), "=r"(r2), "=r"(r3) : "r"(addr));
}
__device__ __forceinline__ uint32_t smem_u32(const void* p) {
    uint32_t a;
    asm("{ .reg .u64 t; cvta.to.shared.u64 t, %1; cvt.u32.u64 %0, t; }" : "=r"(a) : "l"(p));
    return a;
}
__device__ __forceinline__ void cpa16(uint32_t dst, const void* src, bool pred) {
    int sz = pred ? 16 : 0;
    asm volatile("cp.async.cg.shared.global [%0], [%1], 16, %2;"
                 :: "r"(dst), "l"(src), "r"(sz) : "memory");
}
#define CPA_COMMIT() asm volatile("cp.async.commit_group;" ::: "memory")
#define CPA_WAIT1()  asm volatile("cp.async.wait_group 1;" ::: "memory")
#define CPA_WAIT0()  asm volatile("cp.async.wait_group 0;" ::: "memory")

// ============ fp16 mma GEMM: 128x128 tile, BK=32, 3-stage cp.async, ldmatrix ============
constexpr int BKH = 32, LDSH = 40, NSTAGE = 3;
constexpr int BM1 = 128, BN1 = 128;
constexpr int STGH  = 2 * BM1 * LDSH;
constexpr int SMEMH = NSTAGE * STGH * 2;         // 61,440 B -> 3 CTAs/SM

template<bool RELU, bool RESID, bool BIAS, bool HALF_OUT>
__global__ void __launch_bounds__(128) gemm_h(
    const __half* __restrict__ A, const __half* __restrict__ B,
    const float* __restrict__ biasg, const float* __restrict__ Cin,
    void* __restrict__ Cg,
    int M, int N, int K, int lda, int ldb, int ldc, float alpha)
{
    int row0 = blockIdx.y * BM1;
    int col0 = blockIdx.x * BN1;

    extern __shared__ __half smh[];
    uint32_t sm0 = smem_u32(smh);

    int tid = threadIdx.x;
    int wid = tid >> 5, lane = tid & 31;
    int wm = wid >> 1, wn = wid & 1;
    int gid = lane >> 2, tig = lane & 3;

    int cr = tid >> 2;
    int cc = (tid & 3) * 8;

    int arow = wm * 64 + (lane & 15);
    int acolh = (lane & 16) ? 8 : 0;
    uint32_t aBase[4];
    #pragma unroll
    for (int mt = 0; mt < 4; mt++)
        aBase[mt] = sm0 + ((arow + mt * 16) * LDSH + acolh) * 2;
    int brow = wn * 64 + ((lane & 16) ? 8 : 0) + (lane & 7);
    int bcolh = (lane & 8) ? 8 : 0;
    uint32_t bBase[4];
    #pragma unroll
    for (int p = 0; p < 4; p++)
        bBase[p] = sm0 + (BM1 * LDSH + (brow + p * 16) * LDSH + bcolh) * 2;

    float acc[4][8][4];
    #pragma unroll
    for (int a = 0; a < 4; a++)
        #pragma unroll
        for (int b = 0; b < 8; b++)
            #pragma unroll
            for (int c = 0; c < 4; c++) acc[a][b][c] = 0.f;

    int KT = K / BKH;

    auto issue = [&](int kt, int slot) {
        int k0 = kt * BKH;
        uint32_t abase = sm0 + (uint32_t)slot * STGH * 2;
        uint32_t bbase = abase + BM1 * LDSH * 2;
        #pragma unroll
        for (int i = 0; i < 4; i++) {
            int r = cr + i * 32;
            int gm = row0 + r;
            cpa16(abase + (r * LDSH + cc) * 2,
                  A + (size_t)(gm < M ? gm : 0) * lda + k0 + cc, gm < M);
            int gn = col0 + r;
            cpa16(bbase + (r * LDSH + cc) * 2,
                  B + (size_t)(gn < N ? gn : 0) * ldb + k0 + cc, gn < N);
        }
    };

    int nPre = KT < (NSTAGE - 1) ? KT : (NSTAGE - 1);
    for (int p = 0; p < nPre; p++) { issue(p, p); CPA_COMMIT(); }

    for (int kt = 0; kt < KT; kt++) {
        CPA_WAIT1();
        __syncthreads();
        int nxt = kt + NSTAGE - 1;
        if (nxt < KT) issue(nxt, nxt % NSTAGE);
        CPA_COMMIT();

        uint32_t stg = (uint32_t)(kt % NSTAGE) * STGH * 2;

        #pragma unroll
        for (int ks = 0; ks < 2; ks++) {
            uint32_t koff = stg + ks * 32;
            uint32_t af[4][4], bf[8][2];
            #pragma unroll
            for (int mt = 0; mt < 4; mt++)
                ldsm4(af[mt][0], af[mt][1], af[mt][2], af[mt][3], aBase[mt] + koff);
            #pragma unroll
            for (int p = 0; p < 4; p++)
                ldsm4(bf[2*p][0], bf[2*p][1], bf[2*p+1][0], bf[2*p+1][1], bBase[p] + koff);
            #pragma unroll
            for (int mt = 0; mt < 4; mt++)
                #pragma unroll
                for (int nt = 0; nt < 8; nt++)
                    mma16816(acc[mt][nt], af[mt], bf[nt]);
        }
    }

    #pragma unroll
    for (int mt = 0; mt < 4; mt++) {
        #pragma unroll
        for (int half = 0; half < 2; half++) {
            int gm = row0 + wm * 64 + mt * 16 + gid + half * 8;
            if (gm >= M) continue;
            #pragma unroll
            for (int nt = 0; nt < 8; nt++) {
                int gn = col0 + wn * 64 + nt * 8 + 2 * tig;
                if (gn >= N) continue;
                float v0 = acc[mt][nt][half * 2 + 0] * alpha;
                float v1 = acc[mt][nt][half * 2 + 1] * alpha;
                if (BIAS)  { v0 += biasg[gn]; v1 += biasg[gn + 1]; }
                if (RESID) {
                    const float* ci = Cin + (size_t)gm * ldc + gn;
                    v0 += ci[0]; v1 += ci[1];
                }
                if (RELU) { v0 = fmaxf(v0, 0.f); v1 = fmaxf(v1, 0.f); }
                if (HALF_OUT) {
                    __half* cp = (__half*)Cg + (size_t)gm * ldc + gn;
                    *(__half2*)cp = __halves2half2(__float2half_rn(v0), __float2half_rn(v1));
                } else {
                    float* cp = (float*)Cg + (size_t)gm * ldc + gn;
                    *(float2*)cp = make_float2(v0, v1);
                }
            }
        }
    }
}

// ============ fused flash attention (ldmatrix fragment loads) ============
constexpr int FQ_LDH = 72, FV_LDH = 136, FP_LDH = 136;
constexpr int OFF_Q = 0;
constexpr int OFF_K = 128 * FQ_LDH;
constexpr int OFF_V = OFF_K + 128 * FQ_LDH;
constexpr int OFF_P = OFF_V + 64 * FV_LDH;
constexpr int ATT_SMEM = (OFF_P + 128 * FP_LDH) * 2;   // 89,088 B

__global__ void __launch_bounds__(128) attn_k(const __half* __restrict__ qkv,
                                              __half* __restrict__ og) {
    extern __shared__ __half smh[];
    __half* smP = smh + OFF_P;
    uint32_t sb = smem_u32(smh);

    int z  = blockIdx.x;
    int qb = z & 7, bh = z >> 3;
    int b  = bh >> 4, h = bh & 15;
    int row0 = qb * 128;
    const __half* qp = qkv + (size_t)b * S_ * 3 * D_ + (size_t)h * DH_;
    const __half* kp = qp + D_;
    const __half* vt = g_vT + (size_t)bh * DH_ * S_;

    int tid = threadIdx.x, wid = tid >> 5, lane = tid & 31;
    int gid = lane >> 2, tig = lane & 3;
    int wr  = wid * 32;

    // ldmatrix base addresses
    int arow  = wr + (lane & 15);
    int acolh = (lane & 16) ? 8 : 0;
    uint32_t qBase[2], pBase[2];
    #pragma unroll
    for (int mt = 0; mt < 2; mt++) {
        qBase[mt] = sb + (OFF_Q + (arow + mt * 16) * FQ_LDH + acolh) * 2;
        pBase[mt] = sb + (OFF_P + (arow + mt * 16) * FP_LDH + acolh) * 2;
    }
    int brow  = ((lane & 16) ? 8 : 0) + (lane & 7);
    int bcolh = (lane & 8) ? 8 : 0;
    uint32_t kBase[8], vBase[4];
    #pragma unroll
    for (int p = 0; p < 8; p++)
        kBase[p] = sb + (OFF_K + (brow + p * 16) * FQ_LDH + bcolh) * 2;
    #pragma unroll
    for (int p = 0; p < 4; p++)
        vBase[p] = sb + (OFF_V + (brow + p * 16) * FV_LDH + bcolh) * 2;

    float oacc[2][8][4];
    #pragma unroll
    for (int mt = 0; mt < 2; mt++)
        #pragma unroll
        for (int nt = 0; nt < 8; nt++)
            #pragma unroll
            for (int d = 0; d < 4; d++) oacc[mt][nt][d] = 0.f;
    float mrow[2][2] = {{-1e30f, -1e30f}, {-1e30f, -1e30f}};
    float lrow[2][2] = {{0.f, 0.f}, {0.f, 0.f}};

    #pragma unroll
    for (int i = 0; i < 8; i++) {
        int t = tid + i * 128; int r = t >> 3, c = (t & 7) * 8;
        cpa16(sb + (OFF_Q + r * FQ_LDH + c) * 2, qp + (size_t)(row0 + r) * 3 * D_ + c, true);
    }
    CPA_COMMIT();
    #pragma unroll
    for (int i = 0; i < 8; i++) {
        int t = tid + i * 128; int r = t >> 3, c = (t & 7) * 8;
        cpa16(sb + (OFF_K + r * FQ_LDH + c) * 2, kp + (size_t)r * 3 * D_ + c, true);
    }
    CPA_COMMIT();

    int nch = qb + 1;
    for (int c = 0; c < nch; c++) {
        CPA_WAIT0();
        __syncthreads();
        #pragma unroll
        for (int i = 0; i < 8; i++) {
            int t = tid + i * 128; int r = t >> 4, cc = (t & 15) * 8;
            cpa16(sb + (OFF_V + r * FV_LDH + cc) * 2, vt + (size_t)r * S_ + c * 128 + cc, true);
        }
        CPA_COMMIT();

        // ---- S = Q @ K^T  (K=64, 4 ksteps, ldmatrix) ----
        float sacc[2][16][4];
        #pragma unroll
        for (int mt = 0; mt < 2; mt++)
            #pragma unroll
            for (int nt = 0; nt < 16; nt++)
                #pragma unroll
                for (int d = 0; d < 4; d++) sacc[mt][nt][d] = 0.f;
        #pragma unroll
        for (int ks = 0; ks < 4; ks++) {
            uint32_t koff = ks * 32;                // ks*16 halves * 2B
            uint32_t af[2][4], bf[16][2];
            #pragma unroll
            for (int mt = 0; mt < 2; mt++)
                ldsm4(af[mt][0], af[mt][1], af[mt][2], af[mt][3], qBase[mt] + koff);
            #pragma unroll
            for (int p = 0; p < 8; p++)
                ldsm4(bf[2*p][0], bf[2*p][1], bf[2*p+1][0], bf[2*p+1][1], kBase[p] + koff);
            #pragma unroll
            for (int mt = 0; mt < 2; mt++)
                #pragma unroll
                for (int nt = 0; nt < 16; nt++)
                    mma16816(sacc[mt][nt], af[mt], bf[nt]);
        }

        // ---- scale + causal mask + online softmax ----
        bool diag = (c == qb);
        #pragma unroll
        for (int mt = 0; mt < 2; mt++) {
            #pragma unroll
            for (int half = 0; half < 2; half++) {
                int d0 = 2 * half;
                int ig = row0 + wr + 16 * mt + 8 * half + gid;
                float mx = -1e30f;
                #pragma unroll
                for (int nt = 0; nt < 16; nt++) {
                    float a = sacc[mt][nt][d0]     * 0.125f;
                    float e = sacc[mt][nt][d0 + 1] * 0.125f;
                    if (diag) {
                        int j = c * 128 + nt * 8 + 2 * tig;
                        if (j     > ig) a = -1e30f;
                        if (j + 1 > ig) e = -1e30f;
                    }
                    sacc[mt][nt][d0]     = a;
                    sacc[mt][nt][d0 + 1] = e;
                    mx = fmaxf(mx, fmaxf(a, e));
                }
                mx = fmaxf(mx, __shfl_xor_sync(0xffffffffu, mx, 1));
                mx = fmaxf(mx, __shfl_xor_sync(0xffffffffu, mx, 2));
                float mnew = fmaxf(mrow[mt][half], mx);
                float scl  = __expf(mrow[mt][half] - mnew);
                mrow[mt][half] = mnew;
                float ps = 0.f;
                int prow = wr + 16 * mt + 8 * half + gid;
                #pragma unroll
                for (int nt = 0; nt < 16; nt++) {
                    float p0 = __expf(sacc[mt][nt][d0]     - mnew);
                    float p1 = __expf(sacc[mt][nt][d0 + 1] - mnew);
                    ps += p0 + p1;
                    *(__half2*)&smP[prow * FP_LDH + nt * 8 + 2 * tig] =
                        __halves2half2(__float2half_rn(p0), __float2half_rn(p1));
                }
                ps += __shfl_xor_sync(0xffffffffu, ps, 1);
                ps += __shfl_xor_sync(0xffffffffu, ps, 2);
                lrow[mt][half] = lrow[mt][half] * scl + ps;
                #pragma unroll
                for (int nt = 0; nt < 8; nt++) {
                    oacc[mt][nt][d0]     *= scl;
                    oacc[mt][nt][d0 + 1] *= scl;
                }
            }
        }
        __syncwarp();

        CPA_WAIT0();
        __syncthreads();
        if (c + 1 < nch) {
            #pragma unroll
            for (int i = 0; i < 8; i++) {
                int t = tid + i * 128; int r = t >> 3, cc = (t & 7) * 8;
                cpa16(sb + (OFF_K + r * FQ_LDH + cc) * 2,
                      kp + (size_t)((c + 1) * 128 + r) * 3 * D_ + cc, true);
            }
            CPA_COMMIT();
        }

        // ---- O += P @ V  (K=128, 8 ksteps, ldmatrix) ----
        #pragma unroll
        for (int ks = 0; ks < 8; ks++) {
            uint32_t koff = ks * 32;
            uint32_t af[2][4], bf[8][2];
            #pragma unroll
            for (int mt = 0; mt < 2; mt++)
                ldsm4(af[mt][0], af[mt][1], af[mt][2], af[mt][3], pBase[mt] + koff);
            #pragma unroll
            for (int p = 0; p < 4; p++)
                ldsm4(bf[2*p][0], bf[2*p][1], bf[2*p+1][0], bf[2*p+1][1], vBase[p] + koff);
            #pragma unroll
            for (int mt = 0; mt < 2; mt++)
                #pragma unroll
                for (int nt = 0; nt < 8; nt++)
                    mma16816(oacc[mt][nt], af[mt], bf[nt]);
        }
    }

    #pragma unroll
    for (int mt = 0; mt < 2; mt++) {
        #pragma unroll
        for (int half = 0; half < 2; half++) {
            float inv = 1.f / lrow[mt][half];
            int rg = row0 + wr + 16 * mt + 8 * half + gid;
            __half* orow = og + ((size_t)b * S_ + rg) * D_ + h * DH_;
            #pragma unroll
            for (int nt = 0; nt < 8; nt++) {
                float p0 = oacc[mt][nt][2 * half]     * inv;
                float p1 = oacc[mt][nt][2 * half + 1] * inv;
                *(__half2*)&orow[nt * 8 + 2 * tig] =
                    __halves2half2(__float2half_rn(p0), __float2half_rn(p1));
            }
        }
    }
}

// ============ auxiliary kernels ============
__global__ void embed_k(const int* __restrict__ idx, const float* __restrict__ emb,
                        const float* __restrict__ bq, const float* __restrict__ bk,
                        const float* __restrict__ bv) {
    int t = blockIdx.x * blockDim.x + threadIdx.x;
    if (t < NL_ * 3 * D_) {
        int l = t / (3 * D_), r = t - l * 3 * D_;
        float v = (r < D_) ? bq[l * D_ + r] : (r < 2 * D_) ? bk[l * D_ + r - D_] : bv[l * D_ + r - 2 * D_];
        g_bqkv[t] = v;
    }
    if (t >= BSZ_ * D_) return;
    int d = t & (D_ - 1);
    int bs = t >> 10;
    int s = bs & (S_ - 1);
    int tok = idx[bs];
    int i2 = d & ~1;
    float freq = __expf((float)i2 * (-9.210340371976184f / (float)D_));
    float ang = (float)s * freq;
    float pe = (d & 1) ? cosf(ang) : sinf(ang);
    g_x[t] = emb[(size_t)tok * D_ + d] * 32.0f + pe;
}

__global__ void roundcpy_k(const float* __restrict__ in, __half* __restrict__ out, size_t n) {
    size_t i = (size_t)blockIdx.x * blockDim.x + threadIdx.x;
    if (i < n) out[i] = __float2half_rn(in[i]);
}

__global__ void ln_k(const float* __restrict__ in, __half* __restrict__ out,
                     const float* __restrict__ sc, const float* __restrict__ bi) {
    int row = blockIdx.x;
    const float* x = in + (size_t)row * D_;
    int tid = threadIdx.x;
    float s = 0.f, ss = 0.f;
    for (int i = tid; i < D_; i += 256) { float v = x[i]; s += v; ss = fmaf(v, v, ss); }
    __shared__ float rs[8], rq[8];
    #pragma unroll
    for (int o = 16; o > 0; o >>= 1) {
        s  += __shfl_xor_sync(0xffffffffu, s,  o);
        ss += __shfl_xor_sync(0xffffffffu, ss, o);
    }
    if ((tid & 31) == 0) { rs[tid >> 5] = s; rq[tid >> 5] = ss; }
    __syncthreads();
    if (tid < 32) {
        float a = (tid < 8) ? rs[tid] : 0.f;
        float b = (tid < 8) ? rq[tid] : 0.f;
        #pragma unroll
        for (int o = 4; o > 0; o >>= 1) {
            a += __shfl_xor_sync(0xffffffffu, a, o);
            b += __shfl_xor_sync(0xffffffffu, b, o);
        }
        if (tid == 0) { rs[0] = a; rq[0] = b; }
    }
    __syncthreads();
    float mean = rs[0] * (1.0f / D_);
    float var  = rq[0] * (1.0f / D_) - mean * mean;
    float inv  = rsqrtf(var + 1e-5f);
    for (int i = tid; i < D_; i += 256)
        out[(size_t)row * D_ + i] = __float2half_rn((x[i] - mean) * inv * sc[i] + bi[i]);
}

// merged QKV weight repack: z in [0, 3*NL*H); sel = z/(NL*H)
__global__ void qkvw_k(const float* __restrict__ wq, const float* __restrict__ wk,
                       const float* __restrict__ wv) {
    int z = blockIdx.z;
    int sel = z / (NL_ * H_);
    int lh  = z - sel * (NL_ * H_);
    int l = lh / H_, h = lh - l * H_;
    const float* src = (sel == 0 ? wq : sel == 1 ? wk : wv) + ((size_t)(l * H_ + h)) * D_ * DH_;
    __half* dst = g_wqkv + (size_t)l * 3 * D_ * D_ + (size_t)sel * D_ * D_ + (size_t)h * DH_ * D_;
    __shared__ float t[32][33];
    int c0 = blockIdx.x * 32, r0 = blockIdx.y * 32;
    int x = threadIdx.x, y = threadIdx.y;
    #pragma unroll
    for (int i = 0; i < 32; i += 8) {
        int r = r0 + y + i;
        if (r < D_ && c0 + x < DH_) t[y + i][x] = src[(size_t)r * DH_ + c0 + x];
    }
    __syncthreads();
    #pragma unroll
    for (int i = 0; i < 32; i += 8) {
        int c = c0 + y + i;
        if (c < DH_ && r0 + x < D_)
            dst[(size_t)c * D_ + r0 + x] = __float2half_rn(t[x][y + i]);
    }
}

template<typename Tin>
__global__ void transpose_k(const Tin* __restrict__ in, __half* __restrict__ out,
                            int R, int C, int ldi, int ldo,
                            int nz2, long sI1, long sI2, long sO1, long sO2)
{
    int z = blockIdx.z, z1 = z / nz2, z2 = z - z1 * nz2;
    in  += z1 * sI1 + z2 * sI2;
    out += z1 * sO1 + z2 * sO2;
    __shared__ float t[32][33];
    int c0 = blockIdx.x * 32, r0 = blockIdx.y * 32;
    int x = threadIdx.x, y = threadIdx.y;
    #pragma unroll
    for (int i = 0; i < 32; i += 8) {
        int r = r0 + y + i;
        if (r < R && c0 + x < C) t[y + i][x] = (float)in[(size_t)r * ldi + c0 + x];
    }
    __syncthreads();
    #pragma unroll
    for (int i = 0; i < 32; i += 8) {
        int c = c0 + y + i;
        if (c < C && r0 + x < R) out[(size_t)c * ldo + r0 + x] = __float2half_rn(t[x][y + i]);
    }
}

// ============ launch helpers ============
template<bool RELU, bool RESID, bool BIAS, bool HALF_OUT>
static void tc_gemm(const __half* A, const __half* B, const float* bias, const float* Cin, void* C,
                    int M, int N, int K, int lda, int ldb, int ldc, float alpha = 1.f)
{
    cudaFuncSetAttribute(gemm_h<RELU, RESID, BIAS, HALF_OUT>,
                         cudaFuncAttributeMaxDynamicSharedMemorySize, SMEMH);
    dim3 grid(cdiv(N, BN1), cdiv(M, BM1), 1);
    gemm_h<RELU, RESID, BIAS, HALF_OUT><<<grid, 128, SMEMH>>>(
        A, B, bias, Cin, C, M, N, K, lda, ldb, ldc, alpha);
}

template<typename Tin>
static void tr(const Tin* in, __half* out, int R, int C, int ldi, int ldo,
               int Z, int nz2, long sI1, long sI2, long sO1, long sO2)
{
    dim3 grid(cdiv(C, 32), cdiv(R, 32), Z);
    transpose_k<Tin><<<grid, dim3(32, 8)>>>(in, out, R, C, ldi, ldo, nz2, sI1, sI2, sO1, sO2);
}

// ============ orchestration ============
extern "C" void kernel_launch(void* const* d_in, const int* in_sizes, int n_in,
                              void* d_out, int out_size) {
    const int*   idx   = (const int*)  d_in[0];
    const float* emb   = (const float*)d_in[1];
    const float* cls_b = (const float*)d_in[2];
    const float* ln1_s = (const float*)d_in[3];
    const float* ln1_b = (const float*)d_in[4];
    const float* wq    = (const float*)d_in[5];
    const float* bq    = (const float*)d_in[6];
    const float* wk    = (const float*)d_in[7];
    const float* bk    = (const float*)d_in[8];
    const float* wv    = (const float*)d_in[9];
    const float* bv    = (const float*)d_in[10];
    const float* wo    = (const float*)d_in[11];
    const float* bo    = (const float*)d_in[12];
    const float* ln2_s = (const float*)d_in[13];
    const float* ln2_b = (const float*)d_in[14];
    const float* w1    = (const float*)d_in[15];
    const float* b1    = (const float*)d_in[16];
    const float* w2    = (const float*)d_in[17];
    const float* b2    = (const float*)d_in[18];
    const float* lnf_s = (const float*)d_in[19];
    const float* lnf_b = (const float*)d_in[20];
    float* out = (float*)d_out;

    float *gx, *gbq;
    __half *gh, *gqkv, *go, *gff, *gvT, *gwqkv, *gwoT, *gw1T, *gw2T, *gembr;
    cudaGetSymbolAddress((void**)&gx,   g_x);
    cudaGetSymbolAddress((void**)&gh,   g_h);
    cudaGetSymbolAddress((void**)&gqkv, g_qkv);
    cudaGetSymbolAddress((void**)&go,   g_o);
    cudaGetSymbolAddress((void**)&gff,  g_ff);
    cudaGetSymbolAddress((void**)&gvT,  g_vT);
    cudaGetSymbolAddress((void**)&gwqkv,g_wqkv);
    cudaGetSymbolAddress((void**)&gwoT, g_woT);
    cudaGetSymbolAddress((void**)&gw1T, g_w1T);
    cudaGetSymbolAddress((void**)&gw2T, g_w2T);
    cudaGetSymbolAddress((void**)&gbq,  g_bqkv);
    cudaGetSymbolAddress((void**)&gembr,g_embr);

    cudaFuncSetAttribute(attn_k, cudaFuncAttributeMaxDynamicSharedMemorySize, ATT_SMEM);

    embed_k<<<cdiv(BSZ_*D_, 256), 256>>>(idx, emb, bq, bk, bv);
    {
        dim3 grid(cdiv(DH_, 32), cdiv(D_, 32), 3 * NL_ * H_);
        qkvw_k<<<grid, dim3(32, 8)>>>(wq, wk, wv);
    }
    tr<float>(wo, gwoT, D_, D_, D_, D_, NL_, 1, (long)D_*D_, 0, (long)D_*D_, 0);
    tr<float>(w1, gw1T, D_, DFF_, DFF_, D_, NL_, 1, (long)D_*DFF_, 0, (long)DFF_*D_, 0);
    tr<float>(w2, gw2T, DFF_, D_, D_, DFF_, NL_, 1, (long)DFF_*D_, 0, (long)D_*DFF_, 0);
    roundcpy_k<<<cdiv(V_*D_, 256), 256>>>(emb, gembr, (size_t)V_*D_);

    const long sQ = (long)S_ * 3 * D_;

    for (int l = 0; l < NL_; l++) {
        ln_k<<<BSZ_, 256>>>(gx, gh, ln1_s + l*D_, ln1_b + l*D_);

        tc_gemm<false,false,true,true>(gh, gwqkv + (size_t)l*3*D_*D_, gbq + l*3*D_, nullptr, gqkv,
                                       BSZ_, 3*D_, D_, D_, D_, 3*D_);

        tr<__half>(gqkv + 2*D_, gvT, S_, DH_, 3*D_, S_, NB_*H_, H_,
                   sQ, DH_, (long)H_*DH_*S_, (long)DH_*S_);

        attn_k<<<NB_*H_*8, 128, ATT_SMEM>>>(gqkv, go);

        tc_gemm<false,true,true,false>(go, gwoT + (size_t)l*D_*D_, bo + l*D_, gx, gx,
                                       BSZ_, D_, D_, D_, D_, D_);

        ln_k<<<BSZ_, 256>>>(gx, gh, ln2_s + l*D_, ln2_b + l*D_);

        tc_gemm<true,false,true,true>(gh, gw1T + (size_t)l*DFF_*D_, b1 + l*DFF_, nullptr, gff,
                                      BSZ_, DFF_, D_, D_, D_, DFF_);
        tc_gemm<false,true,true,false>(gff, gw2T + (size_t)l*D_*DFF_, b2 + l*D_, gx, gx,
                                       BSZ_, D_, DFF_, DFF_, DFF_, D_);
    }

    ln_k<<<BSZ_, 256>>>(gx, gh, lnf_s, lnf_b);

    tc_gemm<false,false,true,false>(gh, gembr, cls_b, nullptr, out,
                                    BSZ_, V_, D_, D_, D_, V_);
}

// round 14
// speedup vs baseline: 2.5226x; 1.0031x over previous
#include <cuda_runtime.h>
#include <cuda_fp16.h>
#include <math.h>
#include <cstdint>

// ---------------- problem constants ----------------
#define D_   1024
#define H_   16
#define DH_  64
#define NL_  4
#define DFF_ 4096
#define V_   32000
#define S_   1024
#define NB_  2
#define BSZ_ (NB_*S_)

static inline int cdiv(int a, int b) { return (a + b - 1) / b; }

// ---------------- scratch ----------------
__device__ float  g_x   [BSZ_*D_];
__device__ __half g_h   [BSZ_*D_];
__device__ __half g_qkv [BSZ_*3*D_];
__device__ __half g_o   [BSZ_*D_];
__device__ __half g_ff  [BSZ_*DFF_];
__device__ __half g_wqkv[(size_t)NL_*3*D_*D_];
__device__ __half g_woT [(size_t)NL_*D_*D_];
__device__ __half g_w1T [(size_t)NL_*DFF_*D_];
__device__ __half g_w2T [(size_t)NL_*D_*DFF_];
__device__ float  g_bqkv[NL_*3*D_];
__device__ __half g_embr[(size_t)V_*D_];

// ---------------- helpers ----------------
__device__ __forceinline__ void mma16816(float* d, const uint32_t* a, const uint32_t* b) {
    asm volatile(
        "mma.sync.aligned.m16n8k16.row.col.f32.f16.f16.f32 "
        "{%0,%1,%2,%3}, {%4,%5,%6,%7}, {%8,%9}, {%0,%1,%2,%3};"
        : "+f"(d[0]), "+f"(d[1]), "+f"(d[2]), "+f"(d[3])
        : "r"(a[0]), "r"(a[1]), "r"(a[2]), "r"(a[3]), "r"(b[0]), "r"(b[1]));
}
__device__ __forceinline__ void ldsm4(uint32_t& r0, uint32_t& r1, uint32_t& r2, uint32_t& r3,
                                      uint32_t addr) {
    asm volatile("ldmatrix.sync.aligned.m8n8.x4.shared.b16 {%0,%1,%2,%3}, [%4];"
                 : "=r"(r0), "=r"(r1), "=r"(r2), "=r"(r3) : "r"(addr));
}
__device__ __forceinline__ void ldsm4t(uint32_t& r0, uint32_t& r1, uint32_t& r2, uint32_t& r3,
                                       uint32_t addr) {
    asm volatile("ldmatrix.sync.aligned.m8n8.x4.trans.shared.b16 {%0,%1,%2,%3}, [%4];"
                 : "=r"(r0), "=r"(r1), "=r"(r2), "=r"(r3) : "r"(addr));
}
__device__ __forceinline__ uint32_t smem_u32(const void* p) {
    uint32_t a;
    asm("{ .reg .u64 t; cvta.to.shared.u64 t, %1; cvt.u32.u64 %0, t; }" : "=r"(a) : "l"(p));
    return a;
}
__device__ __forceinline__ void cpa16(uint32_t dst, const void* src, bool pred) {
    int sz = pred ? 16 : 0;
    asm volatile("cp.async.cg.shared.global [%0], [%1], 16, %2;"
                 :: "r"(dst), "l"(src), "r"(sz) : "memory");
}
#define CPA_COMMIT() asm volatile("cp.async.commit_group;" ::: "memory")
#define CPA_WAIT1()  asm volatile("cp.async.wait_group 1;" ::: "memory")
#define CPA_WAIT0()  asm volatile("cp.async.wait_group 0;" ::: "memory")

// ============ fp16 mma GEMM: 128x128 tile, BK=32, 3-stage cp.async, ldmatrix ============
constexpr int BKH = 32, LDSH = 40, NSTAGE = 3;
constexpr int BM1 = 128, BN1 = 128;
constexpr int STGH  = 2 * BM1 * LDSH;
constexpr int SMEMH = NSTAGE * STGH * 2;         // 61,440 B -> 3 CTAs/SM

template<bool RELU, bool RESID, bool BIAS, bool HALF_OUT>
__global__ void __launch_bounds__(128) gemm_h(
    const __half* __restrict__ A, const __half* __restrict__ B,
    const float* __restrict__ biasg, const float* __restrict__ Cin,
    void* __restrict__ Cg,
    int M, int N, int K, int lda, int ldb, int ldc, float alpha)
{
    int row0 = blockIdx.y * BM1;
    int col0 = blockIdx.x * BN1;

    extern __shared__ __half smh[];
    uint32_t sm0 = smem_u32(smh);

    int tid = threadIdx.x;
    int wid = tid >> 5, lane = tid & 31;
    int wm = wid >> 1, wn = wid & 1;
    int gid = lane >> 2, tig = lane & 3;

    int cr = tid >> 2;
    int cc = (tid & 3) * 8;

    int arow = wm * 64 + (lane & 15);
    int acolh = (lane & 16) ? 8 : 0;
    uint32_t aBase[4];
    #pragma unroll
    for (int mt = 0; mt < 4; mt++)
        aBase[mt] = sm0 + ((arow + mt * 16) * LDSH + acolh) * 2;
    int brow = wn * 64 + ((lane & 16) ? 8 : 0) + (lane & 7);
    int bcolh = (lane & 8) ? 8 : 0;
    uint32_t bBase[4];
    #pragma unroll
    for (int p = 0; p < 4; p++)
        bBase[p] = sm0 + (BM1 * LDSH + (brow + p * 16) * LDSH + bcolh) * 2;

    float acc[4][8][4];
    #pragma unroll
    for (int a = 0; a < 4; a++)
        #pragma unroll
        for (int b = 0; b < 8; b++)
            #pragma unroll
            for (int c = 0; c < 4; c++) acc[a][b][c] = 0.f;

    int KT = K / BKH;

    auto issue = [&](int kt, int slot) {
        int k0 = kt * BKH;
        uint32_t abase = sm0 + (uint32_t)slot * STGH * 2;
        uint32_t bbase = abase + BM1 * LDSH * 2;
        #pragma unroll
        for (int i = 0; i < 4; i++) {
            int r = cr + i * 32;
            int gm = row0 + r;
            cpa16(abase + (r * LDSH + cc) * 2,
                  A + (size_t)(gm < M ? gm : 0) * lda + k0 + cc, gm < M);
            int gn = col0 + r;
            cpa16(bbase + (r * LDSH + cc) * 2,
                  B + (size_t)(gn < N ? gn : 0) * ldb + k0 + cc, gn < N);
        }
    };

    int nPre = KT < (NSTAGE - 1) ? KT : (NSTAGE - 1);
    for (int p = 0; p < nPre; p++) { issue(p, p); CPA_COMMIT(); }

    for (int kt = 0; kt < KT; kt++) {
        CPA_WAIT1();
        __syncthreads();
        int nxt = kt + NSTAGE - 1;
        if (nxt < KT) issue(nxt, nxt % NSTAGE);
        CPA_COMMIT();

        uint32_t stg = (uint32_t)(kt % NSTAGE) * STGH * 2;

        #pragma unroll
        for (int ks = 0; ks < 2; ks++) {
            uint32_t koff = stg + ks * 32;
            uint32_t af[4][4], bf[8][2];
            #pragma unroll
            for (int mt = 0; mt < 4; mt++)
                ldsm4(af[mt][0], af[mt][1], af[mt][2], af[mt][3], aBase[mt] + koff);
            #pragma unroll
            for (int p = 0; p < 4; p++)
                ldsm4(bf[2*p][0], bf[2*p][1], bf[2*p+1][0], bf[2*p+1][1], bBase[p] + koff);
            #pragma unroll
            for (int mt = 0; mt < 4; mt++)
                #pragma unroll
                for (int nt = 0; nt < 8; nt++)
                    mma16816(acc[mt][nt], af[mt], bf[nt]);
        }
    }

    #pragma unroll
    for (int mt = 0; mt < 4; mt++) {
        #pragma unroll
        for (int half = 0; half < 2; half++) {
            int gm = row0 + wm * 64 + mt * 16 + gid + half * 8;
            if (gm >= M) continue;
            #pragma unroll
            for (int nt = 0; nt < 8; nt++) {
                int gn = col0 + wn * 64 + nt * 8 + 2 * tig;
                if (gn >= N) continue;
                float v0 = acc[mt][nt][half * 2 + 0] * alpha;
                float v1 = acc[mt][nt][half * 2 + 1] * alpha;
                if (BIAS)  { v0 += biasg[gn]; v1 += biasg[gn + 1]; }
                if (RESID) {
                    const float* ci = Cin + (size_t)gm * ldc + gn;
                    v0 += ci[0]; v1 += ci[1];
                }
                if (RELU) { v0 = fmaxf(v0, 0.f); v1 = fmaxf(v1, 0.f); }
                if (HALF_OUT) {
                    __half* cp = (__half*)Cg + (size_t)gm * ldc + gn;
                    *(__half2*)cp = __halves2half2(__float2half_rn(v0), __float2half_rn(v1));
                } else {
                    float* cp = (float*)Cg + (size_t)gm * ldc + gn;
                    *(float2*)cp = make_float2(v0, v1);
                }
            }
        }
    }
}

// ============ fused flash attention (V loaded natively, ldmatrix.trans) ============
constexpr int FQ_LDH = 72, FV_LDH = 72, FP_LDH = 136;
constexpr int OFF_Q = 0;
constexpr int OFF_K = 128 * FQ_LDH;
constexpr int OFF_V = OFF_K + 128 * FQ_LDH;
constexpr int OFF_P = OFF_V + 128 * FV_LDH;
constexpr int ATT_SMEM = (OFF_P + 128 * FP_LDH) * 2;   // 90,112 B

__global__ void __launch_bounds__(128) attn_k(const __half* __restrict__ qkv,
                                              __half* __restrict__ og) {
    extern __shared__ __half smh[];
    __half* smP = smh + OFF_P;
    uint32_t sb = smem_u32(smh);

    int z  = blockIdx.x;
    int qb = z & 7, bh = z >> 3;
    int b  = bh >> 4, h = bh & 15;
    int row0 = qb * 128;
    const __half* qp = qkv + (size_t)b * S_ * 3 * D_ + (size_t)h * DH_;
    const __half* kp = qp + D_;
    const __half* vp = qp + 2 * D_;

    int tid = threadIdx.x, wid = tid >> 5, lane = tid & 31;
    int gid = lane >> 2, tig = lane & 3;
    int wr  = wid * 32;

    // ldmatrix base addresses
    int arow  = wr + (lane & 15);
    int acolh = (lane & 16) ? 8 : 0;
    uint32_t qBase[2], pBase[2];
    #pragma unroll
    for (int mt = 0; mt < 2; mt++) {
        qBase[mt] = sb + (OFF_Q + (arow + mt * 16) * FQ_LDH + acolh) * 2;
        pBase[mt] = sb + (OFF_P + (arow + mt * 16) * FP_LDH + acolh) * 2;
    }
    int brow  = ((lane & 16) ? 8 : 0) + (lane & 7);
    int bcolh = (lane & 8) ? 8 : 0;
    uint32_t kBase[8];
    #pragma unroll
    for (int p = 0; p < 8; p++)
        kBase[p] = sb + (OFF_K + (brow + p * 16) * FQ_LDH + bcolh) * 2;
    // V trans bases: rows = k(j), cols = n(e); x4 = (k0,n0),(k0+8,n0),(k0,n0+8),(k0+8,n0+8)
    int vkrow = ((lane & 8) ? 8 : 0) + (lane & 7);
    int vncol = (lane & 16) ? 8 : 0;
    uint32_t vBase[4];
    #pragma unroll
    for (int p = 0; p < 4; p++)
        vBase[p] = sb + (OFF_V + vkrow * FV_LDH + p * 16 + vncol) * 2;

    float oacc[2][8][4];
    #pragma unroll
    for (int mt = 0; mt < 2; mt++)
        #pragma unroll
        for (int nt = 0; nt < 8; nt++)
            #pragma unroll
            for (int d = 0; d < 4; d++) oacc[mt][nt][d] = 0.f;
    float mrow[2][2] = {{-1e30f, -1e30f}, {-1e30f, -1e30f}};
    float lrow[2][2] = {{0.f, 0.f}, {0.f, 0.f}};

    #pragma unroll
    for (int i = 0; i < 8; i++) {
        int t = tid + i * 128; int r = t >> 3, c = (t & 7) * 8;
        cpa16(sb + (OFF_Q + r * FQ_LDH + c) * 2, qp + (size_t)(row0 + r) * 3 * D_ + c, true);
    }
    CPA_COMMIT();
    #pragma unroll
    for (int i = 0; i < 8; i++) {
        int t = tid + i * 128; int r = t >> 3, c = (t & 7) * 8;
        cpa16(sb + (OFF_K + r * FQ_LDH + c) * 2, kp + (size_t)r * 3 * D_ + c, true);
    }
    CPA_COMMIT();

    int nch = qb + 1;
    for (int c = 0; c < nch; c++) {
        CPA_WAIT0();
        __syncthreads();
        // prefetch V chunk c directly (rows = tokens, 64 halves contiguous)
        #pragma unroll
        for (int i = 0; i < 8; i++) {
            int t = tid + i * 128; int r = t >> 3, cc = (t & 7) * 8;
            cpa16(sb + (OFF_V + r * FV_LDH + cc) * 2,
                  vp + (size_t)(c * 128 + r) * 3 * D_ + cc, true);
        }
        CPA_COMMIT();

        // ---- S = Q @ K^T ----
        float sacc[2][16][4];
        #pragma unroll
        for (int mt = 0; mt < 2; mt++)
            #pragma unroll
            for (int nt = 0; nt < 16; nt++)
                #pragma unroll
                for (int d = 0; d < 4; d++) sacc[mt][nt][d] = 0.f;
        #pragma unroll
        for (int ks = 0; ks < 4; ks++) {
            uint32_t koff = ks * 32;
            uint32_t af[2][4], bf[16][2];
            #pragma unroll
            for (int mt = 0; mt < 2; mt++)
                ldsm4(af[mt][0], af[mt][1], af[mt][2], af[mt][3], qBase[mt] + koff);
            #pragma unroll
            for (int p = 0; p < 8; p++)
                ldsm4(bf[2*p][0], bf[2*p][1], bf[2*p+1][0], bf[2*p+1][1], kBase[p] + koff);
            #pragma unroll
            for (int mt = 0; mt < 2; mt++)
                #pragma unroll
                for (int nt = 0; nt < 16; nt++)
                    mma16816(sacc[mt][nt], af[mt], bf[nt]);
        }

        // ---- scale + causal mask + online softmax ----
        bool diag = (c == qb);
        #pragma unroll
        for (int mt = 0; mt < 2; mt++) {
            #pragma unroll
            for (int half = 0; half < 2; half++) {
                int d0 = 2 * half;
                int ig = row0 + wr + 16 * mt + 8 * half + gid;
                float mx = -1e30f;
                #pragma unroll
                for (int nt = 0; nt < 16; nt++) {
                    float a = sacc[mt][nt][d0]     * 0.125f;
                    float e = sacc[mt][nt][d0 + 1] * 0.125f;
                    if (diag) {
                        int j = c * 128 + nt * 8 + 2 * tig;
                        if (j     > ig) a = -1e30f;
                        if (j + 1 > ig) e = -1e30f;
                    }
                    sacc[mt][nt][d0]     = a;
                    sacc[mt][nt][d0 + 1] = e;
                    mx = fmaxf(mx, fmaxf(a, e));
                }
                mx = fmaxf(mx, __shfl_xor_sync(0xffffffffu, mx, 1));
                mx = fmaxf(mx, __shfl_xor_sync(0xffffffffu, mx, 2));
                float mnew = fmaxf(mrow[mt][half], mx);
                float scl  = __expf(mrow[mt][half] - mnew);
                mrow[mt][half] = mnew;
                float ps = 0.f;
                int prow = wr + 16 * mt + 8 * half + gid;
                #pragma unroll
                for (int nt = 0; nt < 16; nt++) {
                    float p0 = __expf(sacc[mt][nt][d0]     - mnew);
                    float p1 = __expf(sacc[mt][nt][d0 + 1] - mnew);
                    ps += p0 + p1;
                    *(__half2*)&smP[prow * FP_LDH + nt * 8 + 2 * tig] =
                        __halves2half2(__float2half_rn(p0), __float2half_rn(p1));
                }
                ps += __shfl_xor_sync(0xffffffffu, ps, 1);
                ps += __shfl_xor_sync(0xffffffffu, ps, 2);
                lrow[mt][half] = lrow[mt][half] * scl + ps;
                #pragma unroll
                for (int nt = 0; nt < 8; nt++) {
                    oacc[mt][nt][d0]     *= scl;
                    oacc[mt][nt][d0 + 1] *= scl;
                }
            }
        }
        __syncwarp();

        CPA_WAIT0();
        __syncthreads();
        if (c + 1 < nch) {
            #pragma unroll
            for (int i = 0; i < 8; i++) {
                int t = tid + i * 128; int r = t >> 3, cc = (t & 7) * 8;
                cpa16(sb + (OFF_K + r * FQ_LDH + cc) * 2,
                      kp + (size_t)((c + 1) * 128 + r) * 3 * D_ + cc, true);
            }
            CPA_COMMIT();
        }

        // ---- O += P @ V  (V native, trans fragments) ----
        #pragma unroll
        for (int ks = 0; ks < 8; ks++) {
            uint32_t koff = ks * 16 * FV_LDH * 2;   // advance 16 j-rows
            uint32_t pkoff = ks * 32;
            uint32_t af[2][4], bf[8][2];
            #pragma unroll
            for (int mt = 0; mt < 2; mt++)
                ldsm4(af[mt][0], af[mt][1], af[mt][2], af[mt][3], pBase[mt] + pkoff);
            #pragma unroll
            for (int p = 0; p < 4; p++)
                ldsm4t(bf[2*p][0], bf[2*p][1], bf[2*p+1][0], bf[2*p+1][1], vBase[p] + koff);
            #pragma unroll
            for (int mt = 0; mt < 2; mt++)
                #pragma unroll
                for (int nt = 0; nt < 8; nt++)
                    mma16816(oacc[mt][nt], af[mt], bf[nt]);
        }
    }

    #pragma unroll
    for (int mt = 0; mt < 2; mt++) {
        #pragma unroll
        for (int half = 0; half < 2; half++) {
            float inv = 1.f / lrow[mt][half];
            int rg = row0 + wr + 16 * mt + 8 * half + gid;
            __half* orow = og + ((size_t)b * S_ + rg) * D_ + h * DH_;
            #pragma unroll
            for (int nt = 0; nt < 8; nt++) {
                float p0 = oacc[mt][nt][2 * half]     * inv;
                float p1 = oacc[mt][nt][2 * half + 1] * inv;
                *(__half2*)&orow[nt * 8 + 2 * tig] =
                    __halves2half2(__float2half_rn(p0), __float2half_rn(p1));
            }
        }
    }
}

// ============ auxiliary kernels ============
__global__ void embed_k(const int* __restrict__ idx, const float* __restrict__ emb,
                        const float* __restrict__ bq, const float* __restrict__ bk,
                        const float* __restrict__ bv) {
    int t = blockIdx.x * blockDim.x + threadIdx.x;
    if (t < NL_ * 3 * D_) {
        int l = t / (3 * D_), r = t - l * 3 * D_;
        float v = (r < D_) ? bq[l * D_ + r] : (r < 2 * D_) ? bk[l * D_ + r - D_] : bv[l * D_ + r - 2 * D_];
        g_bqkv[t] = v;
    }
    if (t >= BSZ_ * D_) return;
    int d = t & (D_ - 1);
    int bs = t >> 10;
    int s = bs & (S_ - 1);
    int tok = idx[bs];
    int i2 = d & ~1;
    float freq = __expf((float)i2 * (-9.210340371976184f / (float)D_));
    float ang = (float)s * freq;
    float pe = (d & 1) ? cosf(ang) : sinf(ang);
    g_x[t] = emb[(size_t)tok * D_ + d] * 32.0f + pe;
}

__global__ void roundcpy_k(const float* __restrict__ in, __half* __restrict__ out, size_t n) {
    size_t i = (size_t)blockIdx.x * blockDim.x + threadIdx.x;
    if (i < n) out[i] = __float2half_rn(in[i]);
}

__global__ void ln_k(const float* __restrict__ in, __half* __restrict__ out,
                     const float* __restrict__ sc, const float* __restrict__ bi) {
    int row = blockIdx.x;
    const float* x = in + (size_t)row * D_;
    int tid = threadIdx.x;
    float s = 0.f, ss = 0.f;
    for (int i = tid; i < D_; i += 256) { float v = x[i]; s += v; ss = fmaf(v, v, ss); }
    __shared__ float rs[8], rq[8];
    #pragma unroll
    for (int o = 16; o > 0; o >>= 1) {
        s  += __shfl_xor_sync(0xffffffffu, s,  o);
        ss += __shfl_xor_sync(0xffffffffu, ss, o);
    }
    if ((tid & 31) == 0) { rs[tid >> 5] = s; rq[tid >> 5] = ss; }
    __syncthreads();
    if (tid < 32) {
        float a = (tid < 8) ? rs[tid] : 0.f;
        float b = (tid < 8) ? rq[tid] : 0.f;
        #pragma unroll
        for (int o = 4; o > 0; o >>= 1) {
            a += __shfl_xor_sync(0xffffffffu, a, o);
            b += __shfl_xor_sync(0xffffffffu, b, o);
        }
        if (tid == 0) { rs[0] = a; rq[0] = b; }
    }
    __syncthreads();
    float mean = rs[0] * (1.0f / D_);
    float var  = rq[0] * (1.0f / D_) - mean * mean;
    float inv  = rsqrtf(var + 1e-5f);
    for (int i = tid; i < D_; i += 256)
        out[(size_t)row * D_ + i] = __float2half_rn((x[i] - mean) * inv * sc[i] + bi[i]);
}

// merged QKV weight repack
__global__ void qkvw_k(const float* __restrict__ wq, const float* __restrict__ wk,
                       const float* __restrict__ wv) {
    int z = blockIdx.z;
    int sel = z / (NL_ * H_);
    int lh  = z - sel * (NL_ * H_);
    int l = lh / H_, h = lh - l * H_;
    const float* src = (sel == 0 ? wq : sel == 1 ? wk : wv) + ((size_t)(l * H_ + h)) * D_ * DH_;
    __half* dst = g_wqkv + (size_t)l * 3 * D_ * D_ + (size_t)sel * D_ * D_ + (size_t)h * DH_ * D_;
    __shared__ float t[32][33];
    int c0 = blockIdx.x * 32, r0 = blockIdx.y * 32;
    int x = threadIdx.x, y = threadIdx.y;
    #pragma unroll
    for (int i = 0; i < 32; i += 8) {
        int r = r0 + y + i;
        if (r < D_ && c0 + x < DH_) t[y + i][x] = src[(size_t)r * DH_ + c0 + x];
    }
    __syncthreads();
    #pragma unroll
    for (int i = 0; i < 32; i += 8) {
        int c = c0 + y + i;
        if (c < DH_ && r0 + x < D_)
            dst[(size_t)c * D_ + r0 + x] = __float2half_rn(t[x][y + i]);
    }
}

template<typename Tin>
__global__ void transpose_k(const Tin* __restrict__ in, __half* __restrict__ out,
                            int R, int C, int ldi, int ldo,
                            int nz2, long sI1, long sI2, long sO1, long sO2)
{
    int z = blockIdx.z, z1 = z / nz2, z2 = z - z1 * nz2;
    in  += z1 * sI1 + z2 * sI2;
    out += z1 * sO1 + z2 * sO2;
    __shared__ float t[32][33];
    int c0 = blockIdx.x * 32, r0 = blockIdx.y * 32;
    int x = threadIdx.x, y = threadIdx.y;
    #pragma unroll
    for (int i = 0; i < 32; i += 8) {
        int r = r0 + y + i;
        if (r < R && c0 + x < C) t[y + i][x] = (float)in[(size_t)r * ldi + c0 + x];
    }
    __syncthreads();
    #pragma unroll
    for (int i = 0; i < 32; i += 8) {
        int c = c0 + y + i;
        if (c < C && r0 + x < R) out[(size_t)c * ldo + r0 + x] = __float2half_rn(t[x][y + i]);
    }
}

// ============ launch helpers ============
template<bool RELU, bool RESID, bool BIAS, bool HALF_OUT>
static void tc_gemm(const __half* A, const __half* B, const float* bias, const float* Cin, void* C,
                    int M, int N, int K, int lda, int ldb, int ldc, float alpha = 1.f)
{
    cudaFuncSetAttribute(gemm_h<RELU, RESID, BIAS, HALF_OUT>,
                         cudaFuncAttributeMaxDynamicSharedMemorySize, SMEMH);
    dim3 grid(cdiv(N, BN1), cdiv(M, BM1), 1);
    gemm_h<RELU, RESID, BIAS, HALF_OUT><<<grid, 128, SMEMH>>>(
        A, B, bias, Cin, C, M, N, K, lda, ldb, ldc, alpha);
}

template<typename Tin>
static void tr(const Tin* in, __half* out, int R, int C, int ldi, int ldo,
               int Z, int nz2, long sI1, long sI2, long sO1, long sO2)
{
    dim3 grid(cdiv(C, 32), cdiv(R, 32), Z);
    transpose_k<Tin><<<grid, dim3(32, 8)>>>(in, out, R, C, ldi, ldo, nz2, sI1, sI2, sO1, sO2);
}

// ============ orchestration ============
extern "C" void kernel_launch(void* const* d_in, const int* in_sizes, int n_in,
                              void* d_out, int out_size) {
    const int*   idx   = (const int*)  d_in[0];
    const float* emb   = (const float*)d_in[1];
    const float* cls_b = (const float*)d_in[2];
    const float* ln1_s = (const float*)d_in[3];
    const float* ln1_b = (const float*)d_in[4];
    const float* wq    = (const float*)d_in[5];
    const float* bq    = (const float*)d_in[6];
    const float* wk    = (const float*)d_in[7];
    const float* bk    = (const float*)d_in[8];
    const float* wv    = (const float*)d_in[9];
    const float* bv    = (const float*)d_in[10];
    const float* wo    = (const float*)d_in[11];
    const float* bo    = (const float*)d_in[12];
    const float* ln2_s = (const float*)d_in[13];
    const float* ln2_b = (const float*)d_in[14];
    const float* w1    = (const float*)d_in[15];
    const float* b1    = (const float*)d_in[16];
    const float* w2    = (const float*)d_in[17];
    const float* b2    = (const float*)d_in[18];
    const float* lnf_s = (const float*)d_in[19];
    const float* lnf_b = (const float*)d_in[20];
    float* out = (float*)d_out;

    float *gx, *gbq;
    __half *gh, *gqkv, *go, *gff, *gwqkv, *gwoT, *gw1T, *gw2T, *gembr;
    cudaGetSymbolAddress((void**)&gx,   g_x);
    cudaGetSymbolAddress((void**)&gh,   g_h);
    cudaGetSymbolAddress((void**)&gqkv, g_qkv);
    cudaGetSymbolAddress((void**)&go,   g_o);
    cudaGetSymbolAddress((void**)&gff,  g_ff);
    cudaGetSymbolAddress((void**)&gwqkv,g_wqkv);
    cudaGetSymbolAddress((void**)&gwoT, g_woT);
    cudaGetSymbolAddress((void**)&gw1T, g_w1T);
    cudaGetSymbolAddress((void**)&gw2T, g_w2T);
    cudaGetSymbolAddress((void**)&gbq,  g_bqkv);
    cudaGetSymbolAddress((void**)&gembr,g_embr);

    cudaFuncSetAttribute(attn_k, cudaFuncAttributeMaxDynamicSharedMemorySize, ATT_SMEM);

    embed_k<<<cdiv(BSZ_*D_, 256), 256>>>(idx, emb, bq, bk, bv);
    {
        dim3 grid(cdiv(DH_, 32), cdiv(D_, 32), 3 * NL_ * H_);
        qkvw_k<<<grid, dim3(32, 8)>>>(wq, wk, wv);
    }
    tr<float>(wo, gwoT, D_, D_, D_, D_, NL_, 1, (long)D_*D_, 0, (long)D_*D_, 0);
    tr<float>(w1, gw1T, D_, DFF_, DFF_, D_, NL_, 1, (long)D_*DFF_, 0, (long)DFF_*D_, 0);
    tr<float>(w2, gw2T, DFF_, D_, D_, DFF_, NL_, 1, (long)DFF_*D_, 0, (long)D_*DFF_, 0);
    roundcpy_k<<<cdiv(V_*D_, 256), 256>>>(emb, gembr, (size_t)V_*D_);

    for (int l = 0; l < NL_; l++) {
        ln_k<<<BSZ_, 256>>>(gx, gh, ln1_s + l*D_, ln1_b + l*D_);

        tc_gemm<false,false,true,true>(gh, gwqkv + (size_t)l*3*D_*D_, gbq + l*3*D_, nullptr, gqkv,
                                       BSZ_, 3*D_, D_, D_, D_, 3*D_);

        attn_k<<<NB_*H_*8, 128, ATT_SMEM>>>(gqkv, go);

        tc_gemm<false,true,true,false>(go, gwoT + (size_t)l*D_*D_, bo + l*D_, gx, gx,
                                       BSZ_, D_, D_, D_, D_, D_);

        ln_k<<<BSZ_, 256>>>(gx, gh, ln2_s + l*D_, ln2_b + l*D_);

        tc_gemm<true,false,true,true>(gh, gw1T + (size_t)l*DFF_*D_, b1 + l*DFF_, nullptr, gff,
                                      BSZ_, DFF_, D_, D_, D_, DFF_);
        tc_gemm<false,true,true,false>(gff, gw2T + (size_t)l*D_*DFF_, b2 + l*D_, gx, gx,
                                       BSZ_, D_, DFF_, DFF_, DFF_, D_);
    }

    ln_k<<<BSZ_, 256>>>(gx, gh, lnf_s, lnf_b);

    tc_gemm<false,false,true,false>(gh, gembr, cls_b, nullptr, out,
                                    BSZ_, V_, D_, D_, D_, V_);
}

// round 15
// speedup vs baseline: 2.6620x; 1.0552x over previous
#include <cuda_runtime.h>
#include <cuda_fp16.h>
#include <math.h>
#include <cstdint>

// ---------------- problem constants ----------------
#define D_   1024
#define H_   16
#define DH_  64
#define NL_  4
#define DFF_ 4096
#define V_   32000
#define S_   1024
#define NB_  2
#define BSZ_ (NB_*S_)

static inline int cdiv(int a, int b) { return (a + b - 1) / b; }

// ---------------- scratch ----------------
__device__ float  g_x   [BSZ_*D_];
__device__ __half g_h   [BSZ_*D_];
__device__ __half g_qkv [BSZ_*3*D_];
__device__ __half g_o   [BSZ_*D_];
__device__ __half g_ff  [BSZ_*DFF_];
__device__ __half g_wqkv[(size_t)NL_*3*D_*D_];
__device__ __half g_woT [(size_t)NL_*D_*D_];
__device__ __half g_w1T [(size_t)NL_*DFF_*D_];
__device__ __half g_w2T [(size_t)NL_*D_*DFF_];
__device__ float  g_bqkv[NL_*3*D_];
__device__ __half g_embr[(size_t)V_*D_];

// ---------------- helpers ----------------
__device__ __forceinline__ void mma16816(float* d, const uint32_t* a, const uint32_t* b) {
    asm volatile(
        "mma.sync.aligned.m16n8k16.row.col.f32.f16.f16.f32 "
        "{%0,%1,%2,%3}, {%4,%5,%6,%7}, {%8,%9}, {%0,%1,%2,%3};"
        : "+f"(d[0]), "+f"(d[1]), "+f"(d[2]), "+f"(d[3])
        : "r"(a[0]), "r"(a[1]), "r"(a[2]), "r"(a[3]), "r"(b[0]), "r"(b[1]));
}
__device__ __forceinline__ void ldsm4(uint32_t& r0, uint32_t& r1, uint32_t& r2, uint32_t& r3,
                                      uint32_t addr) {
    asm volatile("ldmatrix.sync.aligned.m8n8.x4.shared.b16 {%0,%1,%2,%3}, [%4];"
                 : "=r"(r0), "=r"(r1), "=r"(r2), "=r"(r3) : "r"(addr));
}
__device__ __forceinline__ void ldsm4t(uint32_t& r0, uint32_t& r1, uint32_t& r2, uint32_t& r3,
                                       uint32_t addr) {
    asm volatile("ldmatrix.sync.aligned.m8n8.x4.trans.shared.b16 {%0,%1,%2,%3}, [%4];"
                 : "=r"(r0), "=r"(r1), "=r"(r2), "=r"(r3) : "r"(addr));
}
__device__ __forceinline__ uint32_t smem_u32(const void* p) {
    uint32_t a;
    asm("{ .reg .u64 t; cvta.to.shared.u64 t, %1; cvt.u32.u64 %0, t; }" : "=r"(a) : "l"(p));
    return a;
}
__device__ __forceinline__ void cpa16(uint32_t dst, const void* src, bool pred) {
    int sz = pred ? 16 : 0;
    asm volatile("cp.async.cg.shared.global [%0], [%1], 16, %2;"
                 :: "r"(dst), "l"(src), "r"(sz) : "memory");
}
#define CPA_COMMIT() asm volatile("cp.async.commit_group;" ::: "memory")
#define CPA_WAIT1()  asm volatile("cp.async.wait_group 1;" ::: "memory")
#define CPA_WAIT0()  asm volatile("cp.async.wait_group 0;" ::: "memory")

// ============ fp16 mma GEMM: 128x128 tile, BK=32, 3-stage cp.async, ldmatrix ============
constexpr int BKH = 32, LDSH = 40, NSTAGE = 3;
constexpr int BM1 = 128, BN1 = 128;
constexpr int STGH  = 2 * BM1 * LDSH;
constexpr int SMEMH = NSTAGE * STGH * 2;         // 61,440 B -> 3 CTAs/SM

// SPLITK: grid.z splits K; partials atomicAdd'ed into fp32 C (which pre-holds residual);
//         bias added by split z==0 only. RESID/RELU/HALF_OUT unused in SPLITK mode.
template<bool RELU, bool RESID, bool BIAS, bool HALF_OUT, bool SPLITK>
__global__ void __launch_bounds__(128) gemm_h(
    const __half* __restrict__ A, const __half* __restrict__ B,
    const float* __restrict__ biasg, const float* __restrict__ Cin,
    void* __restrict__ Cg,
    int M, int N, int K, int lda, int ldb, int ldc, float alpha)
{
    int row0 = blockIdx.y * BM1;
    int col0 = blockIdx.x * BN1;

    extern __shared__ __half smh[];
    uint32_t sm0 = smem_u32(smh);

    int tid = threadIdx.x;
    int wid = tid >> 5, lane = tid & 31;
    int wm = wid >> 1, wn = wid & 1;
    int gid = lane >> 2, tig = lane & 3;

    int cr = tid >> 2;
    int cc = (tid & 3) * 8;

    int arow = wm * 64 + (lane & 15);
    int acolh = (lane & 16) ? 8 : 0;
    uint32_t aBase[4];
    #pragma unroll
    for (int mt = 0; mt < 4; mt++)
        aBase[mt] = sm0 + ((arow + mt * 16) * LDSH + acolh) * 2;
    int brow = wn * 64 + ((lane & 16) ? 8 : 0) + (lane & 7);
    int bcolh = (lane & 8) ? 8 : 0;
    uint32_t bBase[4];
    #pragma unroll
    for (int p = 0; p < 4; p++)
        bBase[p] = sm0 + (BM1 * LDSH + (brow + p * 16) * LDSH + bcolh) * 2;

    float acc[4][8][4];
    #pragma unroll
    for (int a = 0; a < 4; a++)
        #pragma unroll
        for (int b = 0; b < 8; b++)
            #pragma unroll
            for (int c = 0; c < 4; c++) acc[a][b][c] = 0.f;

    int KTall = K / BKH;
    int kt0 = 0, kt1 = KTall;
    if (SPLITK) {
        int nz = gridDim.z, z = blockIdx.z;
        kt0 = (KTall * z) / nz;
        kt1 = (KTall * (z + 1)) / nz;
    }
    int nKT = kt1 - kt0;

    auto issue = [&](int kt, int slot) {
        int k0 = kt * BKH;
        uint32_t abase = sm0 + (uint32_t)slot * STGH * 2;
        uint32_t bbase = abase + BM1 * LDSH * 2;
        #pragma unroll
        for (int i = 0; i < 4; i++) {
            int r = cr + i * 32;
            int gm = row0 + r;
            cpa16(abase + (r * LDSH + cc) * 2,
                  A + (size_t)(gm < M ? gm : 0) * lda + k0 + cc, gm < M);
            int gn = col0 + r;
            cpa16(bbase + (r * LDSH + cc) * 2,
                  B + (size_t)(gn < N ? gn : 0) * ldb + k0 + cc, gn < N);
        }
    };

    int nPre = nKT < (NSTAGE - 1) ? nKT : (NSTAGE - 1);
    for (int p = 0; p < nPre; p++) { issue(kt0 + p, p); CPA_COMMIT(); }

    for (int ktl = 0; ktl < nKT; ktl++) {
        CPA_WAIT1();
        __syncthreads();
        int nxt = ktl + NSTAGE - 1;
        if (nxt < nKT) issue(kt0 + nxt, nxt % NSTAGE);
        CPA_COMMIT();

        uint32_t stg = (uint32_t)(ktl % NSTAGE) * STGH * 2;

        #pragma unroll
        for (int ks = 0; ks < 2; ks++) {
            uint32_t koff = stg + ks * 32;
            uint32_t af[4][4], bf[8][2];
            #pragma unroll
            for (int mt = 0; mt < 4; mt++)
                ldsm4(af[mt][0], af[mt][1], af[mt][2], af[mt][3], aBase[mt] + koff);
            #pragma unroll
            for (int p = 0; p < 4; p++)
                ldsm4(bf[2*p][0], bf[2*p][1], bf[2*p+1][0], bf[2*p+1][1], bBase[p] + koff);
            #pragma unroll
            for (int mt = 0; mt < 4; mt++)
                #pragma unroll
                for (int nt = 0; nt < 8; nt++)
                    mma16816(acc[mt][nt], af[mt], bf[nt]);
        }
    }

    bool addb = !SPLITK || blockIdx.z == 0;
    #pragma unroll
    for (int mt = 0; mt < 4; mt++) {
        #pragma unroll
        for (int half = 0; half < 2; half++) {
            int gm = row0 + wm * 64 + mt * 16 + gid + half * 8;
            if (gm >= M) continue;
            #pragma unroll
            for (int nt = 0; nt < 8; nt++) {
                int gn = col0 + wn * 64 + nt * 8 + 2 * tig;
                if (gn >= N) continue;
                float v0 = acc[mt][nt][half * 2 + 0] * alpha;
                float v1 = acc[mt][nt][half * 2 + 1] * alpha;
                if (SPLITK) {
                    if (addb && BIAS) { v0 += biasg[gn]; v1 += biasg[gn + 1]; }
                    float* cp = (float*)Cg + (size_t)gm * ldc + gn;
                    atomicAdd(cp, v0);
                    atomicAdd(cp + 1, v1);
                } else {
                    if (BIAS)  { v0 += biasg[gn]; v1 += biasg[gn + 1]; }
                    if (RESID) {
                        const float* ci = Cin + (size_t)gm * ldc + gn;
                        v0 += ci[0]; v1 += ci[1];
                    }
                    if (RELU) { v0 = fmaxf(v0, 0.f); v1 = fmaxf(v1, 0.f); }
                    if (HALF_OUT) {
                        __half* cp = (__half*)Cg + (size_t)gm * ldc + gn;
                        *(__half2*)cp = __halves2half2(__float2half_rn(v0), __float2half_rn(v1));
                    } else {
                        float* cp = (float*)Cg + (size_t)gm * ldc + gn;
                        *(float2*)cp = make_float2(v0, v1);
                    }
                }
            }
        }
    }
}

// ============ fused flash attention (V native, ldmatrix.trans) ============
constexpr int FQ_LDH = 72, FV_LDH = 72, FP_LDH = 136;
constexpr int OFF_Q = 0;
constexpr int OFF_K = 128 * FQ_LDH;
constexpr int OFF_V = OFF_K + 128 * FQ_LDH;
constexpr int OFF_P = OFF_V + 128 * FV_LDH;
constexpr int ATT_SMEM = (OFF_P + 128 * FP_LDH) * 2;   // 90,112 B

__global__ void __launch_bounds__(128) attn_k(const __half* __restrict__ qkv,
                                              __half* __restrict__ og) {
    extern __shared__ __half smh[];
    __half* smP = smh + OFF_P;
    uint32_t sb = smem_u32(smh);

    int z  = blockIdx.x;
    int qb = z & 7, bh = z >> 3;
    int b  = bh >> 4, h = bh & 15;
    int row0 = qb * 128;
    const __half* qp = qkv + (size_t)b * S_ * 3 * D_ + (size_t)h * DH_;
    const __half* kp = qp + D_;
    const __half* vp = qp + 2 * D_;

    int tid = threadIdx.x, wid = tid >> 5, lane = tid & 31;
    int gid = lane >> 2, tig = lane & 3;
    int wr  = wid * 32;

    int arow  = wr + (lane & 15);
    int acolh = (lane & 16) ? 8 : 0;
    uint32_t qBase[2], pBase[2];
    #pragma unroll
    for (int mt = 0; mt < 2; mt++) {
        qBase[mt] = sb + (OFF_Q + (arow + mt * 16) * FQ_LDH + acolh) * 2;
        pBase[mt] = sb + (OFF_P + (arow + mt * 16) * FP_LDH + acolh) * 2;
    }
    int brow  = ((lane & 16) ? 8 : 0) + (lane & 7);
    int bcolh = (lane & 8) ? 8 : 0;
    uint32_t kBase[8];
    #pragma unroll
    for (int p = 0; p < 8; p++)
        kBase[p] = sb + (OFF_K + (brow + p * 16) * FQ_LDH + bcolh) * 2;
    int vkrow = ((lane & 8) ? 8 : 0) + (lane & 7);
    int vncol = (lane & 16) ? 8 : 0;
    uint32_t vBase[4];
    #pragma unroll
    for (int p = 0; p < 4; p++)
        vBase[p] = sb + (OFF_V + vkrow * FV_LDH + p * 16 + vncol) * 2;

    float oacc[2][8][4];
    #pragma unroll
    for (int mt = 0; mt < 2; mt++)
        #pragma unroll
        for (int nt = 0; nt < 8; nt++)
            #pragma unroll
            for (int d = 0; d < 4; d++) oacc[mt][nt][d] = 0.f;
    float mrow[2][2] = {{-1e30f, -1e30f}, {-1e30f, -1e30f}};
    float lrow[2][2] = {{0.f, 0.f}, {0.f, 0.f}};

    #pragma unroll
    for (int i = 0; i < 8; i++) {
        int t = tid + i * 128; int r = t >> 3, c = (t & 7) * 8;
        cpa16(sb + (OFF_Q + r * FQ_LDH + c) * 2, qp + (size_t)(row0 + r) * 3 * D_ + c, true);
    }
    CPA_COMMIT();
    #pragma unroll
    for (int i = 0; i < 8; i++) {
        int t = tid + i * 128; int r = t >> 3, c = (t & 7) * 8;
        cpa16(sb + (OFF_K + r * FQ_LDH + c) * 2, kp + (size_t)r * 3 * D_ + c, true);
    }
    CPA_COMMIT();

    int nch = qb + 1;
    for (int c = 0; c < nch; c++) {
        CPA_WAIT0();
        __syncthreads();
        #pragma unroll
        for (int i = 0; i < 8; i++) {
            int t = tid + i * 128; int r = t >> 3, cc = (t & 7) * 8;
            cpa16(sb + (OFF_V + r * FV_LDH + cc) * 2,
                  vp + (size_t)(c * 128 + r) * 3 * D_ + cc, true);
        }
        CPA_COMMIT();

        float sacc[2][16][4];
        #pragma unroll
        for (int mt = 0; mt < 2; mt++)
            #pragma unroll
            for (int nt = 0; nt < 16; nt++)
                #pragma unroll
                for (int d = 0; d < 4; d++) sacc[mt][nt][d] = 0.f;
        #pragma unroll
        for (int ks = 0; ks < 4; ks++) {
            uint32_t koff = ks * 32;
            uint32_t af[2][4], bf[16][2];
            #pragma unroll
            for (int mt = 0; mt < 2; mt++)
                ldsm4(af[mt][0], af[mt][1], af[mt][2], af[mt][3], qBase[mt] + koff);
            #pragma unroll
            for (int p = 0; p < 8; p++)
                ldsm4(bf[2*p][0], bf[2*p][1], bf[2*p+1][0], bf[2*p+1][1], kBase[p] + koff);
            #pragma unroll
            for (int mt = 0; mt < 2; mt++)
                #pragma unroll
                for (int nt = 0; nt < 16; nt++)
                    mma16816(sacc[mt][nt], af[mt], bf[nt]);
        }

        bool diag = (c == qb);
        #pragma unroll
        for (int mt = 0; mt < 2; mt++) {
            #pragma unroll
            for (int half = 0; half < 2; half++) {
                int d0 = 2 * half;
                int ig = row0 + wr + 16 * mt + 8 * half + gid;
                float mx = -1e30f;
                #pragma unroll
                for (int nt = 0; nt < 16; nt++) {
                    float a = sacc[mt][nt][d0]     * 0.125f;
                    float e = sacc[mt][nt][d0 + 1] * 0.125f;
                    if (diag) {
                        int j = c * 128 + nt * 8 + 2 * tig;
                        if (j     > ig) a = -1e30f;
                        if (j + 1 > ig) e = -1e30f;
                    }
                    sacc[mt][nt][d0]     = a;
                    sacc[mt][nt][d0 + 1] = e;
                    mx = fmaxf(mx, fmaxf(a, e));
                }
                mx = fmaxf(mx, __shfl_xor_sync(0xffffffffu, mx, 1));
                mx = fmaxf(mx, __shfl_xor_sync(0xffffffffu, mx, 2));
                float mnew = fmaxf(mrow[mt][half], mx);
                float scl  = __expf(mrow[mt][half] - mnew);
                mrow[mt][half] = mnew;
                float ps = 0.f;
                int prow = wr + 16 * mt + 8 * half + gid;
                #pragma unroll
                for (int nt = 0; nt < 16; nt++) {
                    float p0 = __expf(sacc[mt][nt][d0]     - mnew);
                    float p1 = __expf(sacc[mt][nt][d0 + 1] - mnew);
                    ps += p0 + p1;
                    *(__half2*)&smP[prow * FP_LDH + nt * 8 + 2 * tig] =
                        __halves2half2(__float2half_rn(p0), __float2half_rn(p1));
                }
                ps += __shfl_xor_sync(0xffffffffu, ps, 1);
                ps += __shfl_xor_sync(0xffffffffu, ps, 2);
                lrow[mt][half] = lrow[mt][half] * scl + ps;
                #pragma unroll
                for (int nt = 0; nt < 8; nt++) {
                    oacc[mt][nt][d0]     *= scl;
                    oacc[mt][nt][d0 + 1] *= scl;
                }
            }
        }
        __syncwarp();

        CPA_WAIT0();
        __syncthreads();
        if (c + 1 < nch) {
            #pragma unroll
            for (int i = 0; i < 8; i++) {
                int t = tid + i * 128; int r = t >> 3, cc = (t & 7) * 8;
                cpa16(sb + (OFF_K + r * FQ_LDH + cc) * 2,
                      kp + (size_t)((c + 1) * 128 + r) * 3 * D_ + cc, true);
            }
            CPA_COMMIT();
        }

        #pragma unroll
        for (int ks = 0; ks < 8; ks++) {
            uint32_t koff = ks * 16 * FV_LDH * 2;
            uint32_t pkoff = ks * 32;
            uint32_t af[2][4], bf[8][2];
            #pragma unroll
            for (int mt = 0; mt < 2; mt++)
                ldsm4(af[mt][0], af[mt][1], af[mt][2], af[mt][3], pBase[mt] + pkoff);
            #pragma unroll
            for (int p = 0; p < 4; p++)
                ldsm4t(bf[2*p][0], bf[2*p][1], bf[2*p+1][0], bf[2*p+1][1], vBase[p] + koff);
            #pragma unroll
            for (int mt = 0; mt < 2; mt++)
                #pragma unroll
                for (int nt = 0; nt < 8; nt++)
                    mma16816(oacc[mt][nt], af[mt], bf[nt]);
        }
    }

    #pragma unroll
    for (int mt = 0; mt < 2; mt++) {
        #pragma unroll
        for (int half = 0; half < 2; half++) {
            float inv = 1.f / lrow[mt][half];
            int rg = row0 + wr + 16 * mt + 8 * half + gid;
            __half* orow = og + ((size_t)b * S_ + rg) * D_ + h * DH_;
            #pragma unroll
            for (int nt = 0; nt < 8; nt++) {
                float p0 = oacc[mt][nt][2 * half]     * inv;
                float p1 = oacc[mt][nt][2 * half + 1] * inv;
                *(__half2*)&orow[nt * 8 + 2 * tig] =
                    __halves2half2(__float2half_rn(p0), __float2half_rn(p1));
            }
        }
    }
}

// ============ auxiliary kernels ============
__global__ void embed_k(const int* __restrict__ idx, const float* __restrict__ emb,
                        const float* __restrict__ bq, const float* __restrict__ bk,
                        const float* __restrict__ bv) {
    int t = blockIdx.x * blockDim.x + threadIdx.x;
    if (t < NL_ * 3 * D_) {
        int l = t / (3 * D_), r = t - l * 3 * D_;
        float v = (r < D_) ? bq[l * D_ + r] : (r < 2 * D_) ? bk[l * D_ + r - D_] : bv[l * D_ + r - 2 * D_];
        g_bqkv[t] = v;
    }
    if (t >= BSZ_ * D_) return;
    int d = t & (D_ - 1);
    int bs = t >> 10;
    int s = bs & (S_ - 1);
    int tok = idx[bs];
    int i2 = d & ~1;
    float freq = __expf((float)i2 * (-9.210340371976184f / (float)D_));
    float ang = (float)s * freq;
    float pe = (d & 1) ? cosf(ang) : sinf(ang);
    g_x[t] = emb[(size_t)tok * D_ + d] * 32.0f + pe;
}

__global__ void roundcpy_k(const float* __restrict__ in, __half* __restrict__ out, size_t n) {
    size_t i = (size_t)blockIdx.x * blockDim.x + threadIdx.x;
    if (i < n) out[i] = __float2half_rn(in[i]);
}

__global__ void ln_k(const float* __restrict__ in, __half* __restrict__ out,
                     const float* __restrict__ sc, const float* __restrict__ bi) {
    int row = blockIdx.x;
    const float* x = in + (size_t)row * D_;
    int tid = threadIdx.x;
    float s = 0.f, ss = 0.f;
    for (int i = tid; i < D_; i += 256) { float v = x[i]; s += v; ss = fmaf(v, v, ss); }
    __shared__ float rs[8], rq[8];
    #pragma unroll
    for (int o = 16; o > 0; o >>= 1) {
        s  += __shfl_xor_sync(0xffffffffu, s,  o);
        ss += __shfl_xor_sync(0xffffffffu, ss, o);
    }
    if ((tid & 31) == 0) { rs[tid >> 5] = s; rq[tid >> 5] = ss; }
    __syncthreads();
    if (tid < 32) {
        float a = (tid < 8) ? rs[tid] : 0.f;
        float b = (tid < 8) ? rq[tid] : 0.f;
        #pragma unroll
        for (int o = 4; o > 0; o >>= 1) {
            a += __shfl_xor_sync(0xffffffffu, a, o);
            b += __shfl_xor_sync(0xffffffffu, b, o);
        }
        if (tid == 0) { rs[0] = a; rq[0] = b; }
    }
    __syncthreads();
    float mean = rs[0] * (1.0f / D_);
    float var  = rq[0] * (1.0f / D_) - mean * mean;
    float inv  = rsqrtf(var + 1e-5f);
    for (int i = tid; i < D_; i += 256)
        out[(size_t)row * D_ + i] = __float2half_rn((x[i] - mean) * inv * sc[i] + bi[i]);
}

__global__ void qkvw_k(const float* __restrict__ wq, const float* __restrict__ wk,
                       const float* __restrict__ wv) {
    int z = blockIdx.z;
    int sel = z / (NL_ * H_);
    int lh  = z - sel * (NL_ * H_);
    int l = lh / H_, h = lh - l * H_;
    const float* src = (sel == 0 ? wq : sel == 1 ? wk : wv) + ((size_t)(l * H_ + h)) * D_ * DH_;
    __half* dst = g_wqkv + (size_t)l * 3 * D_ * D_ + (size_t)sel * D_ * D_ + (size_t)h * DH_ * D_;
    __shared__ float t[32][33];
    int c0 = blockIdx.x * 32, r0 = blockIdx.y * 32;
    int x = threadIdx.x, y = threadIdx.y;
    #pragma unroll
    for (int i = 0; i < 32; i += 8) {
        int r = r0 + y + i;
        if (r < D_ && c0 + x < DH_) t[y + i][x] = src[(size_t)r * DH_ + c0 + x];
    }
    __syncthreads();
    #pragma unroll
    for (int i = 0; i < 32; i += 8) {
        int c = c0 + y + i;
        if (c < DH_ && r0 + x < D_)
            dst[(size_t)c * D_ + r0 + x] = __float2half_rn(t[x][y + i]);
    }
}

template<typename Tin>
__global__ void transpose_k(const Tin* __restrict__ in, __half* __restrict__ out,
                            int R, int C, int ldi, int ldo,
                            int nz2, long sI1, long sI2, long sO1, long sO2)
{
    int z = blockIdx.z, z1 = z / nz2, z2 = z - z1 * nz2;
    in  += z1 * sI1 + z2 * sI2;
    out += z1 * sO1 + z2 * sO2;
    __shared__ float t[32][33];
    int c0 = blockIdx.x * 32, r0 = blockIdx.y * 32;
    int x = threadIdx.x, y = threadIdx.y;
    #pragma unroll
    for (int i = 0; i < 32; i += 8) {
        int r = r0 + y + i;
        if (r < R && c0 + x < C) t[y + i][x] = (float)in[(size_t)r * ldi + c0 + x];
    }
    __syncthreads();
    #pragma unroll
    for (int i = 0; i < 32; i += 8) {
        int c = c0 + y + i;
        if (c < C && r0 + x < R) out[(size_t)c * ldo + r0 + x] = __float2half_rn(t[x][y + i]);
    }
}

// ============ launch helpers ============
template<bool RELU, bool RESID, bool BIAS, bool HALF_OUT>
static void tc_gemm(const __half* A, const __half* B, const float* bias, const float* Cin, void* C,
                    int M, int N, int K, int lda, int ldb, int ldc, float alpha = 1.f)
{
    cudaFuncSetAttribute(gemm_h<RELU, RESID, BIAS, HALF_OUT, false>,
                         cudaFuncAttributeMaxDynamicSharedMemorySize, SMEMH);
    dim3 grid(cdiv(N, BN1), cdiv(M, BM1), 1);
    gemm_h<RELU, RESID, BIAS, HALF_OUT, false><<<grid, 128, SMEMH>>>(
        A, B, bias, Cin, C, M, N, K, lda, ldb, ldc, alpha);
}

// split-K atomic variant: C (fp32) pre-holds residual; bias added by split 0
static void tc_gemm_sk(const __half* A, const __half* B, const float* bias, float* C,
                       int M, int N, int K, int lda, int ldb, int ldc, int splits)
{
    cudaFuncSetAttribute(gemm_h<false, false, true, false, true>,
                         cudaFuncAttributeMaxDynamicSharedMemorySize, SMEMH);
    dim3 grid(cdiv(N, BN1), cdiv(M, BM1), splits);
    gemm_h<false, false, true, false, true><<<grid, 128, SMEMH>>>(
        A, B, bias, nullptr, C, M, N, K, lda, ldb, ldc, 1.f);
}

template<typename Tin>
static void tr(const Tin* in, __half* out, int R, int C, int ldi, int ldo,
               int Z, int nz2, long sI1, long sI2, long sO1, long sO2)
{
    dim3 grid(cdiv(C, 32), cdiv(R, 32), Z);
    transpose_k<Tin><<<grid, dim3(32, 8)>>>(in, out, R, C, ldi, ldo, nz2, sI1, sI2, sO1, sO2);
}

// ============ orchestration ============
extern "C" void kernel_launch(void* const* d_in, const int* in_sizes, int n_in,
                              void* d_out, int out_size) {
    const int*   idx   = (const int*)  d_in[0];
    const float* emb   = (const float*)d_in[1];
    const float* cls_b = (const float*)d_in[2];
    const float* ln1_s = (const float*)d_in[3];
    const float* ln1_b = (const float*)d_in[4];
    const float* wq    = (const float*)d_in[5];
    const float* bq    = (const float*)d_in[6];
    const float* wk    = (const float*)d_in[7];
    const float* bk    = (const float*)d_in[8];
    const float* wv    = (const float*)d_in[9];
    const float* bv    = (const float*)d_in[10];
    const float* wo    = (const float*)d_in[11];
    const float* bo    = (const float*)d_in[12];
    const float* ln2_s = (const float*)d_in[13];
    const float* ln2_b = (const float*)d_in[14];
    const float* w1    = (const float*)d_in[15];
    const float* b1    = (const float*)d_in[16];
    const float* w2    = (const float*)d_in[17];
    const float* b2    = (const float*)d_in[18];
    const float* lnf_s = (const float*)d_in[19];
    const float* lnf_b = (const float*)d_in[20];
    float* out = (float*)d_out;

    float *gx, *gbq;
    __half *gh, *gqkv, *go, *gff, *gwqkv, *gwoT, *gw1T, *gw2T, *gembr;
    cudaGetSymbolAddress((void**)&gx,   g_x);
    cudaGetSymbolAddress((void**)&gh,   g_h);
    cudaGetSymbolAddress((void**)&gqkv, g_qkv);
    cudaGetSymbolAddress((void**)&go,   g_o);
    cudaGetSymbolAddress((void**)&gff,  g_ff);
    cudaGetSymbolAddress((void**)&gwqkv,g_wqkv);
    cudaGetSymbolAddress((void**)&gwoT, g_woT);
    cudaGetSymbolAddress((void**)&gw1T, g_w1T);
    cudaGetSymbolAddress((void**)&gw2T, g_w2T);
    cudaGetSymbolAddress((void**)&gbq,  g_bqkv);
    cudaGetSymbolAddress((void**)&gembr,g_embr);

    cudaFuncSetAttribute(attn_k, cudaFuncAttributeMaxDynamicSharedMemorySize, ATT_SMEM);

    embed_k<<<cdiv(BSZ_*D_, 256), 256>>>(idx, emb, bq, bk, bv);
    {
        dim3 grid(cdiv(DH_, 32), cdiv(D_, 32), 3 * NL_ * H_);
        qkvw_k<<<grid, dim3(32, 8)>>>(wq, wk, wv);
    }
    tr<float>(wo, gwoT, D_, D_, D_, D_, NL_, 1, (long)D_*D_, 0, (long)D_*D_, 0);
    tr<float>(w1, gw1T, D_, DFF_, DFF_, D_, NL_, 1, (long)D_*DFF_, 0, (long)DFF_*D_, 0);
    tr<float>(w2, gw2T, DFF_, D_, D_, DFF_, NL_, 1, (long)DFF_*D_, 0, (long)D_*DFF_, 0);
    roundcpy_k<<<cdiv(V_*D_, 256), 256>>>(emb, gembr, (size_t)V_*D_);

    for (int l = 0; l < NL_; l++) {
        ln_k<<<BSZ_, 256>>>(gx, gh, ln1_s + l*D_, ln1_b + l*D_);

        tc_gemm<false,false,true,true>(gh, gwqkv + (size_t)l*3*D_*D_, gbq + l*3*D_, nullptr, gqkv,
                                       BSZ_, 3*D_, D_, D_, D_, 3*D_);

        attn_k<<<NB_*H_*8, 128, ATT_SMEM>>>(gqkv, go);

        // x += o @ wo^T + bo  (split-K atomics into residual)
        tc_gemm_sk(go, gwoT + (size_t)l*D_*D_, bo + l*D_, gx,
                   BSZ_, D_, D_, D_, D_, D_, 3);

        ln_k<<<BSZ_, 256>>>(gx, gh, ln2_s + l*D_, ln2_b + l*D_);

        tc_gemm<true,false,true,true>(gh, gw1T + (size_t)l*DFF_*D_, b1 + l*DFF_, nullptr, gff,
                                      BSZ_, DFF_, D_, D_, D_, DFF_);

        // x += ff @ w2 + b2  (split-K atomics into residual)
        tc_gemm_sk(gff, gw2T + (size_t)l*D_*DFF_, b2 + l*D_, gx,
                   BSZ_, D_, DFF_, DFF_, DFF_, D_, 3);
    }

    ln_k<<<BSZ_, 256>>>(gx, gh, lnf_s, lnf_b);

    tc_gemm<false,false,true,false>(gh, gembr, cls_b, nullptr, out,
                                    BSZ_, V_, D_, D_, D_, V_);
}

// round 16
// speedup vs baseline: 2.6841x; 1.0083x over previous
#include <cuda_runtime.h>
#include <cuda_fp16.h>
#include <math.h>
#include <cstdint>

// ---------------- problem constants ----------------
#define D_   1024
#define H_   16
#define DH_  64
#define NL_  4
#define DFF_ 4096
#define V_   32000
#define S_   1024
#define NB_  2
#define BSZ_ (NB_*S_)

static inline int cdiv(int a, int b) { return (a + b - 1) / b; }

// ---------------- scratch ----------------
__device__ float  g_x   [BSZ_*D_];
__device__ __half g_h   [BSZ_*D_];
__device__ __half g_qkv [BSZ_*3*D_];
__device__ __half g_o   [BSZ_*D_];
__device__ __half g_ff  [BSZ_*DFF_];
__device__ __half g_wqkv[(size_t)NL_*3*D_*D_];
__device__ __half g_woT [(size_t)NL_*D_*D_];
__device__ __half g_w1T [(size_t)NL_*DFF_*D_];
__device__ __half g_w2T [(size_t)NL_*D_*DFF_];
__device__ float  g_bqkv[NL_*3*D_];
__device__ __half g_embr[(size_t)V_*D_];

// ---------------- helpers ----------------
__device__ __forceinline__ void mma16816(float* d, const uint32_t* a, const uint32_t* b) {
    asm volatile(
        "mma.sync.aligned.m16n8k16.row.col.f32.f16.f16.f32 "
        "{%0,%1,%2,%3}, {%4,%5,%6,%7}, {%8,%9}, {%0,%1,%2,%3};"
        : "+f"(d[0]), "+f"(d[1]), "+f"(d[2]), "+f"(d[3])
        : "r"(a[0]), "r"(a[1]), "r"(a[2]), "r"(a[3]), "r"(b[0]), "r"(b[1]));
}
__device__ __forceinline__ void ldsm4(uint32_t& r0, uint32_t& r1, uint32_t& r2, uint32_t& r3,
                                      uint32_t addr) {
    asm volatile("ldmatrix.sync.aligned.m8n8.x4.shared.b16 {%0,%1,%2,%3}, [%4];"
                 : "=r"(r0), "=r"(r1), "=r"(r2), "=r"(r3) : "r"(addr));
}
__device__ __forceinline__ void ldsm4t(uint32_t& r0, uint32_t& r1, uint32_t& r2, uint32_t& r3,
                                       uint32_t addr) {
    asm volatile("ldmatrix.sync.aligned.m8n8.x4.trans.shared.b16 {%0,%1,%2,%3}, [%4];"
                 : "=r"(r0), "=r"(r1), "=r"(r2), "=r"(r3) : "r"(addr));
}
__device__ __forceinline__ uint32_t smem_u32(const void* p) {
    uint32_t a;
    asm("{ .reg .u64 t; cvta.to.shared.u64 t, %1; cvt.u32.u64 %0, t; }" : "=r"(a) : "l"(p));
    return a;
}
__device__ __forceinline__ void cpa16(uint32_t dst, const void* src, bool pred) {
    int sz = pred ? 16 : 0;
    asm volatile("cp.async.cg.shared.global [%0], [%1], 16, %2;"
                 :: "r"(dst), "l"(src), "r"(sz) : "memory");
}
#define CPA_COMMIT() asm volatile("cp.async.commit_group;" ::: "memory")
#define CPA_WAIT1()  asm volatile("cp.async.wait_group 1;" ::: "memory")
#define CPA_WAIT0()  asm volatile("cp.async.wait_group 0;" ::: "memory")

// ============ fp16 mma GEMM ============
constexpr int BKH = 32, LDSH = 40, NSTAGE = 3;
constexpr int BM1 = 128, BN1 = 128;
constexpr int STGH  = 2 * BM1 * LDSH;
constexpr int SMEMH = NSTAGE * STGH * 2;         // 61,440 B -> 3 CTAs/SM

template<bool RELU, bool RESID, bool BIAS, bool HALF_OUT, bool SPLITK>
__global__ void __launch_bounds__(128) gemm_h(
    const __half* __restrict__ A, const __half* __restrict__ B,
    const float* __restrict__ biasg, const float* __restrict__ Cin,
    void* __restrict__ Cg,
    int M, int N, int K, int lda, int ldb, int ldc, float alpha)
{
    int row0 = blockIdx.y * BM1;
    int col0 = blockIdx.x * BN1;

    extern __shared__ __half smh[];
    uint32_t sm0 = smem_u32(smh);

    int tid = threadIdx.x;
    int wid = tid >> 5, lane = tid & 31;
    int wm = wid >> 1, wn = wid & 1;
    int gid = lane >> 2, tig = lane & 3;

    int cr = tid >> 2;
    int cc = (tid & 3) * 8;

    int arow = wm * 64 + (lane & 15);
    int acolh = (lane & 16) ? 8 : 0;
    uint32_t aBase[4];
    #pragma unroll
    for (int mt = 0; mt < 4; mt++)
        aBase[mt] = sm0 + ((arow + mt * 16) * LDSH + acolh) * 2;
    int brow = wn * 64 + ((lane & 16) ? 8 : 0) + (lane & 7);
    int bcolh = (lane & 8) ? 8 : 0;
    uint32_t bBase[4];
    #pragma unroll
    for (int p = 0; p < 4; p++)
        bBase[p] = sm0 + (BM1 * LDSH + (brow + p * 16) * LDSH + bcolh) * 2;

    float acc[4][8][4];
    #pragma unroll
    for (int a = 0; a < 4; a++)
        #pragma unroll
        for (int b = 0; b < 8; b++)
            #pragma unroll
            for (int c = 0; c < 4; c++) acc[a][b][c] = 0.f;

    int KTall = K / BKH;
    int kt0 = 0, kt1 = KTall;
    if (SPLITK) {
        int nz = gridDim.z, z = blockIdx.z;
        kt0 = (KTall * z) / nz;
        kt1 = (KTall * (z + 1)) / nz;
    }
    int nKT = kt1 - kt0;

    auto issue = [&](int kt, int slot) {
        int k0 = kt * BKH;
        uint32_t abase = sm0 + (uint32_t)slot * STGH * 2;
        uint32_t bbase = abase + BM1 * LDSH * 2;
        #pragma unroll
        for (int i = 0; i < 4; i++) {
            int r = cr + i * 32;
            int gm = row0 + r;
            cpa16(abase + (r * LDSH + cc) * 2,
                  A + (size_t)(gm < M ? gm : 0) * lda + k0 + cc, gm < M);
            int gn = col0 + r;
            cpa16(bbase + (r * LDSH + cc) * 2,
                  B + (size_t)(gn < N ? gn : 0) * ldb + k0 + cc, gn < N);
        }
    };

    int nPre = nKT < (NSTAGE - 1) ? nKT : (NSTAGE - 1);
    for (int p = 0; p < nPre; p++) { issue(kt0 + p, p); CPA_COMMIT(); }

    for (int ktl = 0; ktl < nKT; ktl++) {
        CPA_WAIT1();
        __syncthreads();
        int nxt = ktl + NSTAGE - 1;
        if (nxt < nKT) issue(kt0 + nxt, nxt % NSTAGE);
        CPA_COMMIT();

        uint32_t stg = (uint32_t)(ktl % NSTAGE) * STGH * 2;

        #pragma unroll
        for (int ks = 0; ks < 2; ks++) {
            uint32_t koff = stg + ks * 32;
            uint32_t af[4][4], bf[8][2];
            #pragma unroll
            for (int mt = 0; mt < 4; mt++)
                ldsm4(af[mt][0], af[mt][1], af[mt][2], af[mt][3], aBase[mt] + koff);
            #pragma unroll
            for (int p = 0; p < 4; p++)
                ldsm4(bf[2*p][0], bf[2*p][1], bf[2*p+1][0], bf[2*p+1][1], bBase[p] + koff);
            #pragma unroll
            for (int mt = 0; mt < 4; mt++)
                #pragma unroll
                for (int nt = 0; nt < 8; nt++)
                    mma16816(acc[mt][nt], af[mt], bf[nt]);
        }
    }

    bool addb = !SPLITK || blockIdx.z == 0;
    #pragma unroll
    for (int mt = 0; mt < 4; mt++) {
        #pragma unroll
        for (int half = 0; half < 2; half++) {
            int gm = row0 + wm * 64 + mt * 16 + gid + half * 8;
            if (gm >= M) continue;
            #pragma unroll
            for (int nt = 0; nt < 8; nt++) {
                int gn = col0 + wn * 64 + nt * 8 + 2 * tig;
                if (gn >= N) continue;
                float v0 = acc[mt][nt][half * 2 + 0] * alpha;
                float v1 = acc[mt][nt][half * 2 + 1] * alpha;
                if (SPLITK) {
                    if (addb && BIAS) { v0 += biasg[gn]; v1 += biasg[gn + 1]; }
                    float* cp = (float*)Cg + (size_t)gm * ldc + gn;
                    atomicAdd(cp, v0);
                    atomicAdd(cp + 1, v1);
                } else {
                    if (BIAS)  { v0 += biasg[gn]; v1 += biasg[gn + 1]; }
                    if (RESID) {
                        const float* ci = Cin + (size_t)gm * ldc + gn;
                        v0 += ci[0]; v1 += ci[1];
                    }
                    if (RELU) { v0 = fmaxf(v0, 0.f); v1 = fmaxf(v1, 0.f); }
                    if (HALF_OUT) {
                        __half* cp = (__half*)Cg + (size_t)gm * ldc + gn;
                        *(__half2*)cp = __halves2half2(__float2half_rn(v0), __float2half_rn(v1));
                    } else {
                        float* cp = (float*)Cg + (size_t)gm * ldc + gn;
                        *(float2*)cp = make_float2(v0, v1);
                    }
                }
            }
        }
    }
}

// ============ fused flash attention ============
constexpr int FQ_LDH = 72, FV_LDH = 72, FP_LDH = 136;
constexpr int OFF_Q = 0;
constexpr int OFF_K = 128 * FQ_LDH;
constexpr int OFF_V = OFF_K + 128 * FQ_LDH;
constexpr int OFF_P = OFF_V + 128 * FV_LDH;
constexpr int ATT_SMEM = (OFF_P + 128 * FP_LDH) * 2;   // 90,112 B

__global__ void __launch_bounds__(128) attn_k(const __half* __restrict__ qkv,
                                              __half* __restrict__ og) {
    extern __shared__ __half smh[];
    __half* smP = smh + OFF_P;
    uint32_t sb = smem_u32(smh);

    int z  = blockIdx.x;
    int qb = z & 7, bh = z >> 3;
    int b  = bh >> 4, h = bh & 15;
    int row0 = qb * 128;
    const __half* qp = qkv + (size_t)b * S_ * 3 * D_ + (size_t)h * DH_;
    const __half* kp = qp + D_;
    const __half* vp = qp + 2 * D_;

    int tid = threadIdx.x, wid = tid >> 5, lane = tid & 31;
    int gid = lane >> 2, tig = lane & 3;
    int wr  = wid * 32;

    int arow  = wr + (lane & 15);
    int acolh = (lane & 16) ? 8 : 0;
    uint32_t qBase[2], pBase[2];
    #pragma unroll
    for (int mt = 0; mt < 2; mt++) {
        qBase[mt] = sb + (OFF_Q + (arow + mt * 16) * FQ_LDH + acolh) * 2;
        pBase[mt] = sb + (OFF_P + (arow + mt * 16) * FP_LDH + acolh) * 2;
    }
    int brow  = ((lane & 16) ? 8 : 0) + (lane & 7);
    int bcolh = (lane & 8) ? 8 : 0;
    uint32_t kBase[8];
    #pragma unroll
    for (int p = 0; p < 8; p++)
        kBase[p] = sb + (OFF_K + (brow + p * 16) * FQ_LDH + bcolh) * 2;
    int vkrow = ((lane & 8) ? 8 : 0) + (lane & 7);
    int vncol = (lane & 16) ? 8 : 0;
    uint32_t vBase[4];
    #pragma unroll
    for (int p = 0; p < 4; p++)
        vBase[p] = sb + (OFF_V + vkrow * FV_LDH + p * 16 + vncol) * 2;

    float oacc[2][8][4];
    #pragma unroll
    for (int mt = 0; mt < 2; mt++)
        #pragma unroll
        for (int nt = 0; nt < 8; nt++)
            #pragma unroll
            for (int d = 0; d < 4; d++) oacc[mt][nt][d] = 0.f;
    float mrow[2][2] = {{-1e30f, -1e30f}, {-1e30f, -1e30f}};
    float lrow[2][2] = {{0.f, 0.f}, {0.f, 0.f}};

    #pragma unroll
    for (int i = 0; i < 8; i++) {
        int t = tid + i * 128; int r = t >> 3, c = (t & 7) * 8;
        cpa16(sb + (OFF_Q + r * FQ_LDH + c) * 2, qp + (size_t)(row0 + r) * 3 * D_ + c, true);
    }
    CPA_COMMIT();
    #pragma unroll
    for (int i = 0; i < 8; i++) {
        int t = tid + i * 128; int r = t >> 3, c = (t & 7) * 8;
        cpa16(sb + (OFF_K + r * FQ_LDH + c) * 2, kp + (size_t)r * 3 * D_ + c, true);
    }
    CPA_COMMIT();

    int nch = qb + 1;
    for (int c = 0; c < nch; c++) {
        CPA_WAIT0();
        __syncthreads();
        #pragma unroll
        for (int i = 0; i < 8; i++) {
            int t = tid + i * 128; int r = t >> 3, cc = (t & 7) * 8;
            cpa16(sb + (OFF_V + r * FV_LDH + cc) * 2,
                  vp + (size_t)(c * 128 + r) * 3 * D_ + cc, true);
        }
        CPA_COMMIT();

        float sacc[2][16][4];
        #pragma unroll
        for (int mt = 0; mt < 2; mt++)
            #pragma unroll
            for (int nt = 0; nt < 16; nt++)
                #pragma unroll
                for (int d = 0; d < 4; d++) sacc[mt][nt][d] = 0.f;
        #pragma unroll
        for (int ks = 0; ks < 4; ks++) {
            uint32_t koff = ks * 32;
            uint32_t af[2][4], bf[16][2];
            #pragma unroll
            for (int mt = 0; mt < 2; mt++)
                ldsm4(af[mt][0], af[mt][1], af[mt][2], af[mt][3], qBase[mt] + koff);
            #pragma unroll
            for (int p = 0; p < 8; p++)
                ldsm4(bf[2*p][0], bf[2*p][1], bf[2*p+1][0], bf[2*p+1][1], kBase[p] + koff);
            #pragma unroll
            for (int mt = 0; mt < 2; mt++)
                #pragma unroll
                for (int nt = 0; nt < 16; nt++)
                    mma16816(sacc[mt][nt], af[mt], bf[nt]);
        }

        bool diag = (c == qb);
        #pragma unroll
        for (int mt = 0; mt < 2; mt++) {
            #pragma unroll
            for (int half = 0; half < 2; half++) {
                int d0 = 2 * half;
                int ig = row0 + wr + 16 * mt + 8 * half + gid;
                float mx = -1e30f;
                #pragma unroll
                for (int nt = 0; nt < 16; nt++) {
                    float a = sacc[mt][nt][d0]     * 0.125f;
                    float e = sacc[mt][nt][d0 + 1] * 0.125f;
                    if (diag) {
                        int j = c * 128 + nt * 8 + 2 * tig;
                        if (j     > ig) a = -1e30f;
                        if (j + 1 > ig) e = -1e30f;
                    }
                    sacc[mt][nt][d0]     = a;
                    sacc[mt][nt][d0 + 1] = e;
                    mx = fmaxf(mx, fmaxf(a, e));
                }
                mx = fmaxf(mx, __shfl_xor_sync(0xffffffffu, mx, 1));
                mx = fmaxf(mx, __shfl_xor_sync(0xffffffffu, mx, 2));
                float mnew = fmaxf(mrow[mt][half], mx);
                float scl  = __expf(mrow[mt][half] - mnew);
                mrow[mt][half] = mnew;
                float ps = 0.f;
                int prow = wr + 16 * mt + 8 * half + gid;
                #pragma unroll
                for (int nt = 0; nt < 16; nt++) {
                    float p0 = __expf(sacc[mt][nt][d0]     - mnew);
                    float p1 = __expf(sacc[mt][nt][d0 + 1] - mnew);
                    ps += p0 + p1;
                    *(__half2*)&smP[prow * FP_LDH + nt * 8 + 2 * tig] =
                        __halves2half2(__float2half_rn(p0), __float2half_rn(p1));
                }
                ps += __shfl_xor_sync(0xffffffffu, ps, 1);
                ps += __shfl_xor_sync(0xffffffffu, ps, 2);
                lrow[mt][half] = lrow[mt][half] * scl + ps;
                #pragma unroll
                for (int nt = 0; nt < 8; nt++) {
                    oacc[mt][nt][d0]     *= scl;
                    oacc[mt][nt][d0 + 1] *= scl;
                }
            }
        }
        __syncwarp();

        CPA_WAIT0();
        __syncthreads();
        if (c + 1 < nch) {
            #pragma unroll
            for (int i = 0; i < 8; i++) {
                int t = tid + i * 128; int r = t >> 3, cc = (t & 7) * 8;
                cpa16(sb + (OFF_K + r * FQ_LDH + cc) * 2,
                      kp + (size_t)((c + 1) * 128 + r) * 3 * D_ + cc, true);
            }
            CPA_COMMIT();
        }

        #pragma unroll
        for (int ks = 0; ks < 8; ks++) {
            uint32_t koff = ks * 16 * FV_LDH * 2;
            uint32_t pkoff = ks * 32;
            uint32_t af[2][4], bf[8][2];
            #pragma unroll
            for (int mt = 0; mt < 2; mt++)
                ldsm4(af[mt][0], af[mt][1], af[mt][2], af[mt][3], pBase[mt] + pkoff);
            #pragma unroll
            for (int p = 0; p < 4; p++)
                ldsm4t(bf[2*p][0], bf[2*p][1], bf[2*p+1][0], bf[2*p+1][1], vBase[p] + koff);
            #pragma unroll
            for (int mt = 0; mt < 2; mt++)
                #pragma unroll
                for (int nt = 0; nt < 8; nt++)
                    mma16816(oacc[mt][nt], af[mt], bf[nt]);
        }
    }

    #pragma unroll
    for (int mt = 0; mt < 2; mt++) {
        #pragma unroll
        for (int half = 0; half < 2; half++) {
            float inv = 1.f / lrow[mt][half];
            int rg = row0 + wr + 16 * mt + 8 * half + gid;
            __half* orow = og + ((size_t)b * S_ + rg) * D_ + h * DH_;
            #pragma unroll
            for (int nt = 0; nt < 8; nt++) {
                float p0 = oacc[mt][nt][2 * half]     * inv;
                float p1 = oacc[mt][nt][2 * half + 1] * inv;
                *(__half2*)&orow[nt * 8 + 2 * tig] =
                    __halves2half2(__float2half_rn(p0), __float2half_rn(p1));
            }
        }
    }
}

// ============ auxiliary kernels ============
__global__ void embed_k(const int* __restrict__ idx, const float* __restrict__ emb,
                        const float* __restrict__ bq, const float* __restrict__ bk,
                        const float* __restrict__ bv) {
    int t = blockIdx.x * blockDim.x + threadIdx.x;
    if (t < NL_ * 3 * D_) {
        int l = t / (3 * D_), r = t - l * 3 * D_;
        float v = (r < D_) ? bq[l * D_ + r] : (r < 2 * D_) ? bk[l * D_ + r - D_] : bv[l * D_ + r - 2 * D_];
        g_bqkv[t] = v;
    }
    if (t >= BSZ_ * D_) return;
    int d = t & (D_ - 1);
    int bs = t >> 10;
    int s = bs & (S_ - 1);
    int tok = idx[bs];
    int i2 = d & ~1;
    float freq = __expf((float)i2 * (-9.210340371976184f / (float)D_));
    float ang = (float)s * freq;
    float pe = (d & 1) ? cosf(ang) : sinf(ang);
    g_x[t] = emb[(size_t)tok * D_ + d] * 32.0f + pe;
}

__global__ void roundcpy_k(const float* __restrict__ in, __half* __restrict__ out, size_t n) {
    size_t i = (size_t)blockIdx.x * blockDim.x + threadIdx.x;
    if (i < n) out[i] = __float2half_rn(in[i]);
}

__global__ void ln_k(const float* __restrict__ in, __half* __restrict__ out,
                     const float* __restrict__ sc, const float* __restrict__ bi) {
    int row = blockIdx.x;
    const float* x = in + (size_t)row * D_;
    int tid = threadIdx.x;
    float s = 0.f, ss = 0.f;
    for (int i = tid; i < D_; i += 256) { float v = x[i]; s += v; ss = fmaf(v, v, ss); }
    __shared__ float rs[8], rq[8];
    #pragma unroll
    for (int o = 16; o > 0; o >>= 1) {
        s  += __shfl_xor_sync(0xffffffffu, s,  o);
        ss += __shfl_xor_sync(0xffffffffu, ss, o);
    }
    if ((tid & 31) == 0) { rs[tid >> 5] = s; rq[tid >> 5] = ss; }
    __syncthreads();
    if (tid < 32) {
        float a = (tid < 8) ? rs[tid] : 0.f;
        float b = (tid < 8) ? rq[tid] : 0.f;
        #pragma unroll
        for (int o = 4; o > 0; o >>= 1) {
            a += __shfl_xor_sync(0xffffffffu, a, o);
            b += __shfl_xor_sync(0xffffffffu, b, o);
        }
        if (tid == 0) { rs[0] = a; rq[0] = b; }
    }
    __syncthreads();
    float mean = rs[0] * (1.0f / D_);
    float var  = rq[0] * (1.0f / D_) - mean * mean;
    float inv  = rsqrtf(var + 1e-5f);
    for (int i = tid; i < D_; i += 256)
        out[(size_t)row * D_ + i] = __float2half_rn((x[i] - mean) * inv * sc[i] + bi[i]);
}

__global__ void qkvw_k(const float* __restrict__ wq, const float* __restrict__ wk,
                       const float* __restrict__ wv) {
    int z = blockIdx.z;
    int sel = z / (NL_ * H_);
    int lh  = z - sel * (NL_ * H_);
    int l = lh / H_, h = lh - l * H_;
    const float* src = (sel == 0 ? wq : sel == 1 ? wk : wv) + ((size_t)(l * H_ + h)) * D_ * DH_;
    __half* dst = g_wqkv + (size_t)l * 3 * D_ * D_ + (size_t)sel * D_ * D_ + (size_t)h * DH_ * D_;
    __shared__ float t[32][33];
    int c0 = blockIdx.x * 32, r0 = blockIdx.y * 32;
    int x = threadIdx.x, y = threadIdx.y;
    #pragma unroll
    for (int i = 0; i < 32; i += 8) {
        int r = r0 + y + i;
        if (r < D_ && c0 + x < DH_) t[y + i][x] = src[(size_t)r * DH_ + c0 + x];
    }
    __syncthreads();
    #pragma unroll
    for (int i = 0; i < 32; i += 8) {
        int c = c0 + y + i;
        if (c < DH_ && r0 + x < D_)
            dst[(size_t)c * D_ + r0 + x] = __float2half_rn(t[x][y + i]);
    }
}

template<typename Tin>
__global__ void transpose_k(const Tin* __restrict__ in, __half* __restrict__ out,
                            int R, int C, int ldi, int ldo,
                            int nz2, long sI1, long sI2, long sO1, long sO2)
{
    int z = blockIdx.z, z1 = z / nz2, z2 = z - z1 * nz2;
    in  += z1 * sI1 + z2 * sI2;
    out += z1 * sO1 + z2 * sO2;
    __shared__ float t[32][33];
    int c0 = blockIdx.x * 32, r0 = blockIdx.y * 32;
    int x = threadIdx.x, y = threadIdx.y;
    #pragma unroll
    for (int i = 0; i < 32; i += 8) {
        int r = r0 + y + i;
        if (r < R && c0 + x < C) t[y + i][x] = (float)in[(size_t)r * ldi + c0 + x];
    }
    __syncthreads();
    #pragma unroll
    for (int i = 0; i < 32; i += 8) {
        int c = c0 + y + i;
        if (c < C && r0 + x < R) out[(size_t)c * ldo + r0 + x] = __float2half_rn(t[x][y + i]);
    }
}

// ============ launch helpers ============
template<bool RELU, bool RESID, bool BIAS, bool HALF_OUT>
static void tc_gemm(const __half* A, const __half* B, const float* bias, const float* Cin, void* C,
                    int M, int N, int K, int lda, int ldb, int ldc, float alpha = 1.f)
{
    cudaFuncSetAttribute(gemm_h<RELU, RESID, BIAS, HALF_OUT, false>,
                         cudaFuncAttributeMaxDynamicSharedMemorySize, SMEMH);
    dim3 grid(cdiv(N, BN1), cdiv(M, BM1), 1);
    gemm_h<RELU, RESID, BIAS, HALF_OUT, false><<<grid, 128, SMEMH>>>(
        A, B, bias, Cin, C, M, N, K, lda, ldb, ldc, alpha);
}

static void tc_gemm_sk(const __half* A, const __half* B, const float* bias, float* C,
                       int M, int N, int K, int lda, int ldb, int ldc, int splits)
{
    cudaFuncSetAttribute(gemm_h<false, false, true, false, true>,
                         cudaFuncAttributeMaxDynamicSharedMemorySize, SMEMH);
    dim3 grid(cdiv(N, BN1), cdiv(M, BM1), splits);
    gemm_h<false, false, true, false, true><<<grid, 128, SMEMH>>>(
        A, B, bias, nullptr, C, M, N, K, lda, ldb, ldc, 1.f);
}

template<typename Tin>
static void tr_s(cudaStream_t st, const Tin* in, __half* out, int R, int C, int ldi, int ldo,
                 int Z, int nz2, long sI1, long sI2, long sO1, long sO2)
{
    dim3 grid(cdiv(C, 32), cdiv(R, 32), Z);
    transpose_k<Tin><<<grid, dim3(32, 8), 0, st>>>(in, out, R, C, ldi, ldo, nz2, sI1, sI2, sO1, sO2);
}

// ============ orchestration ============
extern "C" void kernel_launch(void* const* d_in, const int* in_sizes, int n_in,
                              void* d_out, int out_size) {
    const int*   idx   = (const int*)  d_in[0];
    const float* emb   = (const float*)d_in[1];
    const float* cls_b = (const float*)d_in[2];
    const float* ln1_s = (const float*)d_in[3];
    const float* ln1_b = (const float*)d_in[4];
    const float* wq    = (const float*)d_in[5];
    const float* bq    = (const float*)d_in[6];
    const float* wk    = (const float*)d_in[7];
    const float* bk    = (const float*)d_in[8];
    const float* wv    = (const float*)d_in[9];
    const float* bv    = (const float*)d_in[10];
    const float* wo    = (const float*)d_in[11];
    const float* bo    = (const float*)d_in[12];
    const float* ln2_s = (const float*)d_in[13];
    const float* ln2_b = (const float*)d_in[14];
    const float* w1    = (const float*)d_in[15];
    const float* b1    = (const float*)d_in[16];
    const float* w2    = (const float*)d_in[17];
    const float* b2    = (const float*)d_in[18];
    const float* lnf_s = (const float*)d_in[19];
    const float* lnf_b = (const float*)d_in[20];
    float* out = (float*)d_out;

    float *gx, *gbq;
    __half *gh, *gqkv, *go, *gff, *gwqkv, *gwoT, *gw1T, *gw2T, *gembr;
    cudaGetSymbolAddress((void**)&gx,   g_x);
    cudaGetSymbolAddress((void**)&gh,   g_h);
    cudaGetSymbolAddress((void**)&gqkv, g_qkv);
    cudaGetSymbolAddress((void**)&go,   g_o);
    cudaGetSymbolAddress((void**)&gff,  g_ff);
    cudaGetSymbolAddress((void**)&gwqkv,g_wqkv);
    cudaGetSymbolAddress((void**)&gwoT, g_woT);
    cudaGetSymbolAddress((void**)&gw1T, g_w1T);
    cudaGetSymbolAddress((void**)&gw2T, g_w2T);
    cudaGetSymbolAddress((void**)&gbq,  g_bqkv);
    cudaGetSymbolAddress((void**)&gembr,g_embr);

    cudaFuncSetAttribute(attn_k, cudaFuncAttributeMaxDynamicSharedMemorySize, ATT_SMEM);

    // lazily-created side stream + events (handle creation only; graph work identical every call)
    static cudaStream_t s2 = nullptr;
    static cudaEvent_t evFork = nullptr, evJoin = nullptr;
    if (!s2) {
        cudaStreamCreateWithFlags(&s2, cudaStreamNonBlocking);
        cudaEventCreateWithFlags(&evFork, cudaEventDisableTiming);
        cudaEventCreateWithFlags(&evJoin, cudaEventDisableTiming);
    }

    // fork side stream from the (capturing) default stream
    cudaEventRecord(evFork, 0);
    cudaStreamWaitEvent(s2, evFork, 0);

    // side stream: weight repacks + classifier copy (independent of main chain)
    tr_s<float>(s2, wo, gwoT, D_, D_, D_, D_, NL_, 1, (long)D_*D_, 0, (long)D_*D_, 0);
    tr_s<float>(s2, w1, gw1T, D_, DFF_, DFF_, D_, NL_, 1, (long)D_*DFF_, 0, (long)DFF_*D_, 0);
    tr_s<float>(s2, w2, gw2T, DFF_, D_, D_, DFF_, NL_, 1, (long)DFF_*D_, 0, (long)D_*DFF_, 0);
    roundcpy_k<<<cdiv(V_*D_, 256), 256, 0, s2>>>(emb, gembr, (size_t)V_*D_);
    cudaEventRecord(evJoin, s2);

    // main stream
    embed_k<<<cdiv(BSZ_*D_, 256), 256>>>(idx, emb, bq, bk, bv);
    {
        dim3 grid(cdiv(DH_, 32), cdiv(D_, 32), 3 * NL_ * H_);
        qkvw_k<<<grid, dim3(32, 8)>>>(wq, wk, wv);
    }

    bool joined = false;
    for (int l = 0; l < NL_; l++) {
        ln_k<<<BSZ_, 256>>>(gx, gh, ln1_s + l*D_, ln1_b + l*D_);

        tc_gemm<false,false,true,true>(gh, gwqkv + (size_t)l*3*D_*D_, gbq + l*3*D_, nullptr, gqkv,
                                       BSZ_, 3*D_, D_, D_, D_, 3*D_);

        attn_k<<<NB_*H_*8, 128, ATT_SMEM>>>(gqkv, go);

        if (!joined) {           // side stream outputs first needed here (woT)
            cudaStreamWaitEvent(0, evJoin, 0);
            joined = true;
        }

        tc_gemm_sk(go, gwoT + (size_t)l*D_*D_, bo + l*D_, gx,
                   BSZ_, D_, D_, D_, D_, D_, 3);

        ln_k<<<BSZ_, 256>>>(gx, gh, ln2_s + l*D_, ln2_b + l*D_);

        tc_gemm<true,false,true,true>(gh, gw1T + (size_t)l*DFF_*D_, b1 + l*DFF_, nullptr, gff,
                                      BSZ_, DFF_, D_, D_, D_, DFF_);

        tc_gemm_sk(gff, gw2T + (size_t)l*D_*DFF_, b2 + l*D_, gx,
                   BSZ_, D_, DFF_, DFF_, DFF_, D_, 3);
    }

    ln_k<<<BSZ_, 256>>>(gx, gh, lnf_s, lnf_b);

    tc_gemm<false,false,true,false>(gh, gembr, cls_b, nullptr, out,
                                    BSZ_, V_, D_, D_, D_, V_);
}

// round 17
// speedup vs baseline: 2.8368x; 1.0569x over previous
#include <cuda_runtime.h>
#include <cuda_fp16.h>
#include <math.h>
#include <cstdint>

// ---------------- problem constants ----------------
#define D_   1024
#define H_   16
#define DH_  64
#define NL_  4
#define DFF_ 4096
#define V_   32000
#define S_   1024
#define NB_  2
#define BSZ_ (NB_*S_)

static inline int cdiv(int a, int b) { return (a + b - 1) / b; }

// ---------------- scratch ----------------
__device__ float  g_x   [BSZ_*D_];
__device__ __half g_h   [BSZ_*D_];
__device__ __half g_qkv [BSZ_*3*D_];
__device__ __half g_o   [BSZ_*D_];
__device__ __half g_ff  [BSZ_*DFF_];
__device__ __half g_wqkv[(size_t)NL_*3*D_*D_];
__device__ __half g_woT [(size_t)NL_*D_*D_];
__device__ __half g_w1T [(size_t)NL_*DFF_*D_];
__device__ __half g_w2T [(size_t)NL_*D_*DFF_];
__device__ float  g_bqkv[NL_*3*D_];
__device__ __half g_embr[(size_t)V_*D_];

// ---------------- helpers ----------------
__device__ __forceinline__ void mma16816(float* d, const uint32_t* a, const uint32_t* b) {
    asm volatile(
        "mma.sync.aligned.m16n8k16.row.col.f32.f16.f16.f32 "
        "{%0,%1,%2,%3}, {%4,%5,%6,%7}, {%8,%9}, {%0,%1,%2,%3};"
        : "+f"(d[0]), "+f"(d[1]), "+f"(d[2]), "+f"(d[3])
        : "r"(a[0]), "r"(a[1]), "r"(a[2]), "r"(a[3]), "r"(b[0]), "r"(b[1]));
}
__device__ __forceinline__ void ldsm4(uint32_t& r0, uint32_t& r1, uint32_t& r2, uint32_t& r3,
                                      uint32_t addr) {
    asm volatile("ldmatrix.sync.aligned.m8n8.x4.shared.b16 {%0,%1,%2,%3}, [%4];"
                 : "=r"(r0), "=r"(r1), "=r"(r2), "=r"(r3) : "r"(addr));
}
__device__ __forceinline__ void ldsm4t(uint32_t& r0, uint32_t& r1, uint32_t& r2, uint32_t& r3,
                                       uint32_t addr) {
    asm volatile("ldmatrix.sync.aligned.m8n8.x4.trans.shared.b16 {%0,%1,%2,%3}, [%4];"
                 : "=r"(r0), "=r"(r1), "=r"(r2), "=r"(r3) : "r"(addr));
}
__device__ __forceinline__ uint32_t smem_u32(const void* p) {
    uint32_t a;
    asm("{ .reg .u64 t; cvta.to.shared.u64 t, %1; cvt.u32.u64 %0, t; }" : "=r"(a) : "l"(p));
    return a;
}
__device__ __forceinline__ void cpa16(uint32_t dst, const void* src, bool pred) {
    int sz = pred ? 16 : 0;
    asm volatile("cp.async.cg.shared.global [%0], [%1], 16, %2;"
                 :: "r"(dst), "l"(src), "r"(sz) : "memory");
}
#define CPA_COMMIT() asm volatile("cp.async.commit_group;" ::: "memory")
#define CPA_WAIT1()  asm volatile("cp.async.wait_group 1;" ::: "memory")
#define CPA_WAIT0()  asm volatile("cp.async.wait_group 0;" ::: "memory")

// ============ fp16 mma GEMM ============
constexpr int BKH = 32, LDSH = 40, NSTAGE = 3;
constexpr int BM1 = 128, BN1 = 128;
constexpr int STGH  = 2 * BM1 * LDSH;
constexpr int SMEMH = NSTAGE * STGH * 2;         // 61,440 B -> 3 CTAs/SM

template<bool RELU, bool RESID, bool BIAS, bool HALF_OUT, bool SPLITK>
__global__ void __launch_bounds__(128) gemm_h(
    const __half* __restrict__ A, const __half* __restrict__ B,
    const float* __restrict__ biasg, const float* __restrict__ Cin,
    void* __restrict__ Cg,
    int M, int N, int K, int lda, int ldb, int ldc, float alpha)
{
    int row0 = blockIdx.y * BM1;
    int col0 = blockIdx.x * BN1;

    extern __shared__ __half smh[];
    uint32_t sm0 = smem_u32(smh);

    int tid = threadIdx.x;
    int wid = tid >> 5, lane = tid & 31;
    int wm = wid >> 1, wn = wid & 1;
    int gid = lane >> 2, tig = lane & 3;

    int cr = tid >> 2;
    int cc = (tid & 3) * 8;

    int arow = wm * 64 + (lane & 15);
    int acolh = (lane & 16) ? 8 : 0;
    uint32_t aBase[4];
    #pragma unroll
    for (int mt = 0; mt < 4; mt++)
        aBase[mt] = sm0 + ((arow + mt * 16) * LDSH + acolh) * 2;
    int brow = wn * 64 + ((lane & 16) ? 8 : 0) + (lane & 7);
    int bcolh = (lane & 8) ? 8 : 0;
    uint32_t bBase[4];
    #pragma unroll
    for (int p = 0; p < 4; p++)
        bBase[p] = sm0 + (BM1 * LDSH + (brow + p * 16) * LDSH + bcolh) * 2;

    float acc[4][8][4];
    #pragma unroll
    for (int a = 0; a < 4; a++)
        #pragma unroll
        for (int b = 0; b < 8; b++)
            #pragma unroll
            for (int c = 0; c < 4; c++) acc[a][b][c] = 0.f;

    int KTall = K / BKH;
    int kt0 = 0, kt1 = KTall;
    if (SPLITK) {
        int nz = gridDim.z, z = blockIdx.z;
        kt0 = (KTall * z) / nz;
        kt1 = (KTall * (z + 1)) / nz;
    }
    int nKT = kt1 - kt0;

    auto issue = [&](int kt, int slot) {
        int k0 = kt * BKH;
        uint32_t abase = sm0 + (uint32_t)slot * STGH * 2;
        uint32_t bbase = abase + BM1 * LDSH * 2;
        #pragma unroll
        for (int i = 0; i < 4; i++) {
            int r = cr + i * 32;
            int gm = row0 + r;
            cpa16(abase + (r * LDSH + cc) * 2,
                  A + (size_t)(gm < M ? gm : 0) * lda + k0 + cc, gm < M);
            int gn = col0 + r;
            cpa16(bbase + (r * LDSH + cc) * 2,
                  B + (size_t)(gn < N ? gn : 0) * ldb + k0 + cc, gn < N);
        }
    };

    int nPre = nKT < (NSTAGE - 1) ? nKT : (NSTAGE - 1);
    for (int p = 0; p < nPre; p++) { issue(kt0 + p, p); CPA_COMMIT(); }

    for (int ktl = 0; ktl < nKT; ktl++) {
        CPA_WAIT1();
        __syncthreads();
        int nxt = ktl + NSTAGE - 1;
        if (nxt < nKT) issue(kt0 + nxt, nxt % NSTAGE);
        CPA_COMMIT();

        uint32_t stg = (uint32_t)(ktl % NSTAGE) * STGH * 2;

        #pragma unroll
        for (int ks = 0; ks < 2; ks++) {
            uint32_t koff = stg + ks * 32;
            uint32_t af[4][4], bf[8][2];
            #pragma unroll
            for (int mt = 0; mt < 4; mt++)
                ldsm4(af[mt][0], af[mt][1], af[mt][2], af[mt][3], aBase[mt] + koff);
            #pragma unroll
            for (int p = 0; p < 4; p++)
                ldsm4(bf[2*p][0], bf[2*p][1], bf[2*p+1][0], bf[2*p+1][1], bBase[p] + koff);
            #pragma unroll
            for (int mt = 0; mt < 4; mt++)
                #pragma unroll
                for (int nt = 0; nt < 8; nt++)
                    mma16816(acc[mt][nt], af[mt], bf[nt]);
        }
    }

    bool addb = !SPLITK || blockIdx.z == 0;
    #pragma unroll
    for (int mt = 0; mt < 4; mt++) {
        #pragma unroll
        for (int half = 0; half < 2; half++) {
            int gm = row0 + wm * 64 + mt * 16 + gid + half * 8;
            if (gm >= M) continue;
            #pragma unroll
            for (int nt = 0; nt < 8; nt++) {
                int gn = col0 + wn * 64 + nt * 8 + 2 * tig;
                if (gn >= N) continue;
                float v0 = acc[mt][nt][half * 2 + 0] * alpha;
                float v1 = acc[mt][nt][half * 2 + 1] * alpha;
                if (SPLITK) {
                    if (addb && BIAS) { v0 += biasg[gn]; v1 += biasg[gn + 1]; }
                    float* cp = (float*)Cg + (size_t)gm * ldc + gn;
                    atomicAdd(cp, v0);
                    atomicAdd(cp + 1, v1);
                } else {
                    if (BIAS)  { v0 += biasg[gn]; v1 += biasg[gn + 1]; }
                    if (RESID) {
                        const float* ci = Cin + (size_t)gm * ldc + gn;
                        v0 += ci[0]; v1 += ci[1];
                    }
                    if (RELU) { v0 = fmaxf(v0, 0.f); v1 = fmaxf(v1, 0.f); }
                    if (HALF_OUT) {
                        __half* cp = (__half*)Cg + (size_t)gm * ldc + gn;
                        *(__half2*)cp = __halves2half2(__float2half_rn(v0), __float2half_rn(v1));
                    } else {
                        float* cp = (float*)Cg + (size_t)gm * ldc + gn;
                        *(float2*)cp = make_float2(v0, v1);
                    }
                }
            }
        }
    }
}

// ============ fused flash attention ============
constexpr int FQ_LDH = 72, FV_LDH = 72, FP_LDH = 136;
constexpr int OFF_Q = 0;
constexpr int OFF_K = 128 * FQ_LDH;
constexpr int OFF_V = OFF_K + 128 * FQ_LDH;
constexpr int OFF_P = OFF_V + 128 * FV_LDH;
constexpr int ATT_SMEM = (OFF_P + 128 * FP_LDH) * 2;   // 90,112 B

__global__ void __launch_bounds__(128) attn_k(const __half* __restrict__ qkv,
                                              __half* __restrict__ og) {
    extern __shared__ __half smh[];
    __half* smP = smh + OFF_P;
    uint32_t sb = smem_u32(smh);

    int z  = blockIdx.x;
    int qb = z & 7, bh = z >> 3;
    int b  = bh >> 4, h = bh & 15;
    int row0 = qb * 128;
    const __half* qp = qkv + (size_t)b * S_ * 3 * D_ + (size_t)h * DH_;
    const __half* kp = qp + D_;
    const __half* vp = qp + 2 * D_;

    int tid = threadIdx.x, wid = tid >> 5, lane = tid & 31;
    int gid = lane >> 2, tig = lane & 3;
    int wr  = wid * 32;

    int arow  = wr + (lane & 15);
    int acolh = (lane & 16) ? 8 : 0;
    uint32_t qBase[2], pBase[2];
    #pragma unroll
    for (int mt = 0; mt < 2; mt++) {
        qBase[mt] = sb + (OFF_Q + (arow + mt * 16) * FQ_LDH + acolh) * 2;
        pBase[mt] = sb + (OFF_P + (arow + mt * 16) * FP_LDH + acolh) * 2;
    }
    int brow  = ((lane & 16) ? 8 : 0) + (lane & 7);
    int bcolh = (lane & 8) ? 8 : 0;
    uint32_t kBase[8];
    #pragma unroll
    for (int p = 0; p < 8; p++)
        kBase[p] = sb + (OFF_K + (brow + p * 16) * FQ_LDH + bcolh) * 2;
    int vkrow = ((lane & 8) ? 8 : 0) + (lane & 7);
    int vncol = (lane & 16) ? 8 : 0;
    uint32_t vBase[4];
    #pragma unroll
    for (int p = 0; p < 4; p++)
        vBase[p] = sb + (OFF_V + vkrow * FV_LDH + p * 16 + vncol) * 2;

    float oacc[2][8][4];
    #pragma unroll
    for (int mt = 0; mt < 2; mt++)
        #pragma unroll
        for (int nt = 0; nt < 8; nt++)
            #pragma unroll
            for (int d = 0; d < 4; d++) oacc[mt][nt][d] = 0.f;
    float mrow[2][2] = {{-1e30f, -1e30f}, {-1e30f, -1e30f}};
    float lrow[2][2] = {{0.f, 0.f}, {0.f, 0.f}};

    #pragma unroll
    for (int i = 0; i < 8; i++) {
        int t = tid + i * 128; int r = t >> 3, c = (t & 7) * 8;
        cpa16(sb + (OFF_Q + r * FQ_LDH + c) * 2, qp + (size_t)(row0 + r) * 3 * D_ + c, true);
    }
    CPA_COMMIT();
    #pragma unroll
    for (int i = 0; i < 8; i++) {
        int t = tid + i * 128; int r = t >> 3, c = (t & 7) * 8;
        cpa16(sb + (OFF_K + r * FQ_LDH + c) * 2, kp + (size_t)r * 3 * D_ + c, true);
    }
    CPA_COMMIT();

    int nch = qb + 1;
    for (int c = 0; c < nch; c++) {
        CPA_WAIT0();
        __syncthreads();
        #pragma unroll
        for (int i = 0; i < 8; i++) {
            int t = tid + i * 128; int r = t >> 3, cc = (t & 7) * 8;
            cpa16(sb + (OFF_V + r * FV_LDH + cc) * 2,
                  vp + (size_t)(c * 128 + r) * 3 * D_ + cc, true);
        }
        CPA_COMMIT();

        float sacc[2][16][4];
        #pragma unroll
        for (int mt = 0; mt < 2; mt++)
            #pragma unroll
            for (int nt = 0; nt < 16; nt++)
                #pragma unroll
                for (int d = 0; d < 4; d++) sacc[mt][nt][d] = 0.f;
        #pragma unroll
        for (int ks = 0; ks < 4; ks++) {
            uint32_t koff = ks * 32;
            uint32_t af[2][4], bf[16][2];
            #pragma unroll
            for (int mt = 0; mt < 2; mt++)
                ldsm4(af[mt][0], af[mt][1], af[mt][2], af[mt][3], qBase[mt] + koff);
            #pragma unroll
            for (int p = 0; p < 8; p++)
                ldsm4(bf[2*p][0], bf[2*p][1], bf[2*p+1][0], bf[2*p+1][1], kBase[p] + koff);
            #pragma unroll
            for (int mt = 0; mt < 2; mt++)
                #pragma unroll
                for (int nt = 0; nt < 16; nt++)
                    mma16816(sacc[mt][nt], af[mt], bf[nt]);
        }

        bool diag = (c == qb);
        #pragma unroll
        for (int mt = 0; mt < 2; mt++) {
            #pragma unroll
            for (int half = 0; half < 2; half++) {
                int d0 = 2 * half;
                int ig = row0 + wr + 16 * mt + 8 * half + gid;
                float mx = -1e30f;
                #pragma unroll
                for (int nt = 0; nt < 16; nt++) {
                    float a = sacc[mt][nt][d0]     * 0.125f;
                    float e = sacc[mt][nt][d0 + 1] * 0.125f;
                    if (diag) {
                        int j = c * 128 + nt * 8 + 2 * tig;
                        if (j     > ig) a = -1e30f;
                        if (j + 1 > ig) e = -1e30f;
                    }
                    sacc[mt][nt][d0]     = a;
                    sacc[mt][nt][d0 + 1] = e;
                    mx = fmaxf(mx, fmaxf(a, e));
                }
                mx = fmaxf(mx, __shfl_xor_sync(0xffffffffu, mx, 1));
                mx = fmaxf(mx, __shfl_xor_sync(0xffffffffu, mx, 2));
                float mnew = fmaxf(mrow[mt][half], mx);
                float scl  = __expf(mrow[mt][half] - mnew);
                mrow[mt][half] = mnew;
                float ps = 0.f;
                int prow = wr + 16 * mt + 8 * half + gid;
                #pragma unroll
                for (int nt = 0; nt < 16; nt++) {
                    float p0 = __expf(sacc[mt][nt][d0]     - mnew);
                    float p1 = __expf(sacc[mt][nt][d0 + 1] - mnew);
                    ps += p0 + p1;
                    *(__half2*)&smP[prow * FP_LDH + nt * 8 + 2 * tig] =
                        __halves2half2(__float2half_rn(p0), __float2half_rn(p1));
                }
                ps += __shfl_xor_sync(0xffffffffu, ps, 1);
                ps += __shfl_xor_sync(0xffffffffu, ps, 2);
                lrow[mt][half] = lrow[mt][half] * scl + ps;
                #pragma unroll
                for (int nt = 0; nt < 8; nt++) {
                    oacc[mt][nt][d0]     *= scl;
                    oacc[mt][nt][d0 + 1] *= scl;
                }
            }
        }
        __syncwarp();

        CPA_WAIT0();
        __syncthreads();
        if (c + 1 < nch) {
            #pragma unroll
            for (int i = 0; i < 8; i++) {
                int t = tid + i * 128; int r = t >> 3, cc = (t & 7) * 8;
                cpa16(sb + (OFF_K + r * FQ_LDH + cc) * 2,
                      kp + (size_t)((c + 1) * 128 + r) * 3 * D_ + cc, true);
            }
            CPA_COMMIT();
        }

        #pragma unroll
        for (int ks = 0; ks < 8; ks++) {
            uint32_t koff = ks * 16 * FV_LDH * 2;
            uint32_t pkoff = ks * 32;
            uint32_t af[2][4], bf[8][2];
            #pragma unroll
            for (int mt = 0; mt < 2; mt++)
                ldsm4(af[mt][0], af[mt][1], af[mt][2], af[mt][3], pBase[mt] + pkoff);
            #pragma unroll
            for (int p = 0; p < 4; p++)
                ldsm4t(bf[2*p][0], bf[2*p][1], bf[2*p+1][0], bf[2*p+1][1], vBase[p] + koff);
            #pragma unroll
            for (int mt = 0; mt < 2; mt++)
                #pragma unroll
                for (int nt = 0; nt < 8; nt++)
                    mma16816(oacc[mt][nt], af[mt], bf[nt]);
        }
    }

    #pragma unroll
    for (int mt = 0; mt < 2; mt++) {
        #pragma unroll
        for (int half = 0; half < 2; half++) {
            float inv = 1.f / lrow[mt][half];
            int rg = row0 + wr + 16 * mt + 8 * half + gid;
            __half* orow = og + ((size_t)b * S_ + rg) * D_ + h * DH_;
            #pragma unroll
            for (int nt = 0; nt < 8; nt++) {
                float p0 = oacc[mt][nt][2 * half]     * inv;
                float p1 = oacc[mt][nt][2 * half + 1] * inv;
                *(__half2*)&orow[nt * 8 + 2 * tig] =
                    __halves2half2(__float2half_rn(p0), __float2half_rn(p1));
            }
        }
    }
}

// ============ auxiliary kernels ============
__global__ void embed_k(const int* __restrict__ idx, const float* __restrict__ emb,
                        const float* __restrict__ bq, const float* __restrict__ bk,
                        const float* __restrict__ bv) {
    int t = blockIdx.x * blockDim.x + threadIdx.x;
    if (t < NL_ * 3 * D_) {
        int l = t / (3 * D_), r = t - l * 3 * D_;
        float v = (r < D_) ? bq[l * D_ + r] : (r < 2 * D_) ? bk[l * D_ + r - D_] : bv[l * D_ + r - 2 * D_];
        g_bqkv[t] = v;
    }
    if (t >= BSZ_ * D_) return;
    int d = t & (D_ - 1);
    int bs = t >> 10;
    int s = bs & (S_ - 1);
    int tok = idx[bs];
    int i2 = d & ~1;
    float freq = __expf((float)i2 * (-9.210340371976184f / (float)D_));
    float ang = (float)s * freq;
    float pe = (d & 1) ? cosf(ang) : sinf(ang);
    g_x[t] = emb[(size_t)tok * D_ + d] * 32.0f + pe;
}

// vectorized rounded copy: float4 in -> 2x half2 out
__global__ void roundcpy_k(const float4* __restrict__ in, uint2* __restrict__ out, size_t n4) {
    size_t i = (size_t)blockIdx.x * blockDim.x + threadIdx.x;
    if (i >= n4) return;
    float4 v = in[i];
    __half2 lo = __halves2half2(__float2half_rn(v.x), __float2half_rn(v.y));
    __half2 hi = __halves2half2(__float2half_rn(v.z), __float2half_rn(v.w));
    uint2 o;
    o.x = *(uint32_t*)&lo;
    o.y = *(uint32_t*)&hi;
    out[i] = o;
}

// vectorized layernorm: 256 threads, each owns exactly one float4 (D=1024)
__global__ void __launch_bounds__(256) ln_k(const float* __restrict__ in, __half* __restrict__ out,
                                            const float* __restrict__ sc, const float* __restrict__ bi) {
    int row = blockIdx.x;
    int tid = threadIdx.x;
    const float4* x4 = (const float4*)(in + (size_t)row * D_);
    float4 v = x4[tid];
    float s  = v.x + v.y + v.z + v.w;
    float ss = fmaf(v.x, v.x, fmaf(v.y, v.y, fmaf(v.z, v.z, v.w * v.w)));
    __shared__ float rs[8], rq[8];
    #pragma unroll
    for (int o = 16; o > 0; o >>= 1) {
        s  += __shfl_xor_sync(0xffffffffu, s,  o);
        ss += __shfl_xor_sync(0xffffffffu, ss, o);
    }
    if ((tid & 31) == 0) { rs[tid >> 5] = s; rq[tid >> 5] = ss; }
    __syncthreads();
    if (tid < 32) {
        float a = (tid < 8) ? rs[tid] : 0.f;
        float b = (tid < 8) ? rq[tid] : 0.f;
        #pragma unroll
        for (int o = 4; o > 0; o >>= 1) {
            a += __shfl_xor_sync(0xffffffffu, a, o);
            b += __shfl_xor_sync(0xffffffffu, b, o);
        }
        if (tid == 0) { rs[0] = a; rq[0] = b; }
    }
    __syncthreads();
    float mean = rs[0] * (1.0f / D_);
    float var  = rq[0] * (1.0f / D_) - mean * mean;
    float inv  = rsqrtf(var + 1e-5f);
    float4 sc4 = ((const float4*)sc)[tid];
    float4 bi4 = ((const float4*)bi)[tid];
    float o0 = (v.x - mean) * inv * sc4.x + bi4.x;
    float o1 = (v.y - mean) * inv * sc4.y + bi4.y;
    float o2 = (v.z - mean) * inv * sc4.z + bi4.z;
    float o3 = (v.w - mean) * inv * sc4.w + bi4.w;
    __half2 lo = __halves2half2(__float2half_rn(o0), __float2half_rn(o1));
    __half2 hi = __halves2half2(__float2half_rn(o2), __float2half_rn(o3));
    uint2 pkt;
    pkt.x = *(uint32_t*)&lo;
    pkt.y = *(uint32_t*)&hi;
    ((uint2*)(out + (size_t)row * D_))[tid] = pkt;
}

__global__ void qkvw_k(const float* __restrict__ wq, const float* __restrict__ wk,
                       const float* __restrict__ wv) {
    int z = blockIdx.z;
    int sel = z / (NL_ * H_);
    int lh  = z - sel * (NL_ * H_);
    int l = lh / H_, h = lh - l * H_;
    const float* src = (sel == 0 ? wq : sel == 1 ? wk : wv) + ((size_t)(l * H_ + h)) * D_ * DH_;
    __half* dst = g_wqkv + (size_t)l * 3 * D_ * D_ + (size_t)sel * D_ * D_ + (size_t)h * DH_ * D_;
    __shared__ float t[32][33];
    int c0 = blockIdx.x * 32, r0 = blockIdx.y * 32;
    int x = threadIdx.x, y = threadIdx.y;
    #pragma unroll
    for (int i = 0; i < 32; i += 8) {
        int r = r0 + y + i;
        if (r < D_ && c0 + x < DH_) t[y + i][x] = src[(size_t)r * DH_ + c0 + x];
    }
    __syncthreads();
    #pragma unroll
    for (int i = 0; i < 32; i += 8) {
        int c = c0 + y + i;
        if (c < DH_ && r0 + x < D_)
            dst[(size_t)c * D_ + r0 + x] = __float2half_rn(t[x][y + i]);
    }
}

template<typename Tin>
__global__ void transpose_k(const Tin* __restrict__ in, __half* __restrict__ out,
                            int R, int C, int ldi, int ldo,
                            int nz2, long sI1, long sI2, long sO1, long sO2)
{
    int z = blockIdx.z, z1 = z / nz2, z2 = z - z1 * nz2;
    in  += z1 * sI1 + z2 * sI2;
    out += z1 * sO1 + z2 * sO2;
    __shared__ float t[32][33];
    int c0 = blockIdx.x * 32, r0 = blockIdx.y * 32;
    int x = threadIdx.x, y = threadIdx.y;
    #pragma unroll
    for (int i = 0; i < 32; i += 8) {
        int r = r0 + y + i;
        if (r < R && c0 + x < C) t[y + i][x] = (float)in[(size_t)r * ldi + c0 + x];
    }
    __syncthreads();
    #pragma unroll
    for (int i = 0; i < 32; i += 8) {
        int c = c0 + y + i;
        if (c < C && r0 + x < R) out[(size_t)c * ldo + r0 + x] = __float2half_rn(t[x][y + i]);
    }
}

// ============ launch helpers ============
template<bool RELU, bool RESID, bool BIAS, bool HALF_OUT>
static void tc_gemm(const __half* A, const __half* B, const float* bias, const float* Cin, void* C,
                    int M, int N, int K, int lda, int ldb, int ldc, float alpha = 1.f)
{
    cudaFuncSetAttribute(gemm_h<RELU, RESID, BIAS, HALF_OUT, false>,
                         cudaFuncAttributeMaxDynamicSharedMemorySize, SMEMH);
    dim3 grid(cdiv(N, BN1), cdiv(M, BM1), 1);
    gemm_h<RELU, RESID, BIAS, HALF_OUT, false><<<grid, 128, SMEMH>>>(
        A, B, bias, Cin, C, M, N, K, lda, ldb, ldc, alpha);
}

static void tc_gemm_sk(const __half* A, const __half* B, const float* bias, float* C,
                       int M, int N, int K, int lda, int ldb, int ldc, int splits)
{
    cudaFuncSetAttribute(gemm_h<false, false, true, false, true>,
                         cudaFuncAttributeMaxDynamicSharedMemorySize, SMEMH);
    dim3 grid(cdiv(N, BN1), cdiv(M, BM1), splits);
    gemm_h<false, false, true, false, true><<<grid, 128, SMEMH>>>(
        A, B, bias, nullptr, C, M, N, K, lda, ldb, ldc, 1.f);
}

template<typename Tin>
static void tr_s(cudaStream_t st, const Tin* in, __half* out, int R, int C, int ldi, int ldo,
                 int Z, int nz2, long sI1, long sI2, long sO1, long sO2)
{
    dim3 grid(cdiv(C, 32), cdiv(R, 32), Z);
    transpose_k<Tin><<<grid, dim3(32, 8), 0, st>>>(in, out, R, C, ldi, ldo, nz2, sI1, sI2, sO1, sO2);
}

// ============ orchestration ============
extern "C" void kernel_launch(void* const* d_in, const int* in_sizes, int n_in,
                              void* d_out, int out_size) {
    const int*   idx   = (const int*)  d_in[0];
    const float* emb   = (const float*)d_in[1];
    const float* cls_b = (const float*)d_in[2];
    const float* ln1_s = (const float*)d_in[3];
    const float* ln1_b = (const float*)d_in[4];
    const float* wq    = (const float*)d_in[5];
    const float* bq    = (const float*)d_in[6];
    const float* wk    = (const float*)d_in[7];
    const float* bk    = (const float*)d_in[8];
    const float* wv    = (const float*)d_in[9];
    const float* bv    = (const float*)d_in[10];
    const float* wo    = (const float*)d_in[11];
    const float* bo    = (const float*)d_in[12];
    const float* ln2_s = (const float*)d_in[13];
    const float* ln2_b = (const float*)d_in[14];
    const float* w1    = (const float*)d_in[15];
    const float* b1    = (const float*)d_in[16];
    const float* w2    = (const float*)d_in[17];
    const float* b2    = (const float*)d_in[18];
    const float* lnf_s = (const float*)d_in[19];
    const float* lnf_b = (const float*)d_in[20];
    float* out = (float*)d_out;

    float *gx, *gbq;
    __half *gh, *gqkv, *go, *gff, *gwqkv, *gwoT, *gw1T, *gw2T, *gembr;
    cudaGetSymbolAddress((void**)&gx,   g_x);
    cudaGetSymbolAddress((void**)&gh,   g_h);
    cudaGetSymbolAddress((void**)&gqkv, g_qkv);
    cudaGetSymbolAddress((void**)&go,   g_o);
    cudaGetSymbolAddress((void**)&gff,  g_ff);
    cudaGetSymbolAddress((void**)&gwqkv,g_wqkv);
    cudaGetSymbolAddress((void**)&gwoT, g_woT);
    cudaGetSymbolAddress((void**)&gw1T, g_w1T);
    cudaGetSymbolAddress((void**)&gw2T, g_w2T);
    cudaGetSymbolAddress((void**)&gbq,  g_bqkv);
    cudaGetSymbolAddress((void**)&gembr,g_embr);

    cudaFuncSetAttribute(attn_k, cudaFuncAttributeMaxDynamicSharedMemorySize, ATT_SMEM);

    static cudaStream_t s2 = nullptr;
    static cudaEvent_t evFork = nullptr, evJoin = nullptr;
    if (!s2) {
        cudaStreamCreateWithFlags(&s2, cudaStreamNonBlocking);
        cudaEventCreateWithFlags(&evFork, cudaEventDisableTiming);
        cudaEventCreateWithFlags(&evJoin, cudaEventDisableTiming);
    }

    cudaEventRecord(evFork, 0);
    cudaStreamWaitEvent(s2, evFork, 0);

    // side stream: weight repacks + classifier copy
    tr_s<float>(s2, wo, gwoT, D_, D_, D_, D_, NL_, 1, (long)D_*D_, 0, (long)D_*D_, 0);
    tr_s<float>(s2, w1, gw1T, D_, DFF_, DFF_, D_, NL_, 1, (long)D_*DFF_, 0, (long)DFF_*D_, 0);
    tr_s<float>(s2, w2, gw2T, DFF_, D_, D_, DFF_, NL_, 1, (long)DFF_*D_, 0, (long)D_*DFF_, 0);
    roundcpy_k<<<cdiv((int)((size_t)V_*D_/4), 256), 256, 0, s2>>>(
        (const float4*)emb, (uint2*)gembr, (size_t)V_*D_/4);
    cudaEventRecord(evJoin, s2);

    // main stream
    embed_k<<<cdiv(BSZ_*D_, 256), 256>>>(idx, emb, bq, bk, bv);
    {
        dim3 grid(cdiv(DH_, 32), cdiv(D_, 32), 3 * NL_ * H_);
        qkvw_k<<<grid, dim3(32, 8)>>>(wq, wk, wv);
    }

    bool joined = false;
    for (int l = 0; l < NL_; l++) {
        ln_k<<<BSZ_, 256>>>(gx, gh, ln1_s + l*D_, ln1_b + l*D_);

        tc_gemm<false,false,true,true>(gh, gwqkv + (size_t)l*3*D_*D_, gbq + l*3*D_, nullptr, gqkv,
                                       BSZ_, 3*D_, D_, D_, D_, 3*D_);

        attn_k<<<NB_*H_*8, 128, ATT_SMEM>>>(gqkv, go);

        if (!joined) {
            cudaStreamWaitEvent(0, evJoin, 0);
            joined = true;
        }

        tc_gemm_sk(go, gwoT + (size_t)l*D_*D_, bo + l*D_, gx,
                   BSZ_, D_, D_, D_, D_, D_, 3);

        ln_k<<<BSZ_, 256>>>(gx, gh, ln2_s + l*D_, ln2_b + l*D_);

        tc_gemm<true,false,true,true>(gh, gw1T + (size_t)l*DFF_*D_, b1 + l*DFF_, nullptr, gff,
                                      BSZ_, DFF_, D_, D_, D_, DFF_);

        tc_gemm_sk(gff, gw2T + (size_t)l*D_*DFF_, b2 + l*D_, gx,
                   BSZ_, D_, DFF_, DFF_, DFF_, D_, 3);
    }

    ln_k<<<BSZ_, 256>>>(gx, gh, lnf_s, lnf_b);

    tc_gemm<false,false,true,false>(gh, gembr, cls_b, nullptr, out,
                                    BSZ_, V_, D_, D_, D_, V_);
}